// round 3
// baseline (speedup 1.0000x reference)
#include <cuda_runtime.h>
#include <math.h>

// Problem constants
#define NN 49152
#define CC 512
#define HH 8
#define KK 48
#define DD 64
#define PP 1024            // NN / KK
#define C3 1536            // 3*C
#define C2 1024            // 2*C

// ---------------------------------------------------------------------------
// Scratch (device globals; no runtime allocation)
// ---------------------------------------------------------------------------
__device__ float g_qkv_s[(size_t)NN * C3];   // permuted qkv, sem stream
__device__ float g_qkv_b[(size_t)NN * C3];   // permuted qkv, bnd stream
__device__ float g_h1[(size_t)NN * C2];      // gelu(qcat @ w_f1 + b)
__device__ float g_qf[(size_t)NN * CC];      // fused query (permuted space)
__device__ float g_attn_s[(size_t)NN * CC];  // attention out, scattered back (unpermuted)
__device__ float g_attn_b[(size_t)NN * CC];
__device__ float g_mean_s[NN];
__device__ float g_rstd_s[NN];
__device__ float g_mean_b[NN];
__device__ float g_rstd_b[NN];

// ---------------------------------------------------------------------------
// LayerNorm row statistics: one warp per row of 512
// ---------------------------------------------------------------------------
__global__ void ln_stats_kernel(const float* __restrict__ x,
                                float* __restrict__ mean,
                                float* __restrict__ rstd)
{
    int warp = (blockIdx.x * blockDim.x + threadIdx.x) >> 5;
    int lane = threadIdx.x & 31;
    if (warp >= NN) return;
    const float* row = x + (size_t)warp * CC;
    float s = 0.f, sq = 0.f;
    #pragma unroll 4
    for (int i = lane; i < CC; i += 32) {
        float v = row[i];
        s += v; sq += v * v;
    }
    #pragma unroll
    for (int o = 16; o > 0; o >>= 1) {
        s  += __shfl_xor_sync(0xffffffffu, s, o);
        sq += __shfl_xor_sync(0xffffffffu, sq, o);
    }
    if (lane == 0) {
        float m = s * (1.f / CC);
        float var = sq * (1.f / CC) - m * m;
        mean[warp] = m;
        rstd[warp] = rsqrtf(var + 1e-5f);
    }
}

// ---------------------------------------------------------------------------
// Templated SGEMM: C = op(A) @ B + bias, 128x128x8 tiles, 256 threads, 8x8/thread
// AMODE: 0 = plain A load
//        1 = LayerNorm transform: (a - mean[row]) * rstd[row] * g[k] + b[k]
//        2 = concat: cols [0,512) from A, cols [512,1024) from A2 (both lda)
// EPI:   0 = bias only
//        1 = bias, row scattered to scat[row]
//        2 = bias + exact GELU
//        3 = bias + residual res[row] added
// All dims are multiples of tile sizes; no bounds checks.
// ---------------------------------------------------------------------------
template<int AMODE, int EPI>
__global__ void __launch_bounds__(256)
gemm_kernel(const float* __restrict__ A, const float* __restrict__ A2, int lda,
            const float* __restrict__ B, int ldb,
            const float* __restrict__ bias,
            float* __restrict__ Co, int ldc,
            const float* __restrict__ mean, const float* __restrict__ rstd,
            const float* __restrict__ lng, const float* __restrict__ lnb,
            const int* __restrict__ scat,
            const float* __restrict__ res,
            int Kd)
{
    __shared__ float As[8][128];
    __shared__ float Bs[8][128];

    const int tid  = threadIdx.x;
    const int brow = blockIdx.y * 128;
    const int bcol = blockIdx.x * 128;

    const int a_row = tid >> 1;          // 0..127
    const int a_kc  = (tid & 1) << 2;    // 0 or 4
    const int b_kr  = tid >> 5;          // 0..7
    const int b_col = (tid & 31) << 2;   // 0..124
    const int tx = tid & 15, ty = tid >> 4;

    float acc[8][8];
    #pragma unroll
    for (int i = 0; i < 8; i++)
        #pragma unroll
        for (int j = 0; j < 8; j++) acc[i][j] = 0.f;

    float mrow = 0.f, rrow = 0.f;
    if (AMODE == 1) {
        mrow = mean[brow + a_row];
        rrow = rstd[brow + a_row];
    }

    for (int k0 = 0; k0 < Kd; k0 += 8) {
        const int gr = brow + a_row;
        const int gk = k0 + a_kc;
        float4 av;
        if (AMODE == 2) {
            const float* src = (gk < 512) ? A : A2;
            const int kk2 = (gk < 512) ? gk : (gk - 512);
            av = *(const float4*)(src + (size_t)gr * lda + kk2);
        } else {
            av = *(const float4*)(A + (size_t)gr * lda + gk);
        }
        if (AMODE == 1) {
            av.x = (av.x - mrow) * rrow * lng[gk + 0] + lnb[gk + 0];
            av.y = (av.y - mrow) * rrow * lng[gk + 1] + lnb[gk + 1];
            av.z = (av.z - mrow) * rrow * lng[gk + 2] + lnb[gk + 2];
            av.w = (av.w - mrow) * rrow * lng[gk + 3] + lnb[gk + 3];
        }
        As[a_kc + 0][a_row] = av.x;
        As[a_kc + 1][a_row] = av.y;
        As[a_kc + 2][a_row] = av.z;
        As[a_kc + 3][a_row] = av.w;

        float4 bv = *(const float4*)(B + (size_t)(k0 + b_kr) * ldb + bcol + b_col);
        *(float4*)&Bs[b_kr][b_col] = bv;

        __syncthreads();

        #pragma unroll
        for (int kk = 0; kk < 8; kk++) {
            float4 a0 = *(const float4*)&As[kk][ty * 8];
            float4 a1 = *(const float4*)&As[kk][ty * 8 + 4];
            float4 b0 = *(const float4*)&Bs[kk][tx * 8];
            float4 b1 = *(const float4*)&Bs[kk][tx * 8 + 4];
            float ar[8] = {a0.x, a0.y, a0.z, a0.w, a1.x, a1.y, a1.z, a1.w};
            float br[8] = {b0.x, b0.y, b0.z, b0.w, b1.x, b1.y, b1.z, b1.w};
            #pragma unroll
            for (int i = 0; i < 8; i++)
                #pragma unroll
                for (int j = 0; j < 8; j++)
                    acc[i][j] += ar[i] * br[j];
        }
        __syncthreads();
    }

    #pragma unroll
    for (int i = 0; i < 8; i++) {
        const int row = brow + ty * 8 + i;
        const int orow = (EPI == 1) ? scat[row] : row;
        #pragma unroll
        for (int j4 = 0; j4 < 8; j4 += 4) {
            const int col = bcol + tx * 8 + j4;
            float4 v;
            v.x = acc[i][j4 + 0] + bias[col + 0];
            v.y = acc[i][j4 + 1] + bias[col + 1];
            v.z = acc[i][j4 + 2] + bias[col + 2];
            v.w = acc[i][j4 + 3] + bias[col + 3];
            if (EPI == 2) {
                v.x = 0.5f * v.x * (1.f + erff(v.x * 0.7071067811865475f));
                v.y = 0.5f * v.y * (1.f + erff(v.y * 0.7071067811865475f));
                v.z = 0.5f * v.z * (1.f + erff(v.z * 0.7071067811865475f));
                v.w = 0.5f * v.w * (1.f + erff(v.w * 0.7071067811865475f));
            }
            if (EPI == 3) {
                float4 r4 = *(const float4*)(res + (size_t)row * ldc + col);
                v.x += r4.x; v.y += r4.y; v.z += r4.z; v.w += r4.w;
            }
            *(float4*)(Co + (size_t)orow * ldc + col) = v;
        }
    }
}

// ---------------------------------------------------------------------------
// Per-(patch, head) attention: 48x48 softmax attention over D=64.
// grid.x = PP*HH blocks, 256 threads. Writes rows scattered by order[].
// ---------------------------------------------------------------------------
__global__ void __launch_bounds__(256)
patch_attn_kernel(const float* __restrict__ qf,
                  const float* __restrict__ qkv,
                  const int* __restrict__ order,
                  float* __restrict__ out)
{
    const int p = blockIdx.x >> 3;    // patch
    const int h = blockIdx.x & 7;     // head

    // +1 padded stride to avoid 32-way bank conflicts on the q.k^T inner loop
    __shared__ float qs[48 * 65];
    __shared__ float ks[48 * 65];
    __shared__ float vs[48 * 65];
    __shared__ float sc[48 * 48];

    const int tid = threadIdx.x;
    const size_t rowbase = (size_t)p * KK;

    for (int e = tid; e < 48 * 64; e += 256) {
        const int r = e >> 6, d = e & 63;
        qs[r * 65 + d] = qf[(rowbase + r) * CC + h * DD + d];
        ks[r * 65 + d] = qkv[(rowbase + r) * C3 + 512 + h * DD + d];
        vs[r * 65 + d] = qkv[(rowbase + r) * C3 + 1024 + h * DD + d];
    }
    __syncthreads();

    for (int e = tid; e < 48 * 48; e += 256) {
        const int i = e / 48, m = e % 48;
        float a = 0.f;
        #pragma unroll 8
        for (int d = 0; d < 64; d++)
            a += qs[i * 65 + d] * ks[m * 65 + d];
        sc[e] = a * 0.125f;   // SCALE = D^-0.5
    }
    __syncthreads();

    if (tid < 48) {
        float mx = -1e30f;
        for (int m = 0; m < 48; m++) mx = fmaxf(mx, sc[tid * 48 + m]);
        float sum = 0.f;
        for (int m = 0; m < 48; m++) {
            float ev = expf(sc[tid * 48 + m] - mx);
            sc[tid * 48 + m] = ev;
            sum += ev;
        }
        float inv = 1.f / sum;
        for (int m = 0; m < 48; m++) sc[tid * 48 + m] *= inv;
    }
    __syncthreads();

    for (int e = tid; e < 48 * 64; e += 256) {
        const int i = e >> 6, d = e & 63;
        float a = 0.f;
        #pragma unroll 8
        for (int m = 0; m < 48; m++)
            a += sc[i * 48 + m] * vs[m * 65 + d];
        const int grow = order[rowbase + i];   // scatter: permuted row i -> order[i]
        out[(size_t)grow * CC + h * DD + d] = a;
    }
}

// ---------------------------------------------------------------------------
// Host launch
// ---------------------------------------------------------------------------
extern "C" void kernel_launch(void* const* d_in, const int* in_sizes, int n_in,
                              void* d_out, int out_size)
{
    const float* sem_feat = (const float*)d_in[0];
    const float* bnd_feat = (const float*)d_in[1];
    const int*   order    = (const int*)d_in[2];
    const int*   inverse  = (const int*)d_in[3];
    const float* g_sem    = (const float*)d_in[4];
    const float* b_sem    = (const float*)d_in[5];
    const float* g_bnd    = (const float*)d_in[6];
    const float* b_bnd    = (const float*)d_in[7];
    const float* w_qkv_s  = (const float*)d_in[8];
    const float* b_qkv_s  = (const float*)d_in[9];
    const float* w_qkv_b  = (const float*)d_in[10];
    const float* b_qkv_b  = (const float*)d_in[11];
    const float* w_f1     = (const float*)d_in[12];
    const float* b_f1     = (const float*)d_in[13];
    const float* w_f2     = (const float*)d_in[14];
    const float* b_f2     = (const float*)d_in[15];
    const float* w_os     = (const float*)d_in[16];
    const float* b_os     = (const float*)d_in[17];
    const float* w_ob     = (const float*)d_in[18];
    const float* b_ob     = (const float*)d_in[19];
    float* out = (float*)d_out;

    // Resolve scratch symbol addresses (pure lookups; graph-capture safe)
    float *qkv_s, *qkv_b, *h1, *qf, *attn_s, *attn_b;
    float *mean_s, *rstd_s, *mean_b, *rstd_b;
    cudaGetSymbolAddress((void**)&qkv_s,  g_qkv_s);
    cudaGetSymbolAddress((void**)&qkv_b,  g_qkv_b);
    cudaGetSymbolAddress((void**)&h1,     g_h1);
    cudaGetSymbolAddress((void**)&qf,     g_qf);
    cudaGetSymbolAddress((void**)&attn_s, g_attn_s);
    cudaGetSymbolAddress((void**)&attn_b, g_attn_b);
    cudaGetSymbolAddress((void**)&mean_s, g_mean_s);
    cudaGetSymbolAddress((void**)&rstd_s, g_rstd_s);
    cudaGetSymbolAddress((void**)&mean_b, g_mean_b);
    cudaGetSymbolAddress((void**)&rstd_b, g_rstd_b);

    // 1) LayerNorm statistics (8 rows per 256-thread block)
    ln_stats_kernel<<<NN / 8, 256>>>(sem_feat, mean_s, rstd_s);
    ln_stats_kernel<<<NN / 8, 256>>>(bnd_feat, mean_b, rstd_b);

    // 2) QKV GEMMs with fused LN + scatter-by-inverse (result is permuted qkv)
    gemm_kernel<1, 1><<<dim3(C3 / 128, NN / 128), 256>>>(
        sem_feat, nullptr, CC, w_qkv_s, C3, b_qkv_s, qkv_s, C3,
        mean_s, rstd_s, g_sem, b_sem, inverse, nullptr, CC);
    gemm_kernel<1, 1><<<dim3(C3 / 128, NN / 128), 256>>>(
        bnd_feat, nullptr, CC, w_qkv_b, C3, b_qkv_b, qkv_b, C3,
        mean_b, rstd_b, g_bnd, b_bnd, inverse, nullptr, CC);

    // 3) Fusion MLP: h1 = gelu([q_s | q_b] @ w_f1 + b_f1)
    gemm_kernel<2, 2><<<dim3(C2 / 128, NN / 128), 256>>>(
        qkv_s, qkv_b, C3, w_f1, C2, b_f1, h1, C2,
        nullptr, nullptr, nullptr, nullptr, nullptr, nullptr, C2);

    // 4) q_fused = h1 @ w_f2 + b_f2
    gemm_kernel<0, 0><<<dim3(CC / 128, NN / 128), 256>>>(
        h1, nullptr, C2, w_f2, CC, b_f2, qf, CC,
        nullptr, nullptr, nullptr, nullptr, nullptr, nullptr, C2);

    // 5) Per-patch attention, both streams (scatter output by order -> unpermuted)
    patch_attn_kernel<<<PP * HH, 256>>>(qf, qkv_s, order, attn_s);
    patch_attn_kernel<<<PP * HH, 256>>>(qf, qkv_b, order, attn_b);

    // 6) Output projections + residual
    gemm_kernel<0, 3><<<dim3(CC / 128, NN / 128), 256>>>(
        attn_s, nullptr, CC, w_os, CC, b_os, out, CC,
        nullptr, nullptr, nullptr, nullptr, nullptr, sem_feat, CC);
    gemm_kernel<0, 3><<<dim3(CC / 128, NN / 128), 256>>>(
        attn_b, nullptr, CC, w_ob, CC, b_ob, out + (size_t)NN * CC, CC,
        nullptr, nullptr, nullptr, nullptr, nullptr, bnd_feat, CC);
}

// round 5
// speedup vs baseline: 2.4979x; 2.4979x over previous
#include <cuda_runtime.h>
#include <math.h>
#include <stdint.h>

// Problem constants
#define NN 49152
#define CC 512
#define HH 8
#define KK 48
#define DD 64
#define PP 1024            // NN / KK
#define C3 1536            // 3*C
#define C2 1024            // 2*C

// ---------------------------------------------------------------------------
// Scratch (device globals; no runtime allocation)
// ---------------------------------------------------------------------------
__device__ float g_qkv_s[(size_t)NN * C3];
__device__ float g_qkv_b[(size_t)NN * C3];
__device__ float g_h1[(size_t)NN * C2];
__device__ float g_qf[(size_t)NN * CC];
__device__ float g_attn_s[(size_t)NN * CC];
__device__ float g_attn_b[(size_t)NN * CC];
__device__ float g_mean_s[NN];
__device__ float g_rstd_s[NN];
__device__ float g_mean_b[NN];
__device__ float g_rstd_b[NN];
// Transposed + tf32-rounded weights (B^T, [N,K] row-major = K-major operand)
__device__ float g_wT_qs[(size_t)C3 * CC];
__device__ float g_wT_qb[(size_t)C3 * CC];
__device__ float g_wT_f1[(size_t)C2 * C2];
__device__ float g_wT_f2[(size_t)CC * C2];
__device__ float g_wT_os[(size_t)CC * CC];
__device__ float g_wT_ob[(size_t)CC * CC];

// ---------------------------------------------------------------------------
// tf32 helpers (base-target PTX: sm_80+ features only)
// ---------------------------------------------------------------------------
__device__ __forceinline__ float rtf(float x) {
    uint32_t u;
    asm("cvt.rna.tf32.f32 %0, %1;" : "=r"(u) : "f"(x));
    return __uint_as_float(u);
}

__device__ __forceinline__ void mma_tf32(float* d, const uint32_t* a, const uint32_t* b) {
    asm volatile(
        "mma.sync.aligned.m16n8k8.row.col.f32.tf32.tf32.f32 "
        "{%0,%1,%2,%3}, {%4,%5,%6,%7}, {%8,%9}, {%0,%1,%2,%3};"
        : "+f"(d[0]), "+f"(d[1]), "+f"(d[2]), "+f"(d[3])
        : "r"(a[0]), "r"(a[1]), "r"(a[2]), "r"(a[3]), "r"(b[0]), "r"(b[1]));
}

// ---------------------------------------------------------------------------
// Weight transpose + tf32 rounding: out[c][r] = tf32(in[r][c])
// ---------------------------------------------------------------------------
__global__ void transpose_kernel(const float* __restrict__ in, float* __restrict__ out,
                                 int R, int C)
{
    __shared__ float t[32][33];
    int bx = blockIdx.x * 32, by = blockIdx.y * 32;
    for (int i = threadIdx.y; i < 32; i += 8)
        t[i][threadIdx.x] = in[(size_t)(by + i) * C + bx + threadIdx.x];
    __syncthreads();
    for (int i = threadIdx.y; i < 32; i += 8)
        out[(size_t)(bx + i) * R + by + threadIdx.x] = rtf(t[threadIdx.x][i]);
}

// ---------------------------------------------------------------------------
// LayerNorm row statistics: one warp per row of 512
// ---------------------------------------------------------------------------
__global__ void ln_stats_kernel(const float* __restrict__ x,
                                float* __restrict__ mean, float* __restrict__ rstd)
{
    int warp = (blockIdx.x * blockDim.x + threadIdx.x) >> 5;
    int lane = threadIdx.x & 31;
    if (warp >= NN) return;
    const float* row = x + (size_t)warp * CC;
    float s = 0.f, sq = 0.f;
    #pragma unroll 4
    for (int i = lane; i < CC; i += 32) { float v = row[i]; s += v; sq += v * v; }
    #pragma unroll
    for (int o = 16; o > 0; o >>= 1) {
        s  += __shfl_xor_sync(0xffffffffu, s, o);
        sq += __shfl_xor_sync(0xffffffffu, sq, o);
    }
    if (lane == 0) {
        float m = s * (1.f / CC);
        float var = sq * (1.f / CC) - m * m;
        mean[warp] = m;
        rstd[warp] = rsqrtf(var + 1e-5f);
    }
}

// ---------------------------------------------------------------------------
// TF32 mma.sync GEMM: C[128x128 tile] = op(A)[128xK] @ B^T + epilogue
// A: [M,K] row-major fp32. BT: [N,K] row-major fp32 (tf32-pre-rounded).
// AMODE: 0 plain, 1 LayerNorm transform, 2 concat(A|A2)
// EPI:   0 bias, 1 bias+scatter(scat[row]), 2 bias+GELU, 3 bias+residual
// 256 threads (8 warps, 2x4), warp tile 64x32, K-chunk 32, double-buffered.
// Smem in fragment-major layout; odd ks-slice pads kill STS bank conflicts.
// ---------------------------------------------------------------------------
template<int AMODE, int EPI>
__global__ void __launch_bounds__(256)
gemm_mma(const float* __restrict__ A, const float* __restrict__ A2, int lda,
         const float* __restrict__ BT, const float* __restrict__ bias,
         float* __restrict__ Co, int ldc,
         const float* __restrict__ mean, const float* __restrict__ rstd,
         const float* __restrict__ lng, const float* __restrict__ lnb,
         const int* __restrict__ scat, const float* __restrict__ res, int Kd)
{
    extern __shared__ float sm[];
    // A: stage*4112 + ks*1028 + (mf*32 + lane)*4 + reg   (4 ks-slices, 8 m-frags)
    // B: stage*4104 + ks*1026 + (nf*32 + lane)*2 + reg   (4 ks-slices, 16 n-frags)
    float* sA = sm;
    float* sB = sm + 8224;

    const int tid  = threadIdx.x;
    const int lane = tid & 31, wid = tid >> 5;
    const int brow = blockIdx.y * 128, bcol = blockIdx.x * 128;
    const int rbase = tid >> 3;        // 0..31 : row offset for staging
    const int c4    = tid & 7;         // which float4 within the 32-col chunk
    const int mf0 = (wid >> 2) * 4, nf0 = (wid & 3) * 4;
    const int ksA = c4 >> 1;           // ks slice this thread's float4 lands in
    const int regA_hi = (c4 & 1) << 1; // fc>=4 bit of A reg index
    const int regB = c4 & 1;           // fk>=4 bit of B reg index

    float acc[4][4][4];
    #pragma unroll
    for (int a = 0; a < 4; a++)
        #pragma unroll
        for (int b = 0; b < 4; b++)
            #pragma unroll
            for (int r = 0; r < 4; r++) acc[a][b][r] = 0.f;

    float mrow[4], rrow[4];
    if (AMODE == 1) {
        #pragma unroll
        for (int i = 0; i < 4; i++) {
            mrow[i] = mean[brow + rbase + 32 * i];
            rrow[i] = rstd[brow + rbase + 32 * i];
        }
    }

    float4 rA[4], rB[4];

    auto LDG = [&](int c) {
        const int gk = (c << 5) + (c4 << 2);
        #pragma unroll
        for (int i = 0; i < 4; i++) {
            const int row = brow + rbase + 32 * i;
            if (AMODE == 2) {
                const float* s = (gk < 512) ? A : A2;
                const int k2 = (gk < 512) ? gk : gk - 512;
                rA[i] = *(const float4*)(s + (size_t)row * lda + k2);
            } else {
                rA[i] = *(const float4*)(A + (size_t)row * lda + gk);
            }
        }
        #pragma unroll
        for (int i = 0; i < 4; i++) {
            const int nrow = bcol + rbase + 32 * i;
            rB[i] = *(const float4*)(BT + (size_t)nrow * Kd + gk);
        }
    };

    auto STS = [&](int st, int c) {
        float4 g4, b4;
        if (AMODE == 1) {
            const int gk = (c << 5) + (c4 << 2);
            g4 = *(const float4*)(lng + gk);
            b4 = *(const float4*)(lnb + gk);
        }
        #pragma unroll
        for (int i = 0; i < 4; i++) {
            float va[4] = { rA[i].x, rA[i].y, rA[i].z, rA[i].w };
            if (AMODE == 1) {
                const float gg[4] = { g4.x, g4.y, g4.z, g4.w };
                const float bb[4] = { b4.x, b4.y, b4.z, b4.w };
                #pragma unroll
                for (int j = 0; j < 4; j++)
                    va[j] = (va[j] - mrow[i]) * rrow[i] * gg[j] + bb[j];
            }
            const int row = rbase + 32 * i;
            const int mf = row >> 4, fr = row & 15;
            const int regA = (fr >> 3) | regA_hi;
            float* pa = sA + st * 4112 + ksA * 1028 + (mf * 32 + ((fr & 7) << 2)) * 4 + regA;
            #pragma unroll
            for (int j = 0; j < 4; j++) pa[j * 4] = rtf(va[j]);

            const float vb[4] = { rB[i].x, rB[i].y, rB[i].z, rB[i].w };
            const int nf = row >> 3, fn = row & 7;
            float* pb = sB + st * 4104 + ksA * 1026 + (nf * 32 + (fn << 2)) * 2 + regB;
            #pragma unroll
            for (int j = 0; j < 4; j++) pb[j * 2] = vb[j];
        }
    };

    auto COMPUTE = [&](int st) {
        #pragma unroll
        for (int ks = 0; ks < 4; ks++) {
            uint32_t af[4][4], bf[4][2];
            #pragma unroll
            for (int mi = 0; mi < 4; mi++) {
                const float4 t = *(const float4*)(sA + st * 4112 + ks * 1028 +
                                                  ((mf0 + mi) * 32 + lane) * 4);
                af[mi][0] = __float_as_uint(t.x); af[mi][1] = __float_as_uint(t.y);
                af[mi][2] = __float_as_uint(t.z); af[mi][3] = __float_as_uint(t.w);
            }
            #pragma unroll
            for (int ni = 0; ni < 4; ni++) {
                const float2 t = *(const float2*)(sB + st * 4104 + ks * 1026 +
                                                  ((nf0 + ni) * 32 + lane) * 2);
                bf[ni][0] = __float_as_uint(t.x); bf[ni][1] = __float_as_uint(t.y);
            }
            #pragma unroll
            for (int mi = 0; mi < 4; mi++)
                #pragma unroll
                for (int ni = 0; ni < 4; ni++)
                    mma_tf32(acc[mi][ni], af[mi], bf[ni]);
        }
    };

    const int KC = Kd >> 5;
    LDG(0);
    STS(0, 0);
    __syncthreads();
    for (int c = 0; c < KC; c++) {
        if (c + 1 < KC) LDG(c + 1);
        COMPUTE(c & 1);
        if (c + 1 < KC) {
            STS((c + 1) & 1, c + 1);
            __syncthreads();
        }
    }

    // ---- epilogue: fused bias / gelu / scatter / residual
    const int wm = (wid >> 2) * 64, wn = (wid & 3) * 32;
    #pragma unroll
    for (int mi = 0; mi < 4; mi++) {
        const int ra = brow + wm + mi * 16 + (lane >> 2);
        const int rb = ra + 8;
        const int ora = (EPI == 1) ? scat[ra] : ra;
        const int orb = (EPI == 1) ? scat[rb] : rb;
        #pragma unroll
        for (int ni = 0; ni < 4; ni++) {
            const int col = bcol + wn + ni * 8 + (lane & 3) * 2;
            const float b0 = bias[col], b1 = bias[col + 1];
            float v0 = acc[mi][ni][0] + b0, v1 = acc[mi][ni][1] + b1;
            float v2 = acc[mi][ni][2] + b0, v3 = acc[mi][ni][3] + b1;
            if (EPI == 2) {
                v0 = 0.5f * v0 * (1.f + erff(v0 * 0.7071067811865475f));
                v1 = 0.5f * v1 * (1.f + erff(v1 * 0.7071067811865475f));
                v2 = 0.5f * v2 * (1.f + erff(v2 * 0.7071067811865475f));
                v3 = 0.5f * v3 * (1.f + erff(v3 * 0.7071067811865475f));
            }
            if (EPI == 3) {
                v0 += res[(size_t)ra * ldc + col];
                v1 += res[(size_t)ra * ldc + col + 1];
                v2 += res[(size_t)rb * ldc + col];
                v3 += res[(size_t)rb * ldc + col + 1];
            }
            *(float2*)(Co + (size_t)ora * ldc + col) = make_float2(v0, v1);
            *(float2*)(Co + (size_t)orb * ldc + col) = make_float2(v2, v3);
        }
    }
}

// ---------------------------------------------------------------------------
// Per-(patch, head) attention: 48x48 softmax attention over D=64 (fp32)
// ---------------------------------------------------------------------------
__global__ void __launch_bounds__(256)
patch_attn_kernel(const float* __restrict__ qf,
                  const float* __restrict__ qkv,
                  const int* __restrict__ order,
                  float* __restrict__ out)
{
    const int p = blockIdx.x >> 3;
    const int h = blockIdx.x & 7;

    __shared__ float qs[48 * 65];
    __shared__ float ks[48 * 65];
    __shared__ float vs[48 * 65];
    __shared__ float sc[48 * 48];

    const int tid = threadIdx.x;
    const size_t rowbase = (size_t)p * KK;

    for (int e = tid; e < 48 * 64; e += 256) {
        const int r = e >> 6, d = e & 63;
        qs[r * 65 + d] = qf[(rowbase + r) * CC + h * DD + d];
        ks[r * 65 + d] = qkv[(rowbase + r) * C3 + 512 + h * DD + d];
        vs[r * 65 + d] = qkv[(rowbase + r) * C3 + 1024 + h * DD + d];
    }
    __syncthreads();

    for (int e = tid; e < 48 * 48; e += 256) {
        const int i = e / 48, m = e % 48;
        float a = 0.f;
        #pragma unroll 8
        for (int d = 0; d < 64; d++) a += qs[i * 65 + d] * ks[m * 65 + d];
        sc[e] = a * 0.125f;
    }
    __syncthreads();

    if (tid < 48) {
        float mx = -1e30f;
        for (int m = 0; m < 48; m++) mx = fmaxf(mx, sc[tid * 48 + m]);
        float sum = 0.f;
        for (int m = 0; m < 48; m++) {
            float ev = expf(sc[tid * 48 + m] - mx);
            sc[tid * 48 + m] = ev;
            sum += ev;
        }
        float inv = 1.f / sum;
        for (int m = 0; m < 48; m++) sc[tid * 48 + m] *= inv;
    }
    __syncthreads();

    for (int e = tid; e < 48 * 64; e += 256) {
        const int i = e >> 6, d = e & 63;
        float a = 0.f;
        #pragma unroll 8
        for (int m = 0; m < 48; m++) a += sc[i * 48 + m] * vs[m * 65 + d];
        const int grow = order[rowbase + i];
        out[(size_t)grow * CC + h * DD + d] = a;
    }
}

// ---------------------------------------------------------------------------
// Host launch
// ---------------------------------------------------------------------------
extern "C" void kernel_launch(void* const* d_in, const int* in_sizes, int n_in,
                              void* d_out, int out_size)
{
    const float* sem_feat = (const float*)d_in[0];
    const float* bnd_feat = (const float*)d_in[1];
    const int*   order    = (const int*)d_in[2];
    const int*   inverse  = (const int*)d_in[3];
    const float* g_sem    = (const float*)d_in[4];
    const float* b_sem    = (const float*)d_in[5];
    const float* g_bnd    = (const float*)d_in[6];
    const float* b_bnd    = (const float*)d_in[7];
    const float* w_qkv_s  = (const float*)d_in[8];
    const float* b_qkv_s  = (const float*)d_in[9];
    const float* w_qkv_b  = (const float*)d_in[10];
    const float* b_qkv_b  = (const float*)d_in[11];
    const float* w_f1     = (const float*)d_in[12];
    const float* b_f1     = (const float*)d_in[13];
    const float* w_f2     = (const float*)d_in[14];
    const float* b_f2     = (const float*)d_in[15];
    const float* w_os     = (const float*)d_in[16];
    const float* b_os     = (const float*)d_in[17];
    const float* w_ob     = (const float*)d_in[18];
    const float* b_ob     = (const float*)d_in[19];
    float* out = (float*)d_out;

    float *qkv_s, *qkv_b, *h1, *qf, *attn_s, *attn_b;
    float *mean_s, *rstd_s, *mean_b, *rstd_b;
    float *wT_qs, *wT_qb, *wT_f1, *wT_f2, *wT_os, *wT_ob;
    cudaGetSymbolAddress((void**)&qkv_s,  g_qkv_s);
    cudaGetSymbolAddress((void**)&qkv_b,  g_qkv_b);
    cudaGetSymbolAddress((void**)&h1,     g_h1);
    cudaGetSymbolAddress((void**)&qf,     g_qf);
    cudaGetSymbolAddress((void**)&attn_s, g_attn_s);
    cudaGetSymbolAddress((void**)&attn_b, g_attn_b);
    cudaGetSymbolAddress((void**)&mean_s, g_mean_s);
    cudaGetSymbolAddress((void**)&rstd_s, g_rstd_s);
    cudaGetSymbolAddress((void**)&mean_b, g_mean_b);
    cudaGetSymbolAddress((void**)&rstd_b, g_rstd_b);
    cudaGetSymbolAddress((void**)&wT_qs,  g_wT_qs);
    cudaGetSymbolAddress((void**)&wT_qb,  g_wT_qb);
    cudaGetSymbolAddress((void**)&wT_f1,  g_wT_f1);
    cudaGetSymbolAddress((void**)&wT_f2,  g_wT_f2);
    cudaGetSymbolAddress((void**)&wT_os,  g_wT_os);
    cudaGetSymbolAddress((void**)&wT_ob,  g_wT_ob);

    const int SMEM_DYN = 16432 * 4;   // 65728 B
    cudaFuncSetAttribute(gemm_mma<1, 1>, cudaFuncAttributeMaxDynamicSharedMemorySize, SMEM_DYN);
    cudaFuncSetAttribute(gemm_mma<2, 2>, cudaFuncAttributeMaxDynamicSharedMemorySize, SMEM_DYN);
    cudaFuncSetAttribute(gemm_mma<0, 0>, cudaFuncAttributeMaxDynamicSharedMemorySize, SMEM_DYN);
    cudaFuncSetAttribute(gemm_mma<0, 3>, cudaFuncAttributeMaxDynamicSharedMemorySize, SMEM_DYN);

    dim3 tb(32, 8);
    // 0) weight transposes ([K,N] -> [N,K] K-major, tf32-rounded)
    transpose_kernel<<<dim3(C3 / 32, CC / 32), tb>>>(w_qkv_s, wT_qs, CC, C3);
    transpose_kernel<<<dim3(C3 / 32, CC / 32), tb>>>(w_qkv_b, wT_qb, CC, C3);
    transpose_kernel<<<dim3(C2 / 32, C2 / 32), tb>>>(w_f1, wT_f1, C2, C2);
    transpose_kernel<<<dim3(CC / 32, C2 / 32), tb>>>(w_f2, wT_f2, C2, CC);
    transpose_kernel<<<dim3(CC / 32, CC / 32), tb>>>(w_os, wT_os, CC, CC);
    transpose_kernel<<<dim3(CC / 32, CC / 32), tb>>>(w_ob, wT_ob, CC, CC);

    // 1) LayerNorm statistics
    ln_stats_kernel<<<NN / 8, 256>>>(sem_feat, mean_s, rstd_s);
    ln_stats_kernel<<<NN / 8, 256>>>(bnd_feat, mean_b, rstd_b);

    // 2) QKV GEMMs (fused LN + scatter by inverse)
    gemm_mma<1, 1><<<dim3(C3 / 128, NN / 128), 256, SMEM_DYN>>>(
        sem_feat, nullptr, CC, wT_qs, b_qkv_s, qkv_s, C3,
        mean_s, rstd_s, g_sem, b_sem, inverse, nullptr, CC);
    gemm_mma<1, 1><<<dim3(C3 / 128, NN / 128), 256, SMEM_DYN>>>(
        bnd_feat, nullptr, CC, wT_qb, b_qkv_b, qkv_b, C3,
        mean_b, rstd_b, g_bnd, b_bnd, inverse, nullptr, CC);

    // 3) Fusion MLP layer 1 (concat A + GELU epilogue)
    gemm_mma<2, 2><<<dim3(C2 / 128, NN / 128), 256, SMEM_DYN>>>(
        qkv_s, qkv_b, C3, wT_f1, b_f1, h1, C2,
        nullptr, nullptr, nullptr, nullptr, nullptr, nullptr, C2);

    // 4) Fusion MLP layer 2
    gemm_mma<0, 0><<<dim3(CC / 128, NN / 128), 256, SMEM_DYN>>>(
        h1, nullptr, C2, wT_f2, b_f2, qf, CC,
        nullptr, nullptr, nullptr, nullptr, nullptr, nullptr, C2);

    // 5) Per-patch attention (scatter by order -> unpermuted)
    patch_attn_kernel<<<PP * HH, 256>>>(qf, qkv_s, order, attn_s);
    patch_attn_kernel<<<PP * HH, 256>>>(qf, qkv_b, order, attn_b);

    // 6) Output projections + residual
    gemm_mma<0, 3><<<dim3(CC / 128, NN / 128), 256, SMEM_DYN>>>(
        attn_s, nullptr, CC, wT_os, b_os, out, CC,
        nullptr, nullptr, nullptr, nullptr, nullptr, sem_feat, CC);
    gemm_mma<0, 3><<<dim3(CC / 128, NN / 128), 256, SMEM_DYN>>>(
        attn_b, nullptr, CC, wT_ob, b_ob, out + (size_t)NN * CC, CC,
        nullptr, nullptr, nullptr, nullptr, nullptr, bnd_feat, CC);
}

// round 6
// speedup vs baseline: 3.2543x; 1.3028x over previous
#include <cuda_runtime.h>
#include <cuda_fp16.h>
#include <math.h>
#include <stdint.h>

// Problem constants
#define NN 49152
#define CC 512
#define HH 8
#define KK 48
#define DD 64
#define PP 1024            // NN / KK
#define C3 1536            // 3*C
#define C2 1024            // 2*C

// ---------------------------------------------------------------------------
// Scratch (device globals; no runtime allocation)
// ---------------------------------------------------------------------------
__device__ float g_qkv_s[(size_t)NN * C3];
__device__ float g_qkv_b[(size_t)NN * C3];
__device__ float g_h1[(size_t)NN * C2];
__device__ float g_qf[(size_t)NN * CC];
__device__ float g_attn_s[(size_t)NN * CC];
__device__ float g_attn_b[(size_t)NN * CC];
__device__ float g_mean_s[NN];
__device__ float g_rstd_s[NN];
__device__ float g_mean_b[NN];
__device__ float g_rstd_b[NN];
// Packed fp16 weights in per-chunk fragment-major layout:
// u32 index = ((chunk*(N/128) + nblk)*4 + k16step)*1024 + nfrag*64 + lane*2 + reg
__device__ uint32_t g_wp_qs[(size_t)(CC / 2) * C3];
__device__ uint32_t g_wp_qb[(size_t)(CC / 2) * C3];
__device__ uint32_t g_wp_f1[(size_t)(C2 / 2) * C2];
__device__ uint32_t g_wp_f2[(size_t)(C2 / 2) * CC];
__device__ uint32_t g_wp_os[(size_t)(CC / 2) * CC];
__device__ uint32_t g_wp_ob[(size_t)(CC / 2) * CC];

// ---------------------------------------------------------------------------
// Helpers (base-target PTX, sm_80+ only)
// ---------------------------------------------------------------------------
__device__ __forceinline__ uint32_t pack2h(float a, float b) {
    __half2 h = __floats2half2_rn(a, b);
    return *reinterpret_cast<uint32_t*>(&h);
}

__device__ __forceinline__ void mma_f16(float* d, const uint32_t* a, const uint32_t* b) {
    asm volatile(
        "mma.sync.aligned.m16n8k16.row.col.f32.f16.f16.f32 "
        "{%0,%1,%2,%3}, {%4,%5,%6,%7}, {%8,%9}, {%0,%1,%2,%3};"
        : "+f"(d[0]), "+f"(d[1]), "+f"(d[2]), "+f"(d[3])
        : "r"(a[0]), "r"(a[1]), "r"(a[2]), "r"(a[3]), "r"(b[0]), "r"(b[1]));
}

__device__ __forceinline__ void cp16(uint32_t saddr, const void* gptr) {
    asm volatile("cp.async.cg.shared.global [%0], [%1], 16;" :: "r"(saddr), "l"(gptr));
}
#define CP_COMMIT() asm volatile("cp.async.commit_group;" ::: "memory")
#define CP_WAIT0()  asm volatile("cp.async.wait_group 0;" ::: "memory")

// ---------------------------------------------------------------------------
// Weight pack: w [K,N] fp32 row-major -> fp16 pairs in fragment-major layout
// ---------------------------------------------------------------------------
__global__ void prep_w(const float* __restrict__ w, uint32_t* __restrict__ out,
                       int Kd, int Nd)
{
    int idx = blockIdx.x * 256 + threadIdx.x;      // over (K/2)*N
    if (idx >= (Kd >> 1) * Nd) return;
    int n  = idx % Nd;
    int k  = (idx / Nd) << 1;                      // even k
    float v0 = w[(size_t)k * Nd + n];
    float v1 = w[(size_t)(k + 1) * Nd + n];
    int cc   = k >> 6;
    int step = (k >> 4) & 3;
    int nblk = n >> 7, nn = n & 127;
    int nfrag = nn >> 3;
    int lane  = (nn & 7) * 4 + ((k & 7) >> 1);
    int reg   = (k & 15) >> 3;
    size_t o = ((size_t)(cc * (Nd >> 7) + nblk) * 4 + step) * 1024
             + nfrag * 64 + lane * 2 + reg;
    out[o] = pack2h(v0, v1);
}

// ---------------------------------------------------------------------------
// LayerNorm row statistics: one warp per row of 512
// ---------------------------------------------------------------------------
__global__ void ln_stats_kernel(const float* __restrict__ x,
                                float* __restrict__ mean, float* __restrict__ rstd)
{
    int warp = (blockIdx.x * blockDim.x + threadIdx.x) >> 5;
    int lane = threadIdx.x & 31;
    if (warp >= NN) return;
    const float* row = x + (size_t)warp * CC;
    float s = 0.f, sq = 0.f;
    #pragma unroll 4
    for (int i = lane; i < CC; i += 32) { float v = row[i]; s += v; sq += v * v; }
    #pragma unroll
    for (int o = 16; o > 0; o >>= 1) {
        s  += __shfl_xor_sync(0xffffffffu, s, o);
        sq += __shfl_xor_sync(0xffffffffu, sq, o);
    }
    if (lane == 0) {
        float m = s * (1.f / CC);
        float var = sq * (1.f / CC) - m * m;
        mean[warp] = m;
        rstd[warp] = rsqrtf(var + 1e-5f);
    }
}

// ---------------------------------------------------------------------------
// FP16 mma.sync GEMM: C[128x128] = op(A)[128xK] @ W + epilogue
// A fp32 [M,K] row-major (converted fp16 in staging); W pre-packed fp16 frags.
// AMODE: 0 plain, 1 LayerNorm transform, 2 concat(A|A2)
// EPI:   0 bias, 1 bias+scatter, 2 bias+GELU, 3 bias+residual
// 256 threads (8 warps 2x4), warp tile 64x32, K-chunk 64 (4 k16-steps),
// double-buffered; B via cp.async (contiguous), A via reg path with transform.
// ---------------------------------------------------------------------------
template<int AMODE, int EPI>
__global__ void __launch_bounds__(256)
gemm_mma(const float* __restrict__ A, const float* __restrict__ A2, int lda,
         const uint32_t* __restrict__ Bp, int nbCols,
         const float* __restrict__ bias,
         float* __restrict__ Co, int ldc,
         const float* __restrict__ mean, const float* __restrict__ rstd,
         const float* __restrict__ lng, const float* __restrict__ lnb,
         const int* __restrict__ scat, const float* __restrict__ res, int Kd)
{
    extern __shared__ uint32_t sm[];
    // A: [stage:4128][step:1032][mfrag:128][lane:4][reg]  (pad 8 u32/step)
    // B: [stage:4096][step:1024][nfrag:64][lane:2][reg]
    uint32_t* sA = sm;
    uint32_t* sB = sm + 8256;
    uint32_t sBaddr;
    asm("{ .reg .u64 t; cvta.to.shared.u64 t, %1; cvt.u32.u64 %0, t; }"
        : "=r"(sBaddr) : "l"((const void*)sB));

    const int tid  = threadIdx.x;
    const int lane = tid & 31, wid = tid >> 5;
    const int brow = blockIdx.y * 128, bcol = blockIdx.x * 128;
    const int nblk = blockIdx.x;
    const int mf0 = (wid >> 2) * 4, nf0 = (wid & 3) * 4;

    // A staging geometry: thread covers row rbase (+16*i), k-quad kq
    const int rbase = tid >> 4;              // 0..15
    const int kq    = (tid & 15) << 2;       // 0..60
    const int stepT = kq >> 4;               // k16-step
    const int laneq = (rbase & 7) * 4 + ((kq & 7) >> 1);
    const int regA  = (rbase >> 3) + ((kq >> 3) & 1) * 2;
    const int aoffT = stepT * 1032 + laneq * 4 + regA;

    float acc[4][4][4];
    #pragma unroll
    for (int a = 0; a < 4; a++)
        #pragma unroll
        for (int b = 0; b < 4; b++)
            #pragma unroll
            for (int r = 0; r < 4; r++) acc[a][b][r] = 0.f;

    float mrow[8], rrow[8];
    if (AMODE == 1) {
        #pragma unroll
        for (int i = 0; i < 8; i++) {
            mrow[i] = mean[brow + rbase + 16 * i];
            rrow[i] = rstd[brow + rbase + 16 * i];
        }
    }

    float4 rA[8];

    auto CPB = [&](int c, int st) {
        const uint32_t* src = Bp + ((size_t)(c * nbCols + nblk) << 12);
        #pragma unroll
        for (int j = 0; j < 4; j++)
            cp16(sBaddr + ((st << 12) + (j << 10) + (tid << 2)) * 4,
                 src + (j << 10) + (tid << 2));
        CP_COMMIT();
    };

    auto LDGA = [&](int c) {
        const int gk = (c << 6) + kq;
        #pragma unroll
        for (int i = 0; i < 8; i++) {
            const int row = brow + rbase + 16 * i;
            if (AMODE == 2) {
                const float* s = (gk < 512) ? A : A2;
                const int k2 = (gk < 512) ? gk : gk - 512;
                rA[i] = *(const float4*)(s + (size_t)row * lda + k2);
            } else {
                rA[i] = *(const float4*)(A + (size_t)row * lda + gk);
            }
        }
    };

    auto STSA = [&](int st, int c) {
        float4 g4, b4;
        if (AMODE == 1) {
            const int gk = (c << 6) + kq;
            g4 = *(const float4*)(lng + gk);
            b4 = *(const float4*)(lnb + gk);
        }
        uint32_t* base = sA + st * 4128 + aoffT;
        #pragma unroll
        for (int i = 0; i < 8; i++) {
            float v0 = rA[i].x, v1 = rA[i].y, v2 = rA[i].z, v3 = rA[i].w;
            if (AMODE == 1) {
                v0 = (v0 - mrow[i]) * rrow[i] * g4.x + b4.x;
                v1 = (v1 - mrow[i]) * rrow[i] * g4.y + b4.y;
                v2 = (v2 - mrow[i]) * rrow[i] * g4.z + b4.z;
                v3 = (v3 - mrow[i]) * rrow[i] * g4.w + b4.w;
            }
            uint32_t* p = base + i * 128;     // mfrag = i
            p[0] = pack2h(v0, v1);
            p[4] = pack2h(v2, v3);
        }
    };

    auto COMPUTE = [&](int st) {
        #pragma unroll
        for (int ks = 0; ks < 4; ks++) {
            uint32_t af[4][4], bf[4][2];
            #pragma unroll
            for (int mi = 0; mi < 4; mi++) {
                uint4 t = *(const uint4*)(sA + st * 4128 + ks * 1032 +
                                          (mf0 + mi) * 128 + lane * 4);
                af[mi][0] = t.x; af[mi][1] = t.y; af[mi][2] = t.z; af[mi][3] = t.w;
            }
            #pragma unroll
            for (int ni = 0; ni < 4; ni++) {
                uint2 t = *(const uint2*)(sB + st * 4096 + ks * 1024 +
                                          (nf0 + ni) * 64 + lane * 2);
                bf[ni][0] = t.x; bf[ni][1] = t.y;
            }
            #pragma unroll
            for (int mi = 0; mi < 4; mi++)
                #pragma unroll
                for (int ni = 0; ni < 4; ni++)
                    mma_f16(acc[mi][ni], af[mi], bf[ni]);
        }
    };

    const int KC = Kd >> 6;
    CPB(0, 0);
    LDGA(0);
    STSA(0, 0);
    CP_WAIT0();
    __syncthreads();
    for (int c = 0; c < KC; c++) {
        const int st = c & 1;
        if (c + 1 < KC) { CPB(c + 1, st ^ 1); LDGA(c + 1); }
        COMPUTE(st);
        if (c + 1 < KC) {
            STSA(st ^ 1, c + 1);
            CP_WAIT0();
            __syncthreads();
        }
    }

    // ---- epilogue: fused bias / gelu / scatter / residual
    const int wm = (wid >> 2) * 64, wn = (wid & 3) * 32;
    #pragma unroll
    for (int mi = 0; mi < 4; mi++) {
        const int ra = brow + wm + mi * 16 + (lane >> 2);
        const int rb = ra + 8;
        const int ora = (EPI == 1) ? scat[ra] : ra;
        const int orb = (EPI == 1) ? scat[rb] : rb;
        #pragma unroll
        for (int ni = 0; ni < 4; ni++) {
            const int col = bcol + wn + ni * 8 + (lane & 3) * 2;
            const float b0 = bias[col], b1 = bias[col + 1];
            float v0 = acc[mi][ni][0] + b0, v1 = acc[mi][ni][1] + b1;
            float v2 = acc[mi][ni][2] + b0, v3 = acc[mi][ni][3] + b1;
            if (EPI == 2) {
                v0 = 0.5f * v0 * (1.f + erff(v0 * 0.7071067811865475f));
                v1 = 0.5f * v1 * (1.f + erff(v1 * 0.7071067811865475f));
                v2 = 0.5f * v2 * (1.f + erff(v2 * 0.7071067811865475f));
                v3 = 0.5f * v3 * (1.f + erff(v3 * 0.7071067811865475f));
            }
            if (EPI == 3) {
                v0 += res[(size_t)ra * ldc + col];
                v1 += res[(size_t)ra * ldc + col + 1];
                v2 += res[(size_t)rb * ldc + col];
                v3 += res[(size_t)rb * ldc + col + 1];
            }
            *(float2*)(Co + (size_t)ora * ldc + col) = make_float2(v0, v1);
            *(float2*)(Co + (size_t)orb * ldc + col) = make_float2(v2, v3);
        }
    }
}

// ---------------------------------------------------------------------------
// Per-(patch, head) attention: 48x48 softmax attention over D=64 (fp32)
// ---------------------------------------------------------------------------
__global__ void __launch_bounds__(256)
patch_attn_kernel(const float* __restrict__ qf,
                  const float* __restrict__ qkv,
                  const int* __restrict__ order,
                  float* __restrict__ out)
{
    const int p = blockIdx.x >> 3;
    const int h = blockIdx.x & 7;

    __shared__ float qs[48 * 65];
    __shared__ float ks[48 * 65];
    __shared__ float vs[48 * 65];
    __shared__ float sc[48 * 48];

    const int tid = threadIdx.x;
    const size_t rowbase = (size_t)p * KK;

    for (int e = tid; e < 48 * 64; e += 256) {
        const int r = e >> 6, d = e & 63;
        qs[r * 65 + d] = qf[(rowbase + r) * CC + h * DD + d];
        ks[r * 65 + d] = qkv[(rowbase + r) * C3 + 512 + h * DD + d];
        vs[r * 65 + d] = qkv[(rowbase + r) * C3 + 1024 + h * DD + d];
    }
    __syncthreads();

    for (int e = tid; e < 48 * 48; e += 256) {
        const int i = e / 48, m = e % 48;
        float a = 0.f;
        #pragma unroll 8
        for (int d = 0; d < 64; d++) a += qs[i * 65 + d] * ks[m * 65 + d];
        sc[e] = a * 0.125f;
    }
    __syncthreads();

    if (tid < 48) {
        float mx = -1e30f;
        for (int m = 0; m < 48; m++) mx = fmaxf(mx, sc[tid * 48 + m]);
        float sum = 0.f;
        for (int m = 0; m < 48; m++) {
            float ev = expf(sc[tid * 48 + m] - mx);
            sc[tid * 48 + m] = ev;
            sum += ev;
        }
        float inv = 1.f / sum;
        for (int m = 0; m < 48; m++) sc[tid * 48 + m] *= inv;
    }
    __syncthreads();

    for (int e = tid; e < 48 * 64; e += 256) {
        const int i = e >> 6, d = e & 63;
        float a = 0.f;
        #pragma unroll 8
        for (int m = 0; m < 48; m++) a += sc[i * 48 + m] * vs[m * 65 + d];
        const int grow = order[rowbase + i];
        out[(size_t)grow * CC + h * DD + d] = a;
    }
}

// ---------------------------------------------------------------------------
// Host launch
// ---------------------------------------------------------------------------
extern "C" void kernel_launch(void* const* d_in, const int* in_sizes, int n_in,
                              void* d_out, int out_size)
{
    const float* sem_feat = (const float*)d_in[0];
    const float* bnd_feat = (const float*)d_in[1];
    const int*   order    = (const int*)d_in[2];
    const int*   inverse  = (const int*)d_in[3];
    const float* g_sem    = (const float*)d_in[4];
    const float* b_sem    = (const float*)d_in[5];
    const float* g_bnd    = (const float*)d_in[6];
    const float* b_bnd    = (const float*)d_in[7];
    const float* w_qkv_s  = (const float*)d_in[8];
    const float* b_qkv_s  = (const float*)d_in[9];
    const float* w_qkv_b  = (const float*)d_in[10];
    const float* b_qkv_b  = (const float*)d_in[11];
    const float* w_f1     = (const float*)d_in[12];
    const float* b_f1     = (const float*)d_in[13];
    const float* w_f2     = (const float*)d_in[14];
    const float* b_f2     = (const float*)d_in[15];
    const float* w_os     = (const float*)d_in[16];
    const float* b_os     = (const float*)d_in[17];
    const float* w_ob     = (const float*)d_in[18];
    const float* b_ob     = (const float*)d_in[19];
    float* out = (float*)d_out;

    float *qkv_s, *qkv_b, *h1, *qf, *attn_s, *attn_b;
    float *mean_s, *rstd_s, *mean_b, *rstd_b;
    uint32_t *wp_qs, *wp_qb, *wp_f1, *wp_f2, *wp_os, *wp_ob;
    cudaGetSymbolAddress((void**)&qkv_s,  g_qkv_s);
    cudaGetSymbolAddress((void**)&qkv_b,  g_qkv_b);
    cudaGetSymbolAddress((void**)&h1,     g_h1);
    cudaGetSymbolAddress((void**)&qf,     g_qf);
    cudaGetSymbolAddress((void**)&attn_s, g_attn_s);
    cudaGetSymbolAddress((void**)&attn_b, g_attn_b);
    cudaGetSymbolAddress((void**)&mean_s, g_mean_s);
    cudaGetSymbolAddress((void**)&rstd_s, g_rstd_s);
    cudaGetSymbolAddress((void**)&mean_b, g_mean_b);
    cudaGetSymbolAddress((void**)&rstd_b, g_rstd_b);
    cudaGetSymbolAddress((void**)&wp_qs,  g_wp_qs);
    cudaGetSymbolAddress((void**)&wp_qb,  g_wp_qb);
    cudaGetSymbolAddress((void**)&wp_f1,  g_wp_f1);
    cudaGetSymbolAddress((void**)&wp_f2,  g_wp_f2);
    cudaGetSymbolAddress((void**)&wp_os,  g_wp_os);
    cudaGetSymbolAddress((void**)&wp_ob,  g_wp_ob);

    const int SMEM_DYN = (8256 + 8192) * 4;   // 65792 B
    cudaFuncSetAttribute(gemm_mma<1, 1>, cudaFuncAttributeMaxDynamicSharedMemorySize, SMEM_DYN);
    cudaFuncSetAttribute(gemm_mma<2, 2>, cudaFuncAttributeMaxDynamicSharedMemorySize, SMEM_DYN);
    cudaFuncSetAttribute(gemm_mma<0, 0>, cudaFuncAttributeMaxDynamicSharedMemorySize, SMEM_DYN);
    cudaFuncSetAttribute(gemm_mma<0, 3>, cudaFuncAttributeMaxDynamicSharedMemorySize, SMEM_DYN);

    // 0) pack weights -> fp16 fragment-major layout
    prep_w<<<(CC / 2) * C3 / 256, 256>>>(w_qkv_s, wp_qs, CC, C3);
    prep_w<<<(CC / 2) * C3 / 256, 256>>>(w_qkv_b, wp_qb, CC, C3);
    prep_w<<<(C2 / 2) * C2 / 256, 256>>>(w_f1, wp_f1, C2, C2);
    prep_w<<<(C2 / 2) * CC / 256, 256>>>(w_f2, wp_f2, C2, CC);
    prep_w<<<(CC / 2) * CC / 256, 256>>>(w_os, wp_os, CC, CC);
    prep_w<<<(CC / 2) * CC / 256, 256>>>(w_ob, wp_ob, CC, CC);

    // 1) LayerNorm statistics
    ln_stats_kernel<<<NN / 8, 256>>>(sem_feat, mean_s, rstd_s);
    ln_stats_kernel<<<NN / 8, 256>>>(bnd_feat, mean_b, rstd_b);

    // 2) QKV GEMMs (fused LN + scatter by inverse)
    gemm_mma<1, 1><<<dim3(C3 / 128, NN / 128), 256, SMEM_DYN>>>(
        sem_feat, nullptr, CC, wp_qs, C3 / 128, b_qkv_s, qkv_s, C3,
        mean_s, rstd_s, g_sem, b_sem, inverse, nullptr, CC);
    gemm_mma<1, 1><<<dim3(C3 / 128, NN / 128), 256, SMEM_DYN>>>(
        bnd_feat, nullptr, CC, wp_qb, C3 / 128, b_qkv_b, qkv_b, C3,
        mean_b, rstd_b, g_bnd, b_bnd, inverse, nullptr, CC);

    // 3) Fusion MLP layer 1 (concat A + GELU epilogue)
    gemm_mma<2, 2><<<dim3(C2 / 128, NN / 128), 256, SMEM_DYN>>>(
        qkv_s, qkv_b, C3, wp_f1, C2 / 128, b_f1, h1, C2,
        nullptr, nullptr, nullptr, nullptr, nullptr, nullptr, C2);

    // 4) Fusion MLP layer 2
    gemm_mma<0, 0><<<dim3(CC / 128, NN / 128), 256, SMEM_DYN>>>(
        h1, nullptr, C2, wp_f2, CC / 128, b_f2, qf, CC,
        nullptr, nullptr, nullptr, nullptr, nullptr, nullptr, C2);

    // 5) Per-patch attention (scatter by order -> unpermuted)
    patch_attn_kernel<<<PP * HH, 256>>>(qf, qkv_s, order, attn_s);
    patch_attn_kernel<<<PP * HH, 256>>>(qf, qkv_b, order, attn_b);

    // 6) Output projections + residual
    gemm_mma<0, 3><<<dim3(CC / 128, NN / 128), 256, SMEM_DYN>>>(
        attn_s, nullptr, CC, wp_os, CC / 128, b_os, out, CC,
        nullptr, nullptr, nullptr, nullptr, nullptr, sem_feat, CC);
    gemm_mma<0, 3><<<dim3(CC / 128, NN / 128), 256, SMEM_DYN>>>(
        attn_b, nullptr, CC, wp_ob, CC / 128, b_ob, out + (size_t)NN * CC, CC,
        nullptr, nullptr, nullptr, nullptr, nullptr, bnd_feat, CC);
}

// round 7
// speedup vs baseline: 3.4811x; 1.0697x over previous
#include <cuda_runtime.h>
#include <cuda_fp16.h>
#include <math.h>
#include <stdint.h>

// Problem constants
#define NN 49152
#define CC 512
#define HH 8
#define KK 48
#define DD 64
#define PP 1024            // NN / KK
#define C3 1536            // 3*C
#define C2 1024            // 2*C

// ---------------------------------------------------------------------------
// Scratch (device globals; no runtime allocation)
// ---------------------------------------------------------------------------
__device__ float g_qkv_s[(size_t)NN * C3];
__device__ float g_qkv_b[(size_t)NN * C3];
__device__ float g_h1[(size_t)NN * C2];
__device__ float g_qf[(size_t)NN * CC];
__device__ float g_attn_s[(size_t)NN * CC];
__device__ float g_attn_b[(size_t)NN * CC];
__device__ float g_mean_s[NN];
__device__ float g_rstd_s[NN];
__device__ float g_mean_b[NN];
__device__ float g_rstd_b[NN];
// Packed fp16 weights, fragment-major, grouped by 32-k chunk:
// u32 index = ((chunk*(N/128) + nblk)*2 + k16step)*1024 + nfrag*64 + lane*2 + reg
__device__ uint32_t g_wp_qs[(size_t)(CC / 2) * C3];
__device__ uint32_t g_wp_qb[(size_t)(CC / 2) * C3];
__device__ uint32_t g_wp_f1[(size_t)(C2 / 2) * C2];
__device__ uint32_t g_wp_f2[(size_t)(C2 / 2) * CC];
__device__ uint32_t g_wp_os[(size_t)(CC / 2) * CC];
__device__ uint32_t g_wp_ob[(size_t)(CC / 2) * CC];

// ---------------------------------------------------------------------------
// Helpers (base-target PTX, sm_80+ only)
// ---------------------------------------------------------------------------
__device__ __forceinline__ uint32_t pack2h(float a, float b) {
    __half2 h = __floats2half2_rn(a, b);
    return *reinterpret_cast<uint32_t*>(&h);
}

__device__ __forceinline__ void mma_f16(float* d, const uint32_t* a, const uint32_t* b) {
    asm volatile(
        "mma.sync.aligned.m16n8k16.row.col.f32.f16.f16.f32 "
        "{%0,%1,%2,%3}, {%4,%5,%6,%7}, {%8,%9}, {%0,%1,%2,%3};"
        : "+f"(d[0]), "+f"(d[1]), "+f"(d[2]), "+f"(d[3])
        : "r"(a[0]), "r"(a[1]), "r"(a[2]), "r"(a[3]), "r"(b[0]), "r"(b[1]));
}

__device__ __forceinline__ void cp16(uint32_t saddr, const void* gptr) {
    asm volatile("cp.async.cg.shared.global [%0], [%1], 16;" :: "r"(saddr), "l"(gptr));
}
#define CP_COMMIT() asm volatile("cp.async.commit_group;" ::: "memory")
#define CP_WAIT0()  asm volatile("cp.async.wait_group 0;" ::: "memory")

// ---------------------------------------------------------------------------
// Weight pack: w [K,N] fp32 row-major -> fp16 pairs, fragment-major, 32-k chunks
// ---------------------------------------------------------------------------
__global__ void prep_w(const float* __restrict__ w, uint32_t* __restrict__ out,
                       int Kd, int Nd)
{
    int idx = blockIdx.x * 256 + threadIdx.x;      // over (K/2)*N
    if (idx >= (Kd >> 1) * Nd) return;
    int n  = idx % Nd;
    int k  = (idx / Nd) << 1;                      // even k
    float v0 = w[(size_t)k * Nd + n];
    float v1 = w[(size_t)(k + 1) * Nd + n];
    int cc   = k >> 5;                             // 32-k chunk
    int step = (k >> 4) & 1;
    int nblk = n >> 7, nn = n & 127;
    int nfrag = nn >> 3;
    int lane  = (nn & 7) * 4 + ((k & 7) >> 1);
    int reg   = (k & 15) >> 3;
    size_t o = ((size_t)(cc * (Nd >> 7) + nblk) * 2 + step) * 1024
             + nfrag * 64 + lane * 2 + reg;
    out[o] = pack2h(v0, v1);
}

// ---------------------------------------------------------------------------
// LayerNorm row statistics: one warp per row of 512
// ---------------------------------------------------------------------------
__global__ void ln_stats_kernel(const float* __restrict__ x,
                                float* __restrict__ mean, float* __restrict__ rstd)
{
    int warp = (blockIdx.x * blockDim.x + threadIdx.x) >> 5;
    int lane = threadIdx.x & 31;
    if (warp >= NN) return;
    const float* row = x + (size_t)warp * CC;
    float s = 0.f, sq = 0.f;
    #pragma unroll 4
    for (int i = lane; i < CC; i += 32) { float v = row[i]; s += v; sq += v * v; }
    #pragma unroll
    for (int o = 16; o > 0; o >>= 1) {
        s  += __shfl_xor_sync(0xffffffffu, s, o);
        sq += __shfl_xor_sync(0xffffffffu, sq, o);
    }
    if (lane == 0) {
        float m = s * (1.f / CC);
        float var = sq * (1.f / CC) - m * m;
        mean[warp] = m;
        rstd[warp] = rsqrtf(var + 1e-5f);
    }
}

// ---------------------------------------------------------------------------
// FP16 mma.sync GEMM: C[128x128] = op(A)[128xK] @ W + epilogue
// 128 threads (4 warps, 2x2), warp tile 64x64, K-chunk 32, double-buffered.
// Replication per k16-step: A 2x, B 2x -> 16 KB LDS/step, smem/compute balanced.
// AMODE: 0 plain, 1 LayerNorm transform, 2 concat(A|A2)
// EPI:   0 bias, 1 bias+scatter, 2 bias+GELU, 3 bias+residual
// ---------------------------------------------------------------------------
template<int AMODE, int EPI>
__global__ void __launch_bounds__(128, 2)
gemm_mma(const float* __restrict__ A, const float* __restrict__ A2, int lda,
         const uint32_t* __restrict__ Bp, int nbCols,
         const float* __restrict__ bias,
         float* __restrict__ Co, int ldc,
         const float* __restrict__ mean, const float* __restrict__ rstd,
         const float* __restrict__ lng, const float* __restrict__ lnb,
         const int* __restrict__ scat, const float* __restrict__ res, int Kd)
{
    extern __shared__ uint32_t sm[];
    // A: [stage:2064][step:1032][mfrag:128][lane:4][reg]  (pad 8 u32/step)
    // B: [stage:2048][step:1024][nfrag:64][lane:2][reg]
    uint32_t* sA = sm;
    uint32_t* sB = sm + 4128;
    uint32_t sBaddr;
    asm("{ .reg .u64 t; cvta.to.shared.u64 t, %1; cvt.u32.u64 %0, t; }"
        : "=r"(sBaddr) : "l"((const void*)sB));

    const int tid  = threadIdx.x;
    const int lane = tid & 31, wid = tid >> 5;
    const int brow = blockIdx.y * 128, bcol = blockIdx.x * 128;
    const int nblk = blockIdx.x;
    const int mf0 = (wid >> 1) * 4;          // 4 mfrags (64 rows)
    const int nf0 = (wid & 1) * 8;           // 8 nfrags (64 cols)

    // A staging geometry: thread covers rows rbase+16*i (i<8), k-quad kq
    const int rbase = tid >> 3;              // 0..15
    const int kq    = (tid & 7) << 2;        // 0..28
    const int stepT = kq >> 4;               // k16-step (0/1)
    const int laneq = (rbase & 7) * 4 + ((kq & 7) >> 1);
    const int regA  = (rbase >> 3) + ((kq >> 3) & 1) * 2;
    const int aoffT = stepT * 1032 + laneq * 4 + regA;

    float acc[4][8][4];
    #pragma unroll
    for (int a = 0; a < 4; a++)
        #pragma unroll
        for (int b = 0; b < 8; b++)
            #pragma unroll
            for (int r = 0; r < 4; r++) acc[a][b][r] = 0.f;

    float mrow[8], rrow[8];
    if (AMODE == 1) {
        #pragma unroll
        for (int i = 0; i < 8; i++) {
            mrow[i] = mean[brow + rbase + 16 * i];
            rrow[i] = rstd[brow + rbase + 16 * i];
        }
    }

    float4 rA[8];

    auto CPB = [&](int c, int st) {
        const uint32_t* src = Bp + ((size_t)(c * nbCols + nblk) << 11);
        #pragma unroll
        for (int j = 0; j < 4; j++)
            cp16(sBaddr + ((st << 11) + (j << 9) + (tid << 2)) * 4,
                 src + (j << 9) + (tid << 2));
        CP_COMMIT();
    };

    auto LDGA = [&](int c) {
        const int gk = (c << 5) + kq;
        #pragma unroll
        for (int i = 0; i < 8; i++) {
            const int row = brow + rbase + 16 * i;
            if (AMODE == 2) {
                const float* s = (gk < 512) ? A : A2;
                const int k2 = (gk < 512) ? gk : gk - 512;
                rA[i] = *(const float4*)(s + (size_t)row * lda + k2);
            } else {
                rA[i] = *(const float4*)(A + (size_t)row * lda + gk);
            }
        }
    };

    auto STSA = [&](int st, int c) {
        float4 g4, b4;
        if (AMODE == 1) {
            const int gk = (c << 5) + kq;
            g4 = *(const float4*)(lng + gk);
            b4 = *(const float4*)(lnb + gk);
        }
        uint32_t* base = sA + st * 2064 + aoffT;
        #pragma unroll
        for (int i = 0; i < 8; i++) {
            float v0 = rA[i].x, v1 = rA[i].y, v2 = rA[i].z, v3 = rA[i].w;
            if (AMODE == 1) {
                v0 = (v0 - mrow[i]) * rrow[i] * g4.x + b4.x;
                v1 = (v1 - mrow[i]) * rrow[i] * g4.y + b4.y;
                v2 = (v2 - mrow[i]) * rrow[i] * g4.z + b4.z;
                v3 = (v3 - mrow[i]) * rrow[i] * g4.w + b4.w;
            }
            uint32_t* p = base + i * 128;     // mfrag = i
            p[0] = pack2h(v0, v1);
            p[4] = pack2h(v2, v3);
        }
    };

    auto COMPUTE = [&](int st) {
        #pragma unroll
        for (int ks = 0; ks < 2; ks++) {
            uint32_t af[4][4], bf[8][2];
            #pragma unroll
            for (int mi = 0; mi < 4; mi++) {
                uint4 t = *(const uint4*)(sA + st * 2064 + ks * 1032 +
                                          (mf0 + mi) * 128 + lane * 4);
                af[mi][0] = t.x; af[mi][1] = t.y; af[mi][2] = t.z; af[mi][3] = t.w;
            }
            #pragma unroll
            for (int ni = 0; ni < 8; ni++) {
                uint2 t = *(const uint2*)(sB + st * 2048 + ks * 1024 +
                                          (nf0 + ni) * 64 + lane * 2);
                bf[ni][0] = t.x; bf[ni][1] = t.y;
            }
            #pragma unroll
            for (int mi = 0; mi < 4; mi++)
                #pragma unroll
                for (int ni = 0; ni < 8; ni++)
                    mma_f16(acc[mi][ni], af[mi], bf[ni]);
        }
    };

    const int KC = Kd >> 5;
    CPB(0, 0);
    LDGA(0);
    STSA(0, 0);
    CP_WAIT0();
    __syncthreads();
    for (int c = 0; c < KC; c++) {
        const int st = c & 1;
        if (c + 1 < KC) { CPB(c + 1, st ^ 1); LDGA(c + 1); }
        COMPUTE(st);
        if (c + 1 < KC) {
            STSA(st ^ 1, c + 1);
            CP_WAIT0();
            __syncthreads();
        }
    }

    // ---- epilogue: fused bias / gelu / scatter / residual
    const int wm = (wid >> 1) * 64, wn = (wid & 1) * 64;
    #pragma unroll
    for (int mi = 0; mi < 4; mi++) {
        const int ra = brow + wm + mi * 16 + (lane >> 2);
        const int rb = ra + 8;
        const int ora = (EPI == 1) ? scat[ra] : ra;
        const int orb = (EPI == 1) ? scat[rb] : rb;
        #pragma unroll
        for (int ni = 0; ni < 8; ni++) {
            const int col = bcol + wn + ni * 8 + (lane & 3) * 2;
            const float b0 = bias[col], b1 = bias[col + 1];
            float v0 = acc[mi][ni][0] + b0, v1 = acc[mi][ni][1] + b1;
            float v2 = acc[mi][ni][2] + b0, v3 = acc[mi][ni][3] + b1;
            if (EPI == 2) {
                v0 = 0.5f * v0 * (1.f + erff(v0 * 0.7071067811865475f));
                v1 = 0.5f * v1 * (1.f + erff(v1 * 0.7071067811865475f));
                v2 = 0.5f * v2 * (1.f + erff(v2 * 0.7071067811865475f));
                v3 = 0.5f * v3 * (1.f + erff(v3 * 0.7071067811865475f));
            }
            if (EPI == 3) {
                v0 += res[(size_t)ra * ldc + col];
                v1 += res[(size_t)ra * ldc + col + 1];
                v2 += res[(size_t)rb * ldc + col];
                v3 += res[(size_t)rb * ldc + col + 1];
            }
            *(float2*)(Co + (size_t)ora * ldc + col) = make_float2(v0, v1);
            *(float2*)(Co + (size_t)orb * ldc + col) = make_float2(v2, v3);
        }
    }
}

// ---------------------------------------------------------------------------
// Per-(patch, head) attention: 48x48 softmax attention over D=64 (fp32)
// ---------------------------------------------------------------------------
__global__ void __launch_bounds__(256)
patch_attn_kernel(const float* __restrict__ qf,
                  const float* __restrict__ qkv,
                  const int* __restrict__ order,
                  float* __restrict__ out)
{
    const int p = blockIdx.x >> 3;
    const int h = blockIdx.x & 7;

    __shared__ float qs[48 * 65];
    __shared__ float ks[48 * 65];
    __shared__ float vs[48 * 65];
    __shared__ float sc[48 * 48];

    const int tid = threadIdx.x;
    const size_t rowbase = (size_t)p * KK;

    for (int e = tid; e < 48 * 64; e += 256) {
        const int r = e >> 6, d = e & 63;
        qs[r * 65 + d] = qf[(rowbase + r) * CC + h * DD + d];
        ks[r * 65 + d] = qkv[(rowbase + r) * C3 + 512 + h * DD + d];
        vs[r * 65 + d] = qkv[(rowbase + r) * C3 + 1024 + h * DD + d];
    }
    __syncthreads();

    for (int e = tid; e < 48 * 48; e += 256) {
        const int i = e / 48, m = e % 48;
        float a = 0.f;
        #pragma unroll 8
        for (int d = 0; d < 64; d++) a += qs[i * 65 + d] * ks[m * 65 + d];
        sc[e] = a * 0.125f;
    }
    __syncthreads();

    if (tid < 48) {
        float mx = -1e30f;
        for (int m = 0; m < 48; m++) mx = fmaxf(mx, sc[tid * 48 + m]);
        float sum = 0.f;
        for (int m = 0; m < 48; m++) {
            float ev = expf(sc[tid * 48 + m] - mx);
            sc[tid * 48 + m] = ev;
            sum += ev;
        }
        float inv = 1.f / sum;
        for (int m = 0; m < 48; m++) sc[tid * 48 + m] *= inv;
    }
    __syncthreads();

    for (int e = tid; e < 48 * 64; e += 256) {
        const int i = e >> 6, d = e & 63;
        float a = 0.f;
        #pragma unroll 8
        for (int m = 0; m < 48; m++) a += sc[i * 48 + m] * vs[m * 65 + d];
        const int grow = order[rowbase + i];
        out[(size_t)grow * CC + h * DD + d] = a;
    }
}

// ---------------------------------------------------------------------------
// Host launch
// ---------------------------------------------------------------------------
extern "C" void kernel_launch(void* const* d_in, const int* in_sizes, int n_in,
                              void* d_out, int out_size)
{
    const float* sem_feat = (const float*)d_in[0];
    const float* bnd_feat = (const float*)d_in[1];
    const int*   order    = (const int*)d_in[2];
    const int*   inverse  = (const int*)d_in[3];
    const float* g_sem    = (const float*)d_in[4];
    const float* b_sem    = (const float*)d_in[5];
    const float* g_bnd    = (const float*)d_in[6];
    const float* b_bnd    = (const float*)d_in[7];
    const float* w_qkv_s  = (const float*)d_in[8];
    const float* b_qkv_s  = (const float*)d_in[9];
    const float* w_qkv_b  = (const float*)d_in[10];
    const float* b_qkv_b  = (const float*)d_in[11];
    const float* w_f1     = (const float*)d_in[12];
    const float* b_f1     = (const float*)d_in[13];
    const float* w_f2     = (const float*)d_in[14];
    const float* b_f2     = (const float*)d_in[15];
    const float* w_os     = (const float*)d_in[16];
    const float* b_os     = (const float*)d_in[17];
    const float* w_ob     = (const float*)d_in[18];
    const float* b_ob     = (const float*)d_in[19];
    float* out = (float*)d_out;

    float *qkv_s, *qkv_b, *h1, *qf, *attn_s, *attn_b;
    float *mean_s, *rstd_s, *mean_b, *rstd_b;
    uint32_t *wp_qs, *wp_qb, *wp_f1, *wp_f2, *wp_os, *wp_ob;
    cudaGetSymbolAddress((void**)&qkv_s,  g_qkv_s);
    cudaGetSymbolAddress((void**)&qkv_b,  g_qkv_b);
    cudaGetSymbolAddress((void**)&h1,     g_h1);
    cudaGetSymbolAddress((void**)&qf,     g_qf);
    cudaGetSymbolAddress((void**)&attn_s, g_attn_s);
    cudaGetSymbolAddress((void**)&attn_b, g_attn_b);
    cudaGetSymbolAddress((void**)&mean_s, g_mean_s);
    cudaGetSymbolAddress((void**)&rstd_s, g_rstd_s);
    cudaGetSymbolAddress((void**)&mean_b, g_mean_b);
    cudaGetSymbolAddress((void**)&rstd_b, g_rstd_b);
    cudaGetSymbolAddress((void**)&wp_qs,  g_wp_qs);
    cudaGetSymbolAddress((void**)&wp_qb,  g_wp_qb);
    cudaGetSymbolAddress((void**)&wp_f1,  g_wp_f1);
    cudaGetSymbolAddress((void**)&wp_f2,  g_wp_f2);
    cudaGetSymbolAddress((void**)&wp_os,  g_wp_os);
    cudaGetSymbolAddress((void**)&wp_ob,  g_wp_ob);

    const int SMEM_DYN = (4128 + 4096) * 4;   // 32896 B
    cudaFuncSetAttribute(gemm_mma<1, 1>, cudaFuncAttributeMaxDynamicSharedMemorySize, SMEM_DYN);
    cudaFuncSetAttribute(gemm_mma<2, 2>, cudaFuncAttributeMaxDynamicSharedMemorySize, SMEM_DYN);
    cudaFuncSetAttribute(gemm_mma<0, 0>, cudaFuncAttributeMaxDynamicSharedMemorySize, SMEM_DYN);
    cudaFuncSetAttribute(gemm_mma<0, 3>, cudaFuncAttributeMaxDynamicSharedMemorySize, SMEM_DYN);

    // 0) pack weights -> fp16 fragment-major layout (32-k chunks)
    prep_w<<<(CC / 2) * C3 / 256, 256>>>(w_qkv_s, wp_qs, CC, C3);
    prep_w<<<(CC / 2) * C3 / 256, 256>>>(w_qkv_b, wp_qb, CC, C3);
    prep_w<<<(C2 / 2) * C2 / 256, 256>>>(w_f1, wp_f1, C2, C2);
    prep_w<<<(C2 / 2) * CC / 256, 256>>>(w_f2, wp_f2, C2, CC);
    prep_w<<<(CC / 2) * CC / 256, 256>>>(w_os, wp_os, CC, CC);
    prep_w<<<(CC / 2) * CC / 256, 256>>>(w_ob, wp_ob, CC, CC);

    // 1) LayerNorm statistics
    ln_stats_kernel<<<NN / 8, 256>>>(sem_feat, mean_s, rstd_s);
    ln_stats_kernel<<<NN / 8, 256>>>(bnd_feat, mean_b, rstd_b);

    // 2) QKV GEMMs (fused LN + scatter by inverse)
    gemm_mma<1, 1><<<dim3(C3 / 128, NN / 128), 128, SMEM_DYN>>>(
        sem_feat, nullptr, CC, wp_qs, C3 / 128, b_qkv_s, qkv_s, C3,
        mean_s, rstd_s, g_sem, b_sem, inverse, nullptr, CC);
    gemm_mma<1, 1><<<dim3(C3 / 128, NN / 128), 128, SMEM_DYN>>>(
        bnd_feat, nullptr, CC, wp_qb, C3 / 128, b_qkv_b, qkv_b, C3,
        mean_b, rstd_b, g_bnd, b_bnd, inverse, nullptr, CC);

    // 3) Fusion MLP layer 1 (concat A + GELU epilogue)
    gemm_mma<2, 2><<<dim3(C2 / 128, NN / 128), 128, SMEM_DYN>>>(
        qkv_s, qkv_b, C3, wp_f1, C2 / 128, b_f1, h1, C2,
        nullptr, nullptr, nullptr, nullptr, nullptr, nullptr, C2);

    // 4) Fusion MLP layer 2
    gemm_mma<0, 0><<<dim3(CC / 128, NN / 128), 128, SMEM_DYN>>>(
        h1, nullptr, C2, wp_f2, CC / 128, b_f2, qf, CC,
        nullptr, nullptr, nullptr, nullptr, nullptr, nullptr, C2);

    // 5) Per-patch attention (scatter by order -> unpermuted)
    patch_attn_kernel<<<PP * HH, 256>>>(qf, qkv_s, order, attn_s);
    patch_attn_kernel<<<PP * HH, 256>>>(qf, qkv_b, order, attn_b);

    // 6) Output projections + residual
    gemm_mma<0, 3><<<dim3(CC / 128, NN / 128), 128, SMEM_DYN>>>(
        attn_s, nullptr, CC, wp_os, CC / 128, b_os, out, CC,
        nullptr, nullptr, nullptr, nullptr, nullptr, sem_feat, CC);
    gemm_mma<0, 3><<<dim3(CC / 128, NN / 128), 128, SMEM_DYN>>>(
        attn_b, nullptr, CC, wp_ob, CC / 128, b_ob, out + (size_t)NN * CC, CC,
        nullptr, nullptr, nullptr, nullptr, nullptr, bnd_feat, CC);
}

// round 8
// speedup vs baseline: 3.5299x; 1.0140x over previous
#include <cuda_runtime.h>
#include <cuda_fp16.h>
#include <math.h>
#include <stdint.h>

// Problem constants
#define NN 49152
#define CC 512
#define HH 8
#define KK 48
#define DD 64
#define PP 1024            // NN / KK
#define C3 1536            // 3*C
#define C2 1024            // 2*C

// ---------------------------------------------------------------------------
// Scratch (device globals; no runtime allocation). Intermediates are fp16.
// ---------------------------------------------------------------------------
__device__ __half g_qkv_s[(size_t)NN * C3];
__device__ __half g_qkv_b[(size_t)NN * C3];
__device__ __half g_h1[(size_t)NN * C2];
__device__ __half g_qf[(size_t)NN * CC];
__device__ __half g_attn_s[(size_t)NN * CC];
__device__ __half g_attn_b[(size_t)NN * CC];
__device__ float g_mean_s[NN];
__device__ float g_rstd_s[NN];
__device__ float g_mean_b[NN];
__device__ float g_rstd_b[NN];
// Packed fp16 weights, fragment-major, grouped by 32-k chunk:
// u32 index = ((chunk*(N/128) + nblk)*2 + k16step)*1024 + nfrag*64 + lane*2 + reg
__device__ uint32_t g_wp_qs[(size_t)(CC / 2) * C3];
__device__ uint32_t g_wp_qb[(size_t)(CC / 2) * C3];
__device__ uint32_t g_wp_f1[(size_t)(C2 / 2) * C2];
__device__ uint32_t g_wp_f2[(size_t)(C2 / 2) * CC];
__device__ uint32_t g_wp_os[(size_t)(CC / 2) * CC];
__device__ uint32_t g_wp_ob[(size_t)(CC / 2) * CC];

// ---------------------------------------------------------------------------
// Helpers (base-target PTX, sm_80+ only)
// ---------------------------------------------------------------------------
__device__ __forceinline__ uint32_t pack2h(float a, float b) {
    __half2 h = __floats2half2_rn(a, b);
    return *reinterpret_cast<uint32_t*>(&h);
}

__device__ __forceinline__ void mma_f16(float* d, const uint32_t* a, const uint32_t* b) {
    asm volatile(
        "mma.sync.aligned.m16n8k16.row.col.f32.f16.f16.f32 "
        "{%0,%1,%2,%3}, {%4,%5,%6,%7}, {%8,%9}, {%0,%1,%2,%3};"
        : "+f"(d[0]), "+f"(d[1]), "+f"(d[2]), "+f"(d[3])
        : "r"(a[0]), "r"(a[1]), "r"(a[2]), "r"(a[3]), "r"(b[0]), "r"(b[1]));
}

__device__ __forceinline__ void cp16(uint32_t saddr, const void* gptr) {
    asm volatile("cp.async.cg.shared.global [%0], [%1], 16;" :: "r"(saddr), "l"(gptr));
}
#define CP_COMMIT() asm volatile("cp.async.commit_group;" ::: "memory")
#define CP_WAIT0()  asm volatile("cp.async.wait_group 0;" ::: "memory")

// ---------------------------------------------------------------------------
// Weight pack: w [K,N] fp32 row-major -> fp16 pairs, fragment-major, 32-k chunks
// ---------------------------------------------------------------------------
__global__ void prep_w(const float* __restrict__ w, uint32_t* __restrict__ out,
                       int Kd, int Nd)
{
    int idx = blockIdx.x * 256 + threadIdx.x;      // over (K/2)*N
    if (idx >= (Kd >> 1) * Nd) return;
    int n  = idx % Nd;
    int k  = (idx / Nd) << 1;                      // even k
    float v0 = w[(size_t)k * Nd + n];
    float v1 = w[(size_t)(k + 1) * Nd + n];
    int cc   = k >> 5;                             // 32-k chunk
    int step = (k >> 4) & 1;
    int nblk = n >> 7, nn = n & 127;
    int nfrag = nn >> 3;
    int lane  = (nn & 7) * 4 + ((k & 7) >> 1);
    int reg   = (k & 15) >> 3;
    size_t o = ((size_t)(cc * (Nd >> 7) + nblk) * 2 + step) * 1024
             + nfrag * 64 + lane * 2 + reg;
    out[o] = pack2h(v0, v1);
}

// ---------------------------------------------------------------------------
// LayerNorm row statistics: one warp per row of 512
// ---------------------------------------------------------------------------
__global__ void ln_stats_kernel(const float* __restrict__ x,
                                float* __restrict__ mean, float* __restrict__ rstd)
{
    int warp = (blockIdx.x * blockDim.x + threadIdx.x) >> 5;
    int lane = threadIdx.x & 31;
    if (warp >= NN) return;
    const float* row = x + (size_t)warp * CC;
    float s = 0.f, sq = 0.f;
    #pragma unroll 4
    for (int i = lane; i < CC; i += 32) { float v = row[i]; s += v; sq += v * v; }
    #pragma unroll
    for (int o = 16; o > 0; o >>= 1) {
        s  += __shfl_xor_sync(0xffffffffu, s, o);
        sq += __shfl_xor_sync(0xffffffffu, sq, o);
    }
    if (lane == 0) {
        float m = s * (1.f / CC);
        float var = sq * (1.f / CC) - m * m;
        mean[warp] = m;
        rstd[warp] = rsqrtf(var + 1e-5f);
    }
}

// ---------------------------------------------------------------------------
// FP16 mma.sync GEMM: C[128x128] = op(A)[128xK] @ W + epilogue
// 128 threads (4 warps, 2x2), warp tile 64x64, K-chunk 32, double-buffered.
// AMODE: 0 fp16 plain, 1 fp32+LayerNorm, 2 fp16 concat(A|A2)
// EPI:   0 bias->fp16, 1 bias+scatter->fp16, 2 bias+GELU->fp16,
//        3 bias+residual->fp32
// COMPUTE preloads both k16-steps' fragments before issuing all 64 HMMAs.
// ---------------------------------------------------------------------------
template<int AMODE, int EPI>
__global__ void __launch_bounds__(128, 2)
gemm_mma(const void* __restrict__ Av, const void* __restrict__ A2v, int lda,
         const uint32_t* __restrict__ Bp, int nbCols,
         const float* __restrict__ bias,
         void* __restrict__ Cov, int ldc,
         const float* __restrict__ mean, const float* __restrict__ rstd,
         const float* __restrict__ lng, const float* __restrict__ lnb,
         const int* __restrict__ scat, const float* __restrict__ res, int Kd)
{
    extern __shared__ uint32_t sm[];
    // A: [stage:2064][step:1032][mfrag:128][lane:4][reg]  (pad 8 u32/step)
    // B: [stage:2048][step:1024][nfrag:64][lane:2][reg]
    uint32_t* sA = sm;
    uint32_t* sB = sm + 4128;
    uint32_t sBaddr;
    asm("{ .reg .u64 t; cvta.to.shared.u64 t, %1; cvt.u32.u64 %0, t; }"
        : "=r"(sBaddr) : "l"((const void*)sB));

    const float*  Af  = (const float*)Av;
    const __half* Ah  = (const __half*)Av;
    const __half* A2h = (const __half*)A2v;

    const int tid  = threadIdx.x;
    const int lane = tid & 31, wid = tid >> 5;
    const int brow = blockIdx.y * 128, bcol = blockIdx.x * 128;
    const int nblk = blockIdx.x;
    const int mf0 = (wid >> 1) * 4;          // 4 mfrags (64 rows)
    const int nf0 = (wid & 1) * 8;           // 8 nfrags (64 cols)

    // A staging geometry: thread covers rows rbase+16*i (i<8), k-quad kq
    const int rbase = tid >> 3;              // 0..15
    const int kq    = (tid & 7) << 2;        // 0..28
    const int stepT = kq >> 4;               // k16-step (0/1)
    const int laneq = (rbase & 7) * 4 + ((kq & 7) >> 1);
    const int regA  = (rbase >> 3) + ((kq >> 3) & 1) * 2;
    const int aoffT = stepT * 1032 + laneq * 4 + regA;

    float acc[4][8][4];
    #pragma unroll
    for (int a = 0; a < 4; a++)
        #pragma unroll
        for (int b = 0; b < 8; b++)
            #pragma unroll
            for (int r = 0; r < 4; r++) acc[a][b][r] = 0.f;

    float mrow[8], rrow[8];
    if (AMODE == 1) {
        #pragma unroll
        for (int i = 0; i < 8; i++) {
            mrow[i] = mean[brow + rbase + 16 * i];
            rrow[i] = rstd[brow + rbase + 16 * i];
        }
    }

    float4 rA[8];     // fp32 path (AMODE 1)
    uint2  r16[8];    // fp16 path (AMODE 0/2)

    auto CPB = [&](int c, int st) {
        const uint32_t* src = Bp + ((size_t)(c * nbCols + nblk) << 11);
        #pragma unroll
        for (int j = 0; j < 4; j++)
            cp16(sBaddr + ((st << 11) + (j << 9) + (tid << 2)) * 4,
                 src + (j << 9) + (tid << 2));
        CP_COMMIT();
    };

    auto LDGA = [&](int c) {
        const int gk = (c << 5) + kq;
        #pragma unroll
        for (int i = 0; i < 8; i++) {
            const int row = brow + rbase + 16 * i;
            if (AMODE == 1) {
                rA[i] = *(const float4*)(Af + (size_t)row * lda + gk);
            } else if (AMODE == 2) {
                const __half* s = (gk < 512) ? Ah : A2h;
                const int k2 = (gk < 512) ? gk : gk - 512;
                r16[i] = *(const uint2*)(s + (size_t)row * lda + k2);
            } else {
                r16[i] = *(const uint2*)(Ah + (size_t)row * lda + gk);
            }
        }
    };

    auto STSA = [&](int st, int c) {
        uint32_t* base = sA + st * 2064 + aoffT;
        if (AMODE == 1) {
            const int gk = (c << 5) + kq;
            float4 g4 = *(const float4*)(lng + gk);
            float4 b4 = *(const float4*)(lnb + gk);
            #pragma unroll
            for (int i = 0; i < 8; i++) {
                float v0 = (rA[i].x - mrow[i]) * rrow[i] * g4.x + b4.x;
                float v1 = (rA[i].y - mrow[i]) * rrow[i] * g4.y + b4.y;
                float v2 = (rA[i].z - mrow[i]) * rrow[i] * g4.z + b4.z;
                float v3 = (rA[i].w - mrow[i]) * rrow[i] * g4.w + b4.w;
                uint32_t* p = base + i * 128;
                p[0] = pack2h(v0, v1);
                p[4] = pack2h(v2, v3);
            }
        } else {
            #pragma unroll
            for (int i = 0; i < 8; i++) {
                uint32_t* p = base + i * 128;
                p[0] = r16[i].x;
                p[4] = r16[i].y;
            }
        }
    };

    auto COMPUTE = [&](int st) {
        uint32_t af[2][4][4], bf[2][8][2];
        #pragma unroll
        for (int ks = 0; ks < 2; ks++) {
            #pragma unroll
            for (int mi = 0; mi < 4; mi++) {
                uint4 t = *(const uint4*)(sA + st * 2064 + ks * 1032 +
                                          (mf0 + mi) * 128 + lane * 4);
                af[ks][mi][0] = t.x; af[ks][mi][1] = t.y;
                af[ks][mi][2] = t.z; af[ks][mi][3] = t.w;
            }
            #pragma unroll
            for (int ni = 0; ni < 8; ni++) {
                uint2 t = *(const uint2*)(sB + st * 2048 + ks * 1024 +
                                          (nf0 + ni) * 64 + lane * 2);
                bf[ks][ni][0] = t.x; bf[ks][ni][1] = t.y;
            }
        }
        #pragma unroll
        for (int ks = 0; ks < 2; ks++)
            #pragma unroll
            for (int mi = 0; mi < 4; mi++)
                #pragma unroll
                for (int ni = 0; ni < 8; ni++)
                    mma_f16(acc[mi][ni], af[ks][mi], bf[ks][ni]);
    };

    const int KC = Kd >> 5;
    CPB(0, 0);
    LDGA(0);
    STSA(0, 0);
    CP_WAIT0();
    __syncthreads();
    for (int c = 0; c < KC; c++) {
        const int st = c & 1;
        if (c + 1 < KC) { CPB(c + 1, st ^ 1); LDGA(c + 1); }
        COMPUTE(st);
        if (c + 1 < KC) {
            STSA(st ^ 1, c + 1);
            CP_WAIT0();
            __syncthreads();
        }
    }

    // ---- epilogue: fused bias / gelu / scatter / residual
    const int wm = (wid >> 1) * 64, wn = (wid & 1) * 64;
    float*  Cf = (float*)Cov;
    __half* Ch = (__half*)Cov;
    #pragma unroll
    for (int mi = 0; mi < 4; mi++) {
        const int ra = brow + wm + mi * 16 + (lane >> 2);
        const int rb = ra + 8;
        const int ora = (EPI == 1) ? scat[ra] : ra;
        const int orb = (EPI == 1) ? scat[rb] : rb;
        #pragma unroll
        for (int ni = 0; ni < 8; ni++) {
            const int col = bcol + wn + ni * 8 + (lane & 3) * 2;
            const float b0 = bias[col], b1 = bias[col + 1];
            float v0 = acc[mi][ni][0] + b0, v1 = acc[mi][ni][1] + b1;
            float v2 = acc[mi][ni][2] + b0, v3 = acc[mi][ni][3] + b1;
            if (EPI == 2) {
                v0 = 0.5f * v0 * (1.f + erff(v0 * 0.7071067811865475f));
                v1 = 0.5f * v1 * (1.f + erff(v1 * 0.7071067811865475f));
                v2 = 0.5f * v2 * (1.f + erff(v2 * 0.7071067811865475f));
                v3 = 0.5f * v3 * (1.f + erff(v3 * 0.7071067811865475f));
            }
            if (EPI == 3) {
                v0 += res[(size_t)ra * ldc + col];
                v1 += res[(size_t)ra * ldc + col + 1];
                v2 += res[(size_t)rb * ldc + col];
                v3 += res[(size_t)rb * ldc + col + 1];
                *(float2*)(Cf + (size_t)ra * ldc + col) = make_float2(v0, v1);
                *(float2*)(Cf + (size_t)rb * ldc + col) = make_float2(v2, v3);
            } else {
                *(uint32_t*)(Ch + (size_t)ora * ldc + col) = pack2h(v0, v1);
                *(uint32_t*)(Ch + (size_t)orb * ldc + col) = pack2h(v2, v3);
            }
        }
    }
}

// ---------------------------------------------------------------------------
// Per-(patch, head) attention: 48x48 softmax over D=64; fp16 in/out, fp32 math
// ---------------------------------------------------------------------------
__global__ void __launch_bounds__(256)
patch_attn_kernel(const __half* __restrict__ qf,
                  const __half* __restrict__ qkv,
                  const int* __restrict__ order,
                  __half* __restrict__ out)
{
    const int p = blockIdx.x >> 3;
    const int h = blockIdx.x & 7;

    __shared__ float qs[48 * 65];
    __shared__ float ks[48 * 65];
    __shared__ float vs[48 * 65];
    __shared__ float sc[48 * 48];

    const int tid = threadIdx.x;
    const size_t rowbase = (size_t)p * KK;

    for (int e = tid; e < 48 * 32; e += 256) {
        const int r = e >> 5, d2 = (e & 31) << 1;
        float2 q2 = __half22float2(*(const __half2*)(qf + (rowbase + r) * CC + h * DD + d2));
        float2 k2 = __half22float2(*(const __half2*)(qkv + (rowbase + r) * C3 + 512 + h * DD + d2));
        float2 v2 = __half22float2(*(const __half2*)(qkv + (rowbase + r) * C3 + 1024 + h * DD + d2));
        qs[r * 65 + d2] = q2.x; qs[r * 65 + d2 + 1] = q2.y;
        ks[r * 65 + d2] = k2.x; ks[r * 65 + d2 + 1] = k2.y;
        vs[r * 65 + d2] = v2.x; vs[r * 65 + d2 + 1] = v2.y;
    }
    __syncthreads();

    for (int e = tid; e < 48 * 48; e += 256) {
        const int i = e / 48, m = e % 48;
        float a = 0.f;
        #pragma unroll 8
        for (int d = 0; d < 64; d++) a += qs[i * 65 + d] * ks[m * 65 + d];
        sc[e] = a * 0.125f;
    }
    __syncthreads();

    if (tid < 48) {
        float mx = -1e30f;
        for (int m = 0; m < 48; m++) mx = fmaxf(mx, sc[tid * 48 + m]);
        float sum = 0.f;
        for (int m = 0; m < 48; m++) {
            float ev = expf(sc[tid * 48 + m] - mx);
            sc[tid * 48 + m] = ev;
            sum += ev;
        }
        float inv = 1.f / sum;
        for (int m = 0; m < 48; m++) sc[tid * 48 + m] *= inv;
    }
    __syncthreads();

    for (int e = tid; e < 48 * 64; e += 256) {
        const int i = e >> 6, d = e & 63;
        float a = 0.f;
        #pragma unroll 8
        for (int m = 0; m < 48; m++) a += sc[i * 48 + m] * vs[m * 65 + d];
        const int grow = order[rowbase + i];
        out[(size_t)grow * CC + h * DD + d] = __float2half(a);
    }
}

// ---------------------------------------------------------------------------
// Host launch
// ---------------------------------------------------------------------------
extern "C" void kernel_launch(void* const* d_in, const int* in_sizes, int n_in,
                              void* d_out, int out_size)
{
    const float* sem_feat = (const float*)d_in[0];
    const float* bnd_feat = (const float*)d_in[1];
    const int*   order    = (const int*)d_in[2];
    const int*   inverse  = (const int*)d_in[3];
    const float* g_sem    = (const float*)d_in[4];
    const float* b_sem    = (const float*)d_in[5];
    const float* g_bnd    = (const float*)d_in[6];
    const float* b_bnd    = (const float*)d_in[7];
    const float* w_qkv_s  = (const float*)d_in[8];
    const float* b_qkv_s  = (const float*)d_in[9];
    const float* w_qkv_b  = (const float*)d_in[10];
    const float* b_qkv_b  = (const float*)d_in[11];
    const float* w_f1     = (const float*)d_in[12];
    const float* b_f1     = (const float*)d_in[13];
    const float* w_f2     = (const float*)d_in[14];
    const float* b_f2     = (const float*)d_in[15];
    const float* w_os     = (const float*)d_in[16];
    const float* b_os     = (const float*)d_in[17];
    const float* w_ob     = (const float*)d_in[18];
    const float* b_ob     = (const float*)d_in[19];
    float* out = (float*)d_out;

    __half *qkv_s, *qkv_b, *h1, *qf, *attn_s, *attn_b;
    float *mean_s, *rstd_s, *mean_b, *rstd_b;
    uint32_t *wp_qs, *wp_qb, *wp_f1, *wp_f2, *wp_os, *wp_ob;
    cudaGetSymbolAddress((void**)&qkv_s,  g_qkv_s);
    cudaGetSymbolAddress((void**)&qkv_b,  g_qkv_b);
    cudaGetSymbolAddress((void**)&h1,     g_h1);
    cudaGetSymbolAddress((void**)&qf,     g_qf);
    cudaGetSymbolAddress((void**)&attn_s, g_attn_s);
    cudaGetSymbolAddress((void**)&attn_b, g_attn_b);
    cudaGetSymbolAddress((void**)&mean_s, g_mean_s);
    cudaGetSymbolAddress((void**)&rstd_s, g_rstd_s);
    cudaGetSymbolAddress((void**)&mean_b, g_mean_b);
    cudaGetSymbolAddress((void**)&rstd_b, g_rstd_b);
    cudaGetSymbolAddress((void**)&wp_qs,  g_wp_qs);
    cudaGetSymbolAddress((void**)&wp_qb,  g_wp_qb);
    cudaGetSymbolAddress((void**)&wp_f1,  g_wp_f1);
    cudaGetSymbolAddress((void**)&wp_f2,  g_wp_f2);
    cudaGetSymbolAddress((void**)&wp_os,  g_wp_os);
    cudaGetSymbolAddress((void**)&wp_ob,  g_wp_ob);

    const int SMEM_DYN = (4128 + 4096) * 4;   // 32896 B
    cudaFuncSetAttribute(gemm_mma<1, 1>, cudaFuncAttributeMaxDynamicSharedMemorySize, SMEM_DYN);
    cudaFuncSetAttribute(gemm_mma<2, 2>, cudaFuncAttributeMaxDynamicSharedMemorySize, SMEM_DYN);
    cudaFuncSetAttribute(gemm_mma<0, 0>, cudaFuncAttributeMaxDynamicSharedMemorySize, SMEM_DYN);
    cudaFuncSetAttribute(gemm_mma<0, 3>, cudaFuncAttributeMaxDynamicSharedMemorySize, SMEM_DYN);

    // 0) pack weights -> fp16 fragment-major layout (32-k chunks)
    prep_w<<<(CC / 2) * C3 / 256, 256>>>(w_qkv_s, wp_qs, CC, C3);
    prep_w<<<(CC / 2) * C3 / 256, 256>>>(w_qkv_b, wp_qb, CC, C3);
    prep_w<<<(C2 / 2) * C2 / 256, 256>>>(w_f1, wp_f1, C2, C2);
    prep_w<<<(C2 / 2) * CC / 256, 256>>>(w_f2, wp_f2, C2, CC);
    prep_w<<<(CC / 2) * CC / 256, 256>>>(w_os, wp_os, CC, CC);
    prep_w<<<(CC / 2) * CC / 256, 256>>>(w_ob, wp_ob, CC, CC);

    // 1) LayerNorm statistics
    ln_stats_kernel<<<NN / 8, 256>>>(sem_feat, mean_s, rstd_s);
    ln_stats_kernel<<<NN / 8, 256>>>(bnd_feat, mean_b, rstd_b);

    // 2) QKV GEMMs (fused LN + scatter by inverse, fp16 out)
    gemm_mma<1, 1><<<dim3(C3 / 128, NN / 128), 128, SMEM_DYN>>>(
        sem_feat, nullptr, CC, wp_qs, C3 / 128, b_qkv_s, qkv_s, C3,
        mean_s, rstd_s, g_sem, b_sem, inverse, nullptr, CC);
    gemm_mma<1, 1><<<dim3(C3 / 128, NN / 128), 128, SMEM_DYN>>>(
        bnd_feat, nullptr, CC, wp_qb, C3 / 128, b_qkv_b, qkv_b, C3,
        mean_b, rstd_b, g_bnd, b_bnd, inverse, nullptr, CC);

    // 3) Fusion MLP layer 1 (fp16 concat A + GELU epilogue, fp16 out)
    gemm_mma<2, 2><<<dim3(C2 / 128, NN / 128), 128, SMEM_DYN>>>(
        qkv_s, qkv_b, C3, wp_f1, C2 / 128, b_f1, h1, C2,
        nullptr, nullptr, nullptr, nullptr, nullptr, nullptr, C2);

    // 4) Fusion MLP layer 2 (fp16 A, fp16 out)
    gemm_mma<0, 0><<<dim3(CC / 128, NN / 128), 128, SMEM_DYN>>>(
        h1, nullptr, C2, wp_f2, CC / 128, b_f2, qf, CC,
        nullptr, nullptr, nullptr, nullptr, nullptr, nullptr, C2);

    // 5) Per-patch attention (fp16 in/out, scatter by order -> unpermuted)
    patch_attn_kernel<<<PP * HH, 256>>>(qf, qkv_s, order, attn_s);
    patch_attn_kernel<<<PP * HH, 256>>>(qf, qkv_b, order, attn_b);

    // 6) Output projections + residual (fp16 A, fp32 out)
    gemm_mma<0, 3><<<dim3(CC / 128, NN / 128), 128, SMEM_DYN>>>(
        attn_s, nullptr, CC, wp_os, CC / 128, b_os, out, CC,
        nullptr, nullptr, nullptr, nullptr, nullptr, sem_feat, CC);
    gemm_mma<0, 3><<<dim3(CC / 128, NN / 128), 128, SMEM_DYN>>>(
        attn_b, nullptr, CC, wp_ob, CC / 128, b_ob, out + (size_t)NN * CC, CC,
        nullptr, nullptr, nullptr, nullptr, nullptr, bnd_feat, CC);
}

// round 9
// speedup vs baseline: 5.2167x; 1.4779x over previous
#include <cuda_runtime.h>
#include <cuda_fp16.h>
#include <math.h>
#include <stdint.h>

// Problem constants
#define NN 49152
#define CC 512
#define HH 8
#define KK 48
#define DD 64
#define PP 1024            // NN / KK
#define C3 1536            // 3*C
#define C2 1024            // 2*C

// ---------------------------------------------------------------------------
// Scratch (device globals; no runtime allocation). Intermediates are fp16.
// ---------------------------------------------------------------------------
__device__ __half g_qkv_s[(size_t)NN * C3];
__device__ __half g_qkv_b[(size_t)NN * C3];
__device__ __half g_h1[(size_t)NN * C2];
__device__ __half g_qf[(size_t)NN * CC];
__device__ __half g_attn_s[(size_t)NN * CC];
__device__ __half g_attn_b[(size_t)NN * CC];
__device__ float g_mean_s[NN];
__device__ float g_rstd_s[NN];
__device__ float g_mean_b[NN];
__device__ float g_rstd_b[NN];
// Packed fp16 weights, fragment-major, grouped by 32-k chunk:
// u32 index = ((chunk*(N/128) + nblk)*2 + k16step)*1024 + nfrag*64 + lane*2 + reg
__device__ uint32_t g_wp_qs[(size_t)(CC / 2) * C3];
__device__ uint32_t g_wp_qb[(size_t)(CC / 2) * C3];
__device__ uint32_t g_wp_f1[(size_t)(C2 / 2) * C2];
__device__ uint32_t g_wp_f2[(size_t)(C2 / 2) * CC];
__device__ uint32_t g_wp_os[(size_t)(CC / 2) * CC];
__device__ uint32_t g_wp_ob[(size_t)(CC / 2) * CC];

// ---------------------------------------------------------------------------
// Helpers (base-target PTX, sm_80+ only)
// ---------------------------------------------------------------------------
__device__ __forceinline__ uint32_t pack2h(float a, float b) {
    __half2 h = __floats2half2_rn(a, b);
    return *reinterpret_cast<uint32_t*>(&h);
}

__device__ __forceinline__ void mma_f16(float* d, const uint32_t* a, const uint32_t* b) {
    asm volatile(
        "mma.sync.aligned.m16n8k16.row.col.f32.f16.f16.f32 "
        "{%0,%1,%2,%3}, {%4,%5,%6,%7}, {%8,%9}, {%0,%1,%2,%3};"
        : "+f"(d[0]), "+f"(d[1]), "+f"(d[2]), "+f"(d[3])
        : "r"(a[0]), "r"(a[1]), "r"(a[2]), "r"(a[3]), "r"(b[0]), "r"(b[1]));
}

__device__ __forceinline__ void cp16(uint32_t saddr, const void* gptr) {
    asm volatile("cp.async.cg.shared.global [%0], [%1], 16;" :: "r"(saddr), "l"(gptr));
}
#define CP_COMMIT() asm volatile("cp.async.commit_group;" ::: "memory")
#define CP_WAIT0()  asm volatile("cp.async.wait_group 0;" ::: "memory")

// ---------------------------------------------------------------------------
// Weight pack: w [K,N] fp32 row-major -> fp16 pairs, fragment-major, 32-k chunks
// ---------------------------------------------------------------------------
__global__ void prep_w(const float* __restrict__ w, uint32_t* __restrict__ out,
                       int Kd, int Nd)
{
    int idx = blockIdx.x * 256 + threadIdx.x;      // over (K/2)*N
    if (idx >= (Kd >> 1) * Nd) return;
    int n  = idx % Nd;
    int k  = (idx / Nd) << 1;                      // even k
    float v0 = w[(size_t)k * Nd + n];
    float v1 = w[(size_t)(k + 1) * Nd + n];
    int cc   = k >> 5;                             // 32-k chunk
    int step = (k >> 4) & 1;
    int nblk = n >> 7, nn = n & 127;
    int nfrag = nn >> 3;
    int lane  = (nn & 7) * 4 + ((k & 7) >> 1);
    int reg   = (k & 15) >> 3;
    size_t o = ((size_t)(cc * (Nd >> 7) + nblk) * 2 + step) * 1024
             + nfrag * 64 + lane * 2 + reg;
    out[o] = pack2h(v0, v1);
}

// ---------------------------------------------------------------------------
// LayerNorm row statistics: one warp per row of 512
// ---------------------------------------------------------------------------
__global__ void ln_stats_kernel(const float* __restrict__ x,
                                float* __restrict__ mean, float* __restrict__ rstd)
{
    int warp = (blockIdx.x * blockDim.x + threadIdx.x) >> 5;
    int lane = threadIdx.x & 31;
    if (warp >= NN) return;
    const float* row = x + (size_t)warp * CC;
    float s = 0.f, sq = 0.f;
    #pragma unroll 4
    for (int i = lane; i < CC; i += 32) { float v = row[i]; s += v; sq += v * v; }
    #pragma unroll
    for (int o = 16; o > 0; o >>= 1) {
        s  += __shfl_xor_sync(0xffffffffu, s, o);
        sq += __shfl_xor_sync(0xffffffffu, sq, o);
    }
    if (lane == 0) {
        float m = s * (1.f / CC);
        float var = sq * (1.f / CC) - m * m;
        mean[warp] = m;
        rstd[warp] = rsqrtf(var + 1e-5f);
    }
}

// ---------------------------------------------------------------------------
// FP16 mma.sync GEMM (unchanged from R7): C[128x128] = op(A)[128xK] @ W + epi
// ---------------------------------------------------------------------------
template<int AMODE, int EPI>
__global__ void __launch_bounds__(128, 2)
gemm_mma(const void* __restrict__ Av, const void* __restrict__ A2v, int lda,
         const uint32_t* __restrict__ Bp, int nbCols,
         const float* __restrict__ bias,
         void* __restrict__ Cov, int ldc,
         const float* __restrict__ mean, const float* __restrict__ rstd,
         const float* __restrict__ lng, const float* __restrict__ lnb,
         const int* __restrict__ scat, const float* __restrict__ res, int Kd)
{
    extern __shared__ uint32_t sm[];
    uint32_t* sA = sm;
    uint32_t* sB = sm + 4128;
    uint32_t sBaddr;
    asm("{ .reg .u64 t; cvta.to.shared.u64 t, %1; cvt.u32.u64 %0, t; }"
        : "=r"(sBaddr) : "l"((const void*)sB));

    const float*  Af  = (const float*)Av;
    const __half* Ah  = (const __half*)Av;
    const __half* A2h = (const __half*)A2v;

    const int tid  = threadIdx.x;
    const int lane = tid & 31, wid = tid >> 5;
    const int brow = blockIdx.y * 128, bcol = blockIdx.x * 128;
    const int nblk = blockIdx.x;
    const int mf0 = (wid >> 1) * 4;
    const int nf0 = (wid & 1) * 8;

    const int rbase = tid >> 3;
    const int kq    = (tid & 7) << 2;
    const int stepT = kq >> 4;
    const int laneq = (rbase & 7) * 4 + ((kq & 7) >> 1);
    const int regA  = (rbase >> 3) + ((kq >> 3) & 1) * 2;
    const int aoffT = stepT * 1032 + laneq * 4 + regA;

    float acc[4][8][4];
    #pragma unroll
    for (int a = 0; a < 4; a++)
        #pragma unroll
        for (int b = 0; b < 8; b++)
            #pragma unroll
            for (int r = 0; r < 4; r++) acc[a][b][r] = 0.f;

    float mrow[8], rrow[8];
    if (AMODE == 1) {
        #pragma unroll
        for (int i = 0; i < 8; i++) {
            mrow[i] = mean[brow + rbase + 16 * i];
            rrow[i] = rstd[brow + rbase + 16 * i];
        }
    }

    float4 rA[8];
    uint2  r16[8];

    auto CPB = [&](int c, int st) {
        const uint32_t* src = Bp + ((size_t)(c * nbCols + nblk) << 11);
        #pragma unroll
        for (int j = 0; j < 4; j++)
            cp16(sBaddr + ((st << 11) + (j << 9) + (tid << 2)) * 4,
                 src + (j << 9) + (tid << 2));
        CP_COMMIT();
    };

    auto LDGA = [&](int c) {
        const int gk = (c << 5) + kq;
        #pragma unroll
        for (int i = 0; i < 8; i++) {
            const int row = brow + rbase + 16 * i;
            if (AMODE == 1) {
                rA[i] = *(const float4*)(Af + (size_t)row * lda + gk);
            } else if (AMODE == 2) {
                const __half* s = (gk < 512) ? Ah : A2h;
                const int k2 = (gk < 512) ? gk : gk - 512;
                r16[i] = *(const uint2*)(s + (size_t)row * lda + k2);
            } else {
                r16[i] = *(const uint2*)(Ah + (size_t)row * lda + gk);
            }
        }
    };

    auto STSA = [&](int st, int c) {
        uint32_t* base = sA + st * 2064 + aoffT;
        if (AMODE == 1) {
            const int gk = (c << 5) + kq;
            float4 g4 = *(const float4*)(lng + gk);
            float4 b4 = *(const float4*)(lnb + gk);
            #pragma unroll
            for (int i = 0; i < 8; i++) {
                float v0 = (rA[i].x - mrow[i]) * rrow[i] * g4.x + b4.x;
                float v1 = (rA[i].y - mrow[i]) * rrow[i] * g4.y + b4.y;
                float v2 = (rA[i].z - mrow[i]) * rrow[i] * g4.z + b4.z;
                float v3 = (rA[i].w - mrow[i]) * rrow[i] * g4.w + b4.w;
                uint32_t* p = base + i * 128;
                p[0] = pack2h(v0, v1);
                p[4] = pack2h(v2, v3);
            }
        } else {
            #pragma unroll
            for (int i = 0; i < 8; i++) {
                uint32_t* p = base + i * 128;
                p[0] = r16[i].x;
                p[4] = r16[i].y;
            }
        }
    };

    auto COMPUTE = [&](int st) {
        uint32_t af[2][4][4], bf[2][8][2];
        #pragma unroll
        for (int ks = 0; ks < 2; ks++) {
            #pragma unroll
            for (int mi = 0; mi < 4; mi++) {
                uint4 t = *(const uint4*)(sA + st * 2064 + ks * 1032 +
                                          (mf0 + mi) * 128 + lane * 4);
                af[ks][mi][0] = t.x; af[ks][mi][1] = t.y;
                af[ks][mi][2] = t.z; af[ks][mi][3] = t.w;
            }
            #pragma unroll
            for (int ni = 0; ni < 8; ni++) {
                uint2 t = *(const uint2*)(sB + st * 2048 + ks * 1024 +
                                          (nf0 + ni) * 64 + lane * 2);
                bf[ks][ni][0] = t.x; bf[ks][ni][1] = t.y;
            }
        }
        #pragma unroll
        for (int ks = 0; ks < 2; ks++)
            #pragma unroll
            for (int mi = 0; mi < 4; mi++)
                #pragma unroll
                for (int ni = 0; ni < 8; ni++)
                    mma_f16(acc[mi][ni], af[ks][mi], bf[ks][ni]);
    };

    const int KC = Kd >> 5;
    CPB(0, 0);
    LDGA(0);
    STSA(0, 0);
    CP_WAIT0();
    __syncthreads();
    for (int c = 0; c < KC; c++) {
        const int st = c & 1;
        if (c + 1 < KC) { CPB(c + 1, st ^ 1); LDGA(c + 1); }
        COMPUTE(st);
        if (c + 1 < KC) {
            STSA(st ^ 1, c + 1);
            CP_WAIT0();
            __syncthreads();
        }
    }

    const int wm = (wid >> 1) * 64, wn = (wid & 1) * 64;
    float*  Cf = (float*)Cov;
    __half* Ch = (__half*)Cov;
    #pragma unroll
    for (int mi = 0; mi < 4; mi++) {
        const int ra = brow + wm + mi * 16 + (lane >> 2);
        const int rb = ra + 8;
        const int ora = (EPI == 1) ? scat[ra] : ra;
        const int orb = (EPI == 1) ? scat[rb] : rb;
        #pragma unroll
        for (int ni = 0; ni < 8; ni++) {
            const int col = bcol + wn + ni * 8 + (lane & 3) * 2;
            const float b0 = bias[col], b1 = bias[col + 1];
            float v0 = acc[mi][ni][0] + b0, v1 = acc[mi][ni][1] + b1;
            float v2 = acc[mi][ni][2] + b0, v3 = acc[mi][ni][3] + b1;
            if (EPI == 2) {
                v0 = 0.5f * v0 * (1.f + erff(v0 * 0.7071067811865475f));
                v1 = 0.5f * v1 * (1.f + erff(v1 * 0.7071067811865475f));
                v2 = 0.5f * v2 * (1.f + erff(v2 * 0.7071067811865475f));
                v3 = 0.5f * v3 * (1.f + erff(v3 * 0.7071067811865475f));
            }
            if (EPI == 3) {
                v0 += res[(size_t)ra * ldc + col];
                v1 += res[(size_t)ra * ldc + col + 1];
                v2 += res[(size_t)rb * ldc + col];
                v3 += res[(size_t)rb * ldc + col + 1];
                *(float2*)(Cf + (size_t)ra * ldc + col) = make_float2(v0, v1);
                *(float2*)(Cf + (size_t)rb * ldc + col) = make_float2(v2, v3);
            } else {
                *(uint32_t*)(Ch + (size_t)ora * ldc + col) = pack2h(v0, v1);
                *(uint32_t*)(Ch + (size_t)orb * ldc + col) = pack2h(v2, v3);
            }
        }
    }
}

// ---------------------------------------------------------------------------
// Fused per-(patch, head, stream) attention, register-blocked.
// grid = (PP*HH, 2); block = 256. Phase1: 3x3 score tiles w/ float4 d-chunks.
// Phase2: warp-per-row softmax. Phase3: 3x4 AV tiles. fp16 in/out, fp32 math.
// ---------------------------------------------------------------------------
#define QS 68   // padded row stride (floats), 16B-aligned rows
__global__ void __launch_bounds__(256)
patch_attn_kernel(const __half* __restrict__ qf,
                  const __half* __restrict__ qkv_s,
                  const __half* __restrict__ qkv_b,
                  const int* __restrict__ order,
                  __half* __restrict__ attn_s,
                  __half* __restrict__ attn_b)
{
    const int p = blockIdx.x >> 3;
    const int h = blockIdx.x & 7;
    const __half* qkv = blockIdx.y ? qkv_b : qkv_s;
    __half* out = blockIdx.y ? attn_b : attn_s;

    __shared__ float qs[48 * QS];
    __shared__ float ks[48 * QS];
    __shared__ float vs[48 * QS];
    __shared__ float sc[48 * 48];

    const int tid = threadIdx.x;
    const int lane = tid & 31, wid = tid >> 5;
    const size_t rowbase = (size_t)p * KK;

    // ---- load q/k/v (fp16 -> fp32 smem)
    for (int e = tid; e < 48 * 32; e += 256) {
        const int r = e >> 5, d2 = (e & 31) << 1;
        float2 q2 = __half22float2(*(const __half2*)(qf + (rowbase + r) * CC + h * DD + d2));
        float2 k2 = __half22float2(*(const __half2*)(qkv + (rowbase + r) * C3 + 512 + h * DD + d2));
        float2 v2 = __half22float2(*(const __half2*)(qkv + (rowbase + r) * C3 + 1024 + h * DD + d2));
        qs[r * QS + d2] = q2.x; qs[r * QS + d2 + 1] = q2.y;
        ks[r * QS + d2] = k2.x; ks[r * QS + d2 + 1] = k2.y;
        vs[r * QS + d2] = v2.x; vs[r * QS + d2 + 1] = v2.y;
    }
    __syncthreads();

    const int tx = tid & 15, ty = tid >> 4;
    const int i0 = ty * 3;

    // ---- phase 1: scores, 3x3 tile per thread, float4 over d
    {
        const int m0 = tx * 3;
        float a[3][3];
        #pragma unroll
        for (int j = 0; j < 3; j++)
            #pragma unroll
            for (int l = 0; l < 3; l++) a[j][l] = 0.f;
        #pragma unroll 4
        for (int dk = 0; dk < 16; dk++) {
            float4 q[3], k[3];
            #pragma unroll
            for (int j = 0; j < 3; j++) q[j] = *(const float4*)&qs[(i0 + j) * QS + dk * 4];
            #pragma unroll
            for (int l = 0; l < 3; l++) k[l] = *(const float4*)&ks[(m0 + l) * QS + dk * 4];
            #pragma unroll
            for (int j = 0; j < 3; j++)
                #pragma unroll
                for (int l = 0; l < 3; l++)
                    a[j][l] += q[j].x * k[l].x + q[j].y * k[l].y
                             + q[j].z * k[l].z + q[j].w * k[l].w;
        }
        #pragma unroll
        for (int j = 0; j < 3; j++)
            #pragma unroll
            for (int l = 0; l < 3; l++)
                sc[(i0 + j) * 48 + m0 + l] = a[j][l] * 0.125f;
    }
    __syncthreads();

    // ---- phase 2: softmax, warp per row (rows wid, wid+8, ...)
    for (int r = wid; r < 48; r += 8) {
        float x0 = sc[r * 48 + lane];
        float x1 = (lane < 16) ? sc[r * 48 + 32 + lane] : -1e30f;
        float mx = fmaxf(x0, x1);
        #pragma unroll
        for (int o = 16; o > 0; o >>= 1) mx = fmaxf(mx, __shfl_xor_sync(0xffffffffu, mx, o));
        float e0 = expf(x0 - mx);
        float e1 = (lane < 16) ? expf(x1 - mx) : 0.f;
        float s = e0 + e1;
        #pragma unroll
        for (int o = 16; o > 0; o >>= 1) s += __shfl_xor_sync(0xffffffffu, s, o);
        float inv = 1.f / s;
        sc[r * 48 + lane] = e0 * inv;
        if (lane < 16) sc[r * 48 + 32 + lane] = e1 * inv;
    }
    __syncthreads();

    // ---- phase 3: O = A @ V, 3 rows x 4 cols per thread
    {
        const int d0 = tx * 4;
        float o[3][4];
        #pragma unroll
        for (int j = 0; j < 3; j++)
            #pragma unroll
            for (int l = 0; l < 4; l++) o[j][l] = 0.f;
        #pragma unroll 4
        for (int m = 0; m < 48; m++) {
            float4 v4 = *(const float4*)&vs[m * QS + d0];
            float s0 = sc[(i0 + 0) * 48 + m];
            float s1 = sc[(i0 + 1) * 48 + m];
            float s2 = sc[(i0 + 2) * 48 + m];
            o[0][0] += s0 * v4.x; o[0][1] += s0 * v4.y; o[0][2] += s0 * v4.z; o[0][3] += s0 * v4.w;
            o[1][0] += s1 * v4.x; o[1][1] += s1 * v4.y; o[1][2] += s1 * v4.z; o[1][3] += s1 * v4.w;
            o[2][0] += s2 * v4.x; o[2][1] += s2 * v4.y; o[2][2] += s2 * v4.z; o[2][3] += s2 * v4.w;
        }
        #pragma unroll
        for (int j = 0; j < 3; j++) {
            const int grow = order[rowbase + i0 + j];
            uint2 w;
            w.x = pack2h(o[j][0], o[j][1]);
            w.y = pack2h(o[j][2], o[j][3]);
            *(uint2*)(out + (size_t)grow * CC + h * DD + d0) = w;
        }
    }
}

// ---------------------------------------------------------------------------
// Host launch (ordered so the first QKV GEMM is launch index 5 for ncu -s 5)
// ---------------------------------------------------------------------------
extern "C" void kernel_launch(void* const* d_in, const int* in_sizes, int n_in,
                              void* d_out, int out_size)
{
    const float* sem_feat = (const float*)d_in[0];
    const float* bnd_feat = (const float*)d_in[1];
    const int*   order    = (const int*)d_in[2];
    const int*   inverse  = (const int*)d_in[3];
    const float* g_sem    = (const float*)d_in[4];
    const float* b_sem    = (const float*)d_in[5];
    const float* g_bnd    = (const float*)d_in[6];
    const float* b_bnd    = (const float*)d_in[7];
    const float* w_qkv_s  = (const float*)d_in[8];
    const float* b_qkv_s  = (const float*)d_in[9];
    const float* w_qkv_b  = (const float*)d_in[10];
    const float* b_qkv_b  = (const float*)d_in[11];
    const float* w_f1     = (const float*)d_in[12];
    const float* b_f1     = (const float*)d_in[13];
    const float* w_f2     = (const float*)d_in[14];
    const float* b_f2     = (const float*)d_in[15];
    const float* w_os     = (const float*)d_in[16];
    const float* b_os     = (const float*)d_in[17];
    const float* w_ob     = (const float*)d_in[18];
    const float* b_ob     = (const float*)d_in[19];
    float* out = (float*)d_out;

    __half *qkv_s, *qkv_b, *h1, *qf, *attn_s, *attn_b;
    float *mean_s, *rstd_s, *mean_b, *rstd_b;
    uint32_t *wp_qs, *wp_qb, *wp_f1, *wp_f2, *wp_os, *wp_ob;
    cudaGetSymbolAddress((void**)&qkv_s,  g_qkv_s);
    cudaGetSymbolAddress((void**)&qkv_b,  g_qkv_b);
    cudaGetSymbolAddress((void**)&h1,     g_h1);
    cudaGetSymbolAddress((void**)&qf,     g_qf);
    cudaGetSymbolAddress((void**)&attn_s, g_attn_s);
    cudaGetSymbolAddress((void**)&attn_b, g_attn_b);
    cudaGetSymbolAddress((void**)&mean_s, g_mean_s);
    cudaGetSymbolAddress((void**)&rstd_s, g_rstd_s);
    cudaGetSymbolAddress((void**)&mean_b, g_mean_b);
    cudaGetSymbolAddress((void**)&rstd_b, g_rstd_b);
    cudaGetSymbolAddress((void**)&wp_qs,  g_wp_qs);
    cudaGetSymbolAddress((void**)&wp_qb,  g_wp_qb);
    cudaGetSymbolAddress((void**)&wp_f1,  g_wp_f1);
    cudaGetSymbolAddress((void**)&wp_f2,  g_wp_f2);
    cudaGetSymbolAddress((void**)&wp_os,  g_wp_os);
    cudaGetSymbolAddress((void**)&wp_ob,  g_wp_ob);

    const int SMEM_DYN = (4128 + 4096) * 4;   // 32896 B
    cudaFuncSetAttribute(gemm_mma<1, 1>, cudaFuncAttributeMaxDynamicSharedMemorySize, SMEM_DYN);
    cudaFuncSetAttribute(gemm_mma<2, 2>, cudaFuncAttributeMaxDynamicSharedMemorySize, SMEM_DYN);
    cudaFuncSetAttribute(gemm_mma<0, 0>, cudaFuncAttributeMaxDynamicSharedMemorySize, SMEM_DYN);
    cudaFuncSetAttribute(gemm_mma<0, 3>, cudaFuncAttributeMaxDynamicSharedMemorySize, SMEM_DYN);

    // launches 0-4: preps + LN stats
    prep_w<<<(CC / 2) * C3 / 256, 256>>>(w_qkv_s, wp_qs, CC, C3);            // 0
    prep_w<<<(CC / 2) * C3 / 256, 256>>>(w_qkv_b, wp_qb, CC, C3);            // 1
    ln_stats_kernel<<<NN / 8, 256>>>(sem_feat, mean_s, rstd_s);              // 2
    ln_stats_kernel<<<NN / 8, 256>>>(bnd_feat, mean_b, rstd_b);              // 3
    prep_w<<<(C2 / 2) * C2 / 256, 256>>>(w_f1, wp_f1, C2, C2);               // 4

    // launch 5: first QKV GEMM (profiled by ncu -s 5 -c 1)
    gemm_mma<1, 1><<<dim3(C3 / 128, NN / 128), 128, SMEM_DYN>>>(             // 5
        sem_feat, nullptr, CC, wp_qs, C3 / 128, b_qkv_s, qkv_s, C3,
        mean_s, rstd_s, g_sem, b_sem, inverse, nullptr, CC);
    gemm_mma<1, 1><<<dim3(C3 / 128, NN / 128), 128, SMEM_DYN>>>(             // 6
        bnd_feat, nullptr, CC, wp_qb, C3 / 128, b_qkv_b, qkv_b, C3,
        mean_b, rstd_b, g_bnd, b_bnd, inverse, nullptr, CC);

    prep_w<<<(C2 / 2) * CC / 256, 256>>>(w_f2, wp_f2, C2, CC);               // 7
    gemm_mma<2, 2><<<dim3(C2 / 128, NN / 128), 128, SMEM_DYN>>>(             // 8
        qkv_s, qkv_b, C3, wp_f1, C2 / 128, b_f1, h1, C2,
        nullptr, nullptr, nullptr, nullptr, nullptr, nullptr, C2);
    prep_w<<<(CC / 2) * CC / 256, 256>>>(w_os, wp_os, CC, CC);               // 9
    gemm_mma<0, 0><<<dim3(CC / 128, NN / 128), 128, SMEM_DYN>>>(             // 10
        h1, nullptr, C2, wp_f2, CC / 128, b_f2, qf, CC,
        nullptr, nullptr, nullptr, nullptr, nullptr, nullptr, C2);
    prep_w<<<(CC / 2) * CC / 256, 256>>>(w_ob, wp_ob, CC, CC);               // 11

    // fused attention, both streams
    patch_attn_kernel<<<dim3(PP * HH, 2), 256>>>(qf, qkv_s, qkv_b, order,    // 12
                                                 attn_s, attn_b);

    gemm_mma<0, 3><<<dim3(CC / 128, NN / 128), 128, SMEM_DYN>>>(             // 13
        attn_s, nullptr, CC, wp_os, CC / 128, b_os, out, CC,
        nullptr, nullptr, nullptr, nullptr, nullptr, sem_feat, CC);
    gemm_mma<0, 3><<<dim3(CC / 128, NN / 128), 128, SMEM_DYN>>>(             // 14
        attn_b, nullptr, CC, wp_ob, CC / 128, b_ob, out + (size_t)NN * CC, CC,
        nullptr, nullptr, nullptr, nullptr, nullptr, bnd_feat, CC);
}

// round 10
// speedup vs baseline: 6.7423x; 1.2924x over previous
#include <cuda_runtime.h>
#include <cuda_fp16.h>
#include <math.h>
#include <stdint.h>

// Problem constants
#define NN 49152
#define CC 512
#define HH 8
#define KK 48
#define DD 64
#define PP 1024            // NN / KK
#define C3 1536            // 3*C
#define C2 1024            // 2*C

// ---------------------------------------------------------------------------
// Scratch (device globals; no runtime allocation). Intermediates are fp16.
// ---------------------------------------------------------------------------
__device__ __half g_xln_s[(size_t)NN * CC];   // LN-transformed inputs, fp16
__device__ __half g_xln_b[(size_t)NN * CC];
__device__ __half g_qkv_s[(size_t)NN * C3];
__device__ __half g_qkv_b[(size_t)NN * C3];
__device__ __half g_h1[(size_t)NN * C2];
__device__ __half g_qf[(size_t)NN * CC];
__device__ __half g_attn_s[(size_t)NN * CC];
__device__ __half g_attn_b[(size_t)NN * CC];
// Packed fp16 weights, fragment-major, grouped by 64-k chunk:
// u32 index = ((chunk*(N/128) + nblk)*4 + k16step)*1024 + nfrag*64 + lane*2 + reg
__device__ uint32_t g_wp_qs[(size_t)(CC / 2) * C3];
__device__ uint32_t g_wp_qb[(size_t)(CC / 2) * C3];
__device__ uint32_t g_wp_f1[(size_t)(C2 / 2) * C2];
__device__ uint32_t g_wp_f2[(size_t)(C2 / 2) * CC];
__device__ uint32_t g_wp_os[(size_t)(CC / 2) * CC];
__device__ uint32_t g_wp_ob[(size_t)(CC / 2) * CC];

// ---------------------------------------------------------------------------
// Helpers (base-target PTX, sm_80+ only)
// ---------------------------------------------------------------------------
__device__ __forceinline__ uint32_t pack2h(float a, float b) {
    __half2 h = __floats2half2_rn(a, b);
    return *reinterpret_cast<uint32_t*>(&h);
}

__device__ __forceinline__ void mma_f16(float* d, const uint32_t* a, const uint32_t* b) {
    asm volatile(
        "mma.sync.aligned.m16n8k16.row.col.f32.f16.f16.f32 "
        "{%0,%1,%2,%3}, {%4,%5,%6,%7}, {%8,%9}, {%0,%1,%2,%3};"
        : "+f"(d[0]), "+f"(d[1]), "+f"(d[2]), "+f"(d[3])
        : "r"(a[0]), "r"(a[1]), "r"(a[2]), "r"(a[3]), "r"(b[0]), "r"(b[1]));
}

__device__ __forceinline__ void cp16(uint32_t saddr, const void* gptr) {
    asm volatile("cp.async.cg.shared.global [%0], [%1], 16;" :: "r"(saddr), "l"(gptr));
}
#define CP_COMMIT() asm volatile("cp.async.commit_group;" ::: "memory")
#define CP_WAIT0()  asm volatile("cp.async.wait_group 0;" ::: "memory")
#define CP_WAIT1()  asm volatile("cp.async.wait_group 1;" ::: "memory")

// ---------------------------------------------------------------------------
// Weight pack: w [K,N] fp32 row-major -> fp16 pairs, fragment-major, 64-k chunks
// ---------------------------------------------------------------------------
__global__ void prep_w(const float* __restrict__ w, uint32_t* __restrict__ out,
                       int Kd, int Nd)
{
    int idx = blockIdx.x * 256 + threadIdx.x;      // over (K/2)*N
    if (idx >= (Kd >> 1) * Nd) return;
    int n  = idx % Nd;
    int k  = (idx / Nd) << 1;                      // even k
    float v0 = w[(size_t)k * Nd + n];
    float v1 = w[(size_t)(k + 1) * Nd + n];
    int cc   = k >> 6;                             // 64-k chunk
    int step = (k >> 4) & 3;
    int nblk = n >> 7, nn = n & 127;
    int nfrag = nn >> 3;
    int lane  = (nn & 7) * 4 + ((k & 7) >> 1);
    int reg   = (k & 15) >> 3;
    size_t o = ((size_t)(cc * (Nd >> 7) + nblk) * 4 + step) * 1024
             + nfrag * 64 + lane * 2 + reg;
    out[o] = pack2h(v0, v1);
}

// ---------------------------------------------------------------------------
// Fused LayerNorm: stats + transform, fp32 in -> fp16 out. One warp per row.
// ---------------------------------------------------------------------------
__global__ void __launch_bounds__(256)
ln_fp16(const float* __restrict__ x, const float* __restrict__ g,
        const float* __restrict__ b, __half* __restrict__ o)
{
    const int row  = blockIdx.x * 8 + (threadIdx.x >> 5);
    const int lane = threadIdx.x & 31;
    const float* xr = x + (size_t)row * CC;
    float4 v[4];
    float s = 0.f, sq = 0.f;
    #pragma unroll
    for (int j = 0; j < 4; j++) {
        v[j] = *(const float4*)(xr + lane * 4 + 128 * j);
        s  += v[j].x + v[j].y + v[j].z + v[j].w;
        sq += v[j].x * v[j].x + v[j].y * v[j].y + v[j].z * v[j].z + v[j].w * v[j].w;
    }
    #pragma unroll
    for (int off = 16; off > 0; off >>= 1) {
        s  += __shfl_xor_sync(0xffffffffu, s, off);
        sq += __shfl_xor_sync(0xffffffffu, sq, off);
    }
    const float m = s * (1.f / CC);
    const float r = rsqrtf(sq * (1.f / CC) - m * m + 1e-5f);
    __half* orow = o + (size_t)row * CC;
    #pragma unroll
    for (int j = 0; j < 4; j++) {
        const int col = lane * 4 + 128 * j;
        float4 g4 = *(const float4*)(g + col);
        float4 b4 = *(const float4*)(b + col);
        uint2 w;
        w.x = pack2h((v[j].x - m) * r * g4.x + b4.x, (v[j].y - m) * r * g4.y + b4.y);
        w.y = pack2h((v[j].z - m) * r * g4.z + b4.z, (v[j].w - m) * r * g4.w + b4.w);
        *(uint2*)(orow + col) = w;
    }
}

// ---------------------------------------------------------------------------
// Fully-async FP16 mma.sync GEMM: C[128x128] = op(A)[128xK] @ W + epilogue
// 128 threads (4 warps, 2x2), warp tile 64x64, K-chunk 64, 2-stage cp.async.
// A fp16 row-major -> cp.async into SW128-swizzled smem -> ldmatrix fragments.
// B prepacked fragment-major -> cp.async -> direct LDS.64.
// AMODE: 0 plain fp16, 2 concat(A|A2)
// EPI:   0 bias->fp16, 1 bias+scatter->fp16, 2 bias+GELU->fp16, 3 bias+residual->fp32
// ---------------------------------------------------------------------------
template<int AMODE, int EPI>
__global__ void __launch_bounds__(128, 2)
gemm_mma(const __half* __restrict__ A, const __half* __restrict__ A2, int lda,
         const uint32_t* __restrict__ Bp, int nbCols,
         const float* __restrict__ bias,
         void* __restrict__ Cov, int ldc,
         const int* __restrict__ scat, const float* __restrict__ res, int Kd)
{
    extern __shared__ uint32_t sm[];
    // A: 2 stages x 16384 B (128 rows x 128 B, SW128-swizzled 16B chunks)
    // B: 2 stages x 4096 u32 (4 k16-steps x 1024, fragment-major)
    uint32_t* sB = sm + 8192;
    uint32_t sAaddr;
    asm("{ .reg .u64 t; cvta.to.shared.u64 t, %1; cvt.u32.u64 %0, t; }"
        : "=r"(sAaddr) : "l"((const void*)sm));
    const uint32_t sBaddr = sAaddr + 32768;

    const int tid  = threadIdx.x;
    const int lane = tid & 31, wid = tid >> 5;
    const int brow = blockIdx.y * 128, bcol = blockIdx.x * 128;
    const int nblk = blockIdx.x;
    const int mf0 = (wid >> 1) * 4;          // 4 mfrags (64 rows)
    const int nf0 = (wid & 1) * 8;           // 8 nfrags (64 cols)

    float acc[4][8][4];
    #pragma unroll
    for (int a = 0; a < 4; a++)
        #pragma unroll
        for (int b = 0; b < 8; b++)
            #pragma unroll
            for (int r = 0; r < 4; r++) acc[a][b][r] = 0.f;

    // ---- async A copy: 128 rows x 64 cols fp16, 16B chunk c -> c ^ (row&7)
    const int ar0 = tid >> 3;                // 0..15
    const int ac  = tid & 7;                 // 16B chunk within row
    auto CPA = [&](int c, int st) {
        const int k0 = c << 6;
        const __half* src;
        int kk;
        if (AMODE == 2) {
            src = (k0 < 512) ? A : A2;
            kk  = (k0 < 512) ? k0 : k0 - 512;
        } else { src = A; kk = k0; }
        #pragma unroll
        for (int i = 0; i < 8; i++) {
            const int row = ar0 + 16 * i;
            uint32_t dst = sAaddr + st * 16384 + row * 128 + ((ac ^ (row & 7)) << 4);
            cp16(dst, src + (size_t)(brow + row) * lda + kk + ac * 8);
        }
    };
    auto CPB = [&](int c, int st) {
        const uint32_t* src = Bp + ((size_t)(c * nbCols + nblk) << 12);
        #pragma unroll
        for (int j = 0; j < 8; j++)
            cp16(sBaddr + (st * 4096 + (j << 9) + (tid << 2)) * 4,
                 src + (j << 9) + (tid << 2));
    };

    auto COMPUTE = [&](int st) {
        #pragma unroll
        for (int ks = 0; ks < 4; ks++) {
            uint32_t af[4][4], bf[8][2];
            #pragma unroll
            for (int mi = 0; mi < 4; mi++) {
                uint32_t addr = sAaddr + st * 16384
                              + ((mf0 + mi) * 16 + (lane & 15)) * 128
                              + ((((ks << 1) + (lane >> 4)) ^ (lane & 7)) << 4);
                asm volatile(
                    "ldmatrix.sync.aligned.m8n8.x4.shared.b16 {%0,%1,%2,%3}, [%4];"
                    : "=r"(af[mi][0]), "=r"(af[mi][1]), "=r"(af[mi][2]), "=r"(af[mi][3])
                    : "r"(addr));
            }
            #pragma unroll
            for (int ni = 0; ni < 8; ni++) {
                uint2 t = *(const uint2*)(sB + st * 4096 + ks * 1024 +
                                          (nf0 + ni) * 64 + lane * 2);
                bf[ni][0] = t.x; bf[ni][1] = t.y;
            }
            #pragma unroll
            for (int mi = 0; mi < 4; mi++)
                #pragma unroll
                for (int ni = 0; ni < 8; ni++)
                    mma_f16(acc[mi][ni], af[mi], bf[ni]);
        }
    };

    const int KC = Kd >> 6;
    CPA(0, 0); CPB(0, 0); CP_COMMIT();
    CPA(1, 1); CPB(1, 1); CP_COMMIT();
    for (int c = 0; c < KC; c++) {
        const int st = c & 1;
        if (c + 1 < KC) CP_WAIT1(); else CP_WAIT0();
        __syncthreads();
        COMPUTE(st);
        __syncthreads();
        if (c + 2 < KC) { CPA(c + 2, st); CPB(c + 2, st); CP_COMMIT(); }
    }

    // ---- epilogue: fused bias / gelu / scatter / residual
    const int wm = (wid >> 1) * 64, wn = (wid & 1) * 64;
    float*  Cf = (float*)Cov;
    __half* Ch = (__half*)Cov;
    #pragma unroll
    for (int mi = 0; mi < 4; mi++) {
        const int ra = brow + wm + mi * 16 + (lane >> 2);
        const int rb = ra + 8;
        const int ora = (EPI == 1) ? scat[ra] : ra;
        const int orb = (EPI == 1) ? scat[rb] : rb;
        #pragma unroll
        for (int ni = 0; ni < 8; ni++) {
            const int col = bcol + wn + ni * 8 + (lane & 3) * 2;
            const float b0 = bias[col], b1 = bias[col + 1];
            float v0 = acc[mi][ni][0] + b0, v1 = acc[mi][ni][1] + b1;
            float v2 = acc[mi][ni][2] + b0, v3 = acc[mi][ni][3] + b1;
            if (EPI == 2) {
                v0 = 0.5f * v0 * (1.f + erff(v0 * 0.7071067811865475f));
                v1 = 0.5f * v1 * (1.f + erff(v1 * 0.7071067811865475f));
                v2 = 0.5f * v2 * (1.f + erff(v2 * 0.7071067811865475f));
                v3 = 0.5f * v3 * (1.f + erff(v3 * 0.7071067811865475f));
            }
            if (EPI == 3) {
                v0 += res[(size_t)ra * ldc + col];
                v1 += res[(size_t)ra * ldc + col + 1];
                v2 += res[(size_t)rb * ldc + col];
                v3 += res[(size_t)rb * ldc + col + 1];
                *(float2*)(Cf + (size_t)ra * ldc + col) = make_float2(v0, v1);
                *(float2*)(Cf + (size_t)rb * ldc + col) = make_float2(v2, v3);
            } else {
                *(uint32_t*)(Ch + (size_t)ora * ldc + col) = pack2h(v0, v1);
                *(uint32_t*)(Ch + (size_t)orb * ldc + col) = pack2h(v2, v3);
            }
        }
    }
}

// ---------------------------------------------------------------------------
// Fused per-(patch, head, stream) attention, register-blocked (R8, unchanged)
// ---------------------------------------------------------------------------
#define QS 68   // padded row stride (floats), 16B-aligned rows
__global__ void __launch_bounds__(256)
patch_attn_kernel(const __half* __restrict__ qf,
                  const __half* __restrict__ qkv_s,
                  const __half* __restrict__ qkv_b,
                  const int* __restrict__ order,
                  __half* __restrict__ attn_s,
                  __half* __restrict__ attn_b)
{
    const int p = blockIdx.x >> 3;
    const int h = blockIdx.x & 7;
    const __half* qkv = blockIdx.y ? qkv_b : qkv_s;
    __half* out = blockIdx.y ? attn_b : attn_s;

    __shared__ float qs[48 * QS];
    __shared__ float ks[48 * QS];
    __shared__ float vs[48 * QS];
    __shared__ float sc[48 * 48];

    const int tid = threadIdx.x;
    const int lane = tid & 31, wid = tid >> 5;
    const size_t rowbase = (size_t)p * KK;

    for (int e = tid; e < 48 * 32; e += 256) {
        const int r = e >> 5, d2 = (e & 31) << 1;
        float2 q2 = __half22float2(*(const __half2*)(qf + (rowbase + r) * CC + h * DD + d2));
        float2 k2 = __half22float2(*(const __half2*)(qkv + (rowbase + r) * C3 + 512 + h * DD + d2));
        float2 v2 = __half22float2(*(const __half2*)(qkv + (rowbase + r) * C3 + 1024 + h * DD + d2));
        qs[r * QS + d2] = q2.x; qs[r * QS + d2 + 1] = q2.y;
        ks[r * QS + d2] = k2.x; ks[r * QS + d2 + 1] = k2.y;
        vs[r * QS + d2] = v2.x; vs[r * QS + d2 + 1] = v2.y;
    }
    __syncthreads();

    const int tx = tid & 15, ty = tid >> 4;
    const int i0 = ty * 3;

    {
        const int m0 = tx * 3;
        float a[3][3];
        #pragma unroll
        for (int j = 0; j < 3; j++)
            #pragma unroll
            for (int l = 0; l < 3; l++) a[j][l] = 0.f;
        #pragma unroll 4
        for (int dk = 0; dk < 16; dk++) {
            float4 q[3], k[3];
            #pragma unroll
            for (int j = 0; j < 3; j++) q[j] = *(const float4*)&qs[(i0 + j) * QS + dk * 4];
            #pragma unroll
            for (int l = 0; l < 3; l++) k[l] = *(const float4*)&ks[(m0 + l) * QS + dk * 4];
            #pragma unroll
            for (int j = 0; j < 3; j++)
                #pragma unroll
                for (int l = 0; l < 3; l++)
                    a[j][l] += q[j].x * k[l].x + q[j].y * k[l].y
                             + q[j].z * k[l].z + q[j].w * k[l].w;
        }
        #pragma unroll
        for (int j = 0; j < 3; j++)
            #pragma unroll
            for (int l = 0; l < 3; l++)
                sc[(i0 + j) * 48 + m0 + l] = a[j][l] * 0.125f;
    }
    __syncthreads();

    for (int r = wid; r < 48; r += 8) {
        float x0 = sc[r * 48 + lane];
        float x1 = (lane < 16) ? sc[r * 48 + 32 + lane] : -1e30f;
        float mx = fmaxf(x0, x1);
        #pragma unroll
        for (int o = 16; o > 0; o >>= 1) mx = fmaxf(mx, __shfl_xor_sync(0xffffffffu, mx, o));
        float e0 = expf(x0 - mx);
        float e1 = (lane < 16) ? expf(x1 - mx) : 0.f;
        float s = e0 + e1;
        #pragma unroll
        for (int o = 16; o > 0; o >>= 1) s += __shfl_xor_sync(0xffffffffu, s, o);
        float inv = 1.f / s;
        sc[r * 48 + lane] = e0 * inv;
        if (lane < 16) sc[r * 48 + 32 + lane] = e1 * inv;
    }
    __syncthreads();

    {
        const int d0 = tx * 4;
        float o[3][4];
        #pragma unroll
        for (int j = 0; j < 3; j++)
            #pragma unroll
            for (int l = 0; l < 4; l++) o[j][l] = 0.f;
        #pragma unroll 4
        for (int m = 0; m < 48; m++) {
            float4 v4 = *(const float4*)&vs[m * QS + d0];
            float s0 = sc[(i0 + 0) * 48 + m];
            float s1 = sc[(i0 + 1) * 48 + m];
            float s2 = sc[(i0 + 2) * 48 + m];
            o[0][0] += s0 * v4.x; o[0][1] += s0 * v4.y; o[0][2] += s0 * v4.z; o[0][3] += s0 * v4.w;
            o[1][0] += s1 * v4.x; o[1][1] += s1 * v4.y; o[1][2] += s1 * v4.z; o[1][3] += s1 * v4.w;
            o[2][0] += s2 * v4.x; o[2][1] += s2 * v4.y; o[2][2] += s2 * v4.z; o[2][3] += s2 * v4.w;
        }
        #pragma unroll
        for (int j = 0; j < 3; j++) {
            const int grow = order[rowbase + i0 + j];
            uint2 w;
            w.x = pack2h(o[j][0], o[j][1]);
            w.y = pack2h(o[j][2], o[j][3]);
            *(uint2*)(out + (size_t)grow * CC + h * DD + d0) = w;
        }
    }
}

// ---------------------------------------------------------------------------
// Host launch (first QKV GEMM kept at launch index 5 for ncu -s 5)
// ---------------------------------------------------------------------------
extern "C" void kernel_launch(void* const* d_in, const int* in_sizes, int n_in,
                              void* d_out, int out_size)
{
    const float* sem_feat = (const float*)d_in[0];
    const float* bnd_feat = (const float*)d_in[1];
    const int*   order    = (const int*)d_in[2];
    const int*   inverse  = (const int*)d_in[3];
    const float* g_sem    = (const float*)d_in[4];
    const float* b_sem    = (const float*)d_in[5];
    const float* g_bnd    = (const float*)d_in[6];
    const float* b_bnd    = (const float*)d_in[7];
    const float* w_qkv_s  = (const float*)d_in[8];
    const float* b_qkv_s  = (const float*)d_in[9];
    const float* w_qkv_b  = (const float*)d_in[10];
    const float* b_qkv_b  = (const float*)d_in[11];
    const float* w_f1     = (const float*)d_in[12];
    const float* b_f1     = (const float*)d_in[13];
    const float* w_f2     = (const float*)d_in[14];
    const float* b_f2     = (const float*)d_in[15];
    const float* w_os     = (const float*)d_in[16];
    const float* b_os     = (const float*)d_in[17];
    const float* w_ob     = (const float*)d_in[18];
    const float* b_ob     = (const float*)d_in[19];
    float* out = (float*)d_out;

    __half *xln_s, *xln_b, *qkv_s, *qkv_b, *h1, *qf, *attn_s, *attn_b;
    uint32_t *wp_qs, *wp_qb, *wp_f1, *wp_f2, *wp_os, *wp_ob;
    cudaGetSymbolAddress((void**)&xln_s,  g_xln_s);
    cudaGetSymbolAddress((void**)&xln_b,  g_xln_b);
    cudaGetSymbolAddress((void**)&qkv_s,  g_qkv_s);
    cudaGetSymbolAddress((void**)&qkv_b,  g_qkv_b);
    cudaGetSymbolAddress((void**)&h1,     g_h1);
    cudaGetSymbolAddress((void**)&qf,     g_qf);
    cudaGetSymbolAddress((void**)&attn_s, g_attn_s);
    cudaGetSymbolAddress((void**)&attn_b, g_attn_b);
    cudaGetSymbolAddress((void**)&wp_qs,  g_wp_qs);
    cudaGetSymbolAddress((void**)&wp_qb,  g_wp_qb);
    cudaGetSymbolAddress((void**)&wp_f1,  g_wp_f1);
    cudaGetSymbolAddress((void**)&wp_f2,  g_wp_f2);
    cudaGetSymbolAddress((void**)&wp_os,  g_wp_os);
    cudaGetSymbolAddress((void**)&wp_ob,  g_wp_ob);

    const int SMEM_DYN = 65536;   // A 32KB + B 32KB (2 stages)
    cudaFuncSetAttribute(gemm_mma<0, 1>, cudaFuncAttributeMaxDynamicSharedMemorySize, SMEM_DYN);
    cudaFuncSetAttribute(gemm_mma<2, 2>, cudaFuncAttributeMaxDynamicSharedMemorySize, SMEM_DYN);
    cudaFuncSetAttribute(gemm_mma<0, 0>, cudaFuncAttributeMaxDynamicSharedMemorySize, SMEM_DYN);
    cudaFuncSetAttribute(gemm_mma<0, 3>, cudaFuncAttributeMaxDynamicSharedMemorySize, SMEM_DYN);

    prep_w<<<(CC / 2) * C3 / 256, 256>>>(w_qkv_s, wp_qs, CC, C3);            // 0
    prep_w<<<(CC / 2) * C3 / 256, 256>>>(w_qkv_b, wp_qb, CC, C3);            // 1
    ln_fp16<<<NN / 8, 256>>>(sem_feat, g_sem, b_sem, xln_s);                 // 2
    ln_fp16<<<NN / 8, 256>>>(bnd_feat, g_bnd, b_bnd, xln_b);                 // 3
    prep_w<<<(C2 / 2) * C2 / 256, 256>>>(w_f1, wp_f1, C2, C2);               // 4

    // QKV GEMMs (fp16 LN'd A, scatter by inverse, fp16 out)
    gemm_mma<0, 1><<<dim3(C3 / 128, NN / 128), 128, SMEM_DYN>>>(             // 5
        xln_s, nullptr, CC, wp_qs, C3 / 128, b_qkv_s, qkv_s, C3,
        inverse, nullptr, CC);
    gemm_mma<0, 1><<<dim3(C3 / 128, NN / 128), 128, SMEM_DYN>>>(             // 6
        xln_b, nullptr, CC, wp_qb, C3 / 128, b_qkv_b, qkv_b, C3,
        inverse, nullptr, CC);

    prep_w<<<(C2 / 2) * CC / 256, 256>>>(w_f2, wp_f2, C2, CC);               // 7
    gemm_mma<2, 2><<<dim3(C2 / 128, NN / 128), 128, SMEM_DYN>>>(             // 8
        qkv_s, qkv_b, C3, wp_f1, C2 / 128, b_f1, h1, C2,
        nullptr, nullptr, C2);
    prep_w<<<(CC / 2) * CC / 256, 256>>>(w_os, wp_os, CC, CC);               // 9
    gemm_mma<0, 0><<<dim3(CC / 128, NN / 128), 128, SMEM_DYN>>>(             // 10
        h1, nullptr, C2, wp_f2, CC / 128, b_f2, qf, CC,
        nullptr, nullptr, C2);
    prep_w<<<(CC / 2) * CC / 256, 256>>>(w_ob, wp_ob, CC, CC);               // 11

    patch_attn_kernel<<<dim3(PP * HH, 2), 256>>>(qf, qkv_s, qkv_b, order,    // 12
                                                 attn_s, attn_b);

    gemm_mma<0, 3><<<dim3(CC / 128, NN / 128), 128, SMEM_DYN>>>(             // 13
        attn_s, nullptr, CC, wp_os, CC / 128, b_os, out, CC,
        nullptr, sem_feat, CC);
    gemm_mma<0, 3><<<dim3(CC / 128, NN / 128), 128, SMEM_DYN>>>(             // 14
        attn_b, nullptr, CC, wp_ob, CC / 128, b_ob, out + (size_t)NN * CC, CC,
        nullptr, bnd_feat, CC);
}

// round 13
// speedup vs baseline: 7.8819x; 1.1690x over previous
#include <cuda_runtime.h>
#include <cuda_fp16.h>
#include <math.h>
#include <stdint.h>

// Problem constants
#define NN 49152
#define CC 512
#define HH 8
#define KK 48
#define DD 64
#define PP 1024            // NN / KK
#define C3 1536            // 3*C
#define C2 1024            // 2*C

// ---------------------------------------------------------------------------
// Scratch (device globals; no runtime allocation). Intermediates are fp16.
// ---------------------------------------------------------------------------
__device__ __half g_xln_s[(size_t)NN * CC];   // LN-transformed inputs, fp16
__device__ __half g_xln_b[(size_t)NN * CC];
__device__ __half g_qkv_s[(size_t)NN * C3];
__device__ __half g_qkv_b[(size_t)NN * C3];
__device__ __half g_h1[(size_t)NN * C2];
__device__ __half g_qf[(size_t)NN * CC];
__device__ __half g_attn_s[(size_t)NN * CC];
__device__ __half g_attn_b[(size_t)NN * CC];
// Packed fp16 weights, fragment-major, grouped by 64-k chunk:
// u32 index = ((chunk*(N/128) + nblk)*4 + k16step)*1024 + nfrag*64 + lane*2 + reg
__device__ uint32_t g_wp_qs[(size_t)(CC / 2) * C3];
__device__ uint32_t g_wp_qb[(size_t)(CC / 2) * C3];
__device__ uint32_t g_wp_f1[(size_t)(C2 / 2) * C2];
__device__ uint32_t g_wp_f2[(size_t)(C2 / 2) * CC];
__device__ uint32_t g_wp_os[(size_t)(CC / 2) * CC];
__device__ uint32_t g_wp_ob[(size_t)(CC / 2) * CC];

// ---------------------------------------------------------------------------
// Helpers (base-target PTX, sm_80+ only)
// ---------------------------------------------------------------------------
__device__ __forceinline__ uint32_t pack2h(float a, float b) {
    __half2 h = __floats2half2_rn(a, b);
    return *reinterpret_cast<uint32_t*>(&h);
}

__device__ __forceinline__ uint32_t smem_u32(const void* p) {
    uint32_t a;
    asm("{ .reg .u64 t; cvta.to.shared.u64 t, %1; cvt.u32.u64 %0, t; }"
        : "=r"(a) : "l"(p));
    return a;
}

__device__ __forceinline__ void mma_f16(float* d, const uint32_t* a, const uint32_t* b) {
    asm volatile(
        "mma.sync.aligned.m16n8k16.row.col.f32.f16.f16.f32 "
        "{%0,%1,%2,%3}, {%4,%5,%6,%7}, {%8,%9}, {%0,%1,%2,%3};"
        : "+f"(d[0]), "+f"(d[1]), "+f"(d[2]), "+f"(d[3])
        : "r"(a[0]), "r"(a[1]), "r"(a[2]), "r"(a[3]), "r"(b[0]), "r"(b[1]));
}

__device__ __forceinline__ void cp16(uint32_t saddr, const void* gptr) {
    asm volatile("cp.async.cg.shared.global [%0], [%1], 16;" :: "r"(saddr), "l"(gptr));
}
#define CP_COMMIT() asm volatile("cp.async.commit_group;" ::: "memory")
#define CP_WAIT0()  asm volatile("cp.async.wait_group 0;" ::: "memory")
#define CP_WAIT1()  asm volatile("cp.async.wait_group 1;" ::: "memory")

// ---------------------------------------------------------------------------
// Weight pack: w [K,N] fp32 row-major -> fp16 pairs, fragment-major, 64-k chunks
// ---------------------------------------------------------------------------
__global__ void prep_w(const float* __restrict__ w, uint32_t* __restrict__ out,
                       int Kd, int Nd)
{
    int idx = blockIdx.x * 256 + threadIdx.x;      // over (K/2)*N
    if (idx >= (Kd >> 1) * Nd) return;
    int n  = idx % Nd;
    int k  = (idx / Nd) << 1;                      // even k
    float v0 = w[(size_t)k * Nd + n];
    float v1 = w[(size_t)(k + 1) * Nd + n];
    int cc   = k >> 6;                             // 64-k chunk
    int step = (k >> 4) & 3;
    int nblk = n >> 7, nn = n & 127;
    int nfrag = nn >> 3;
    int lane  = (nn & 7) * 4 + ((k & 7) >> 1);
    int reg   = (k & 15) >> 3;
    size_t o = ((size_t)(cc * (Nd >> 7) + nblk) * 4 + step) * 1024
             + nfrag * 64 + lane * 2 + reg;
    out[o] = pack2h(v0, v1);
}

// ---------------------------------------------------------------------------
// Fused LayerNorm: stats + transform, fp32 in -> fp16 out. One warp per row.
// ---------------------------------------------------------------------------
__global__ void __launch_bounds__(256)
ln_fp16(const float* __restrict__ x, const float* __restrict__ g,
        const float* __restrict__ b, __half* __restrict__ o)
{
    const int row  = blockIdx.x * 8 + (threadIdx.x >> 5);
    const int lane = threadIdx.x & 31;
    const float* xr = x + (size_t)row * CC;
    float4 v[4];
    float s = 0.f, sq = 0.f;
    #pragma unroll
    for (int j = 0; j < 4; j++) {
        v[j] = *(const float4*)(xr + lane * 4 + 128 * j);
        s  += v[j].x + v[j].y + v[j].z + v[j].w;
        sq += v[j].x * v[j].x + v[j].y * v[j].y + v[j].z * v[j].z + v[j].w * v[j].w;
    }
    #pragma unroll
    for (int off = 16; off > 0; off >>= 1) {
        s  += __shfl_xor_sync(0xffffffffu, s, off);
        sq += __shfl_xor_sync(0xffffffffu, sq, off);
    }
    const float m = s * (1.f / CC);
    const float r = rsqrtf(sq * (1.f / CC) - m * m + 1e-5f);
    __half* orow = o + (size_t)row * CC;
    #pragma unroll
    for (int j = 0; j < 4; j++) {
        const int col = lane * 4 + 128 * j;
        float4 g4 = *(const float4*)(g + col);
        float4 b4 = *(const float4*)(b + col);
        uint2 w;
        w.x = pack2h((v[j].x - m) * r * g4.x + b4.x, (v[j].y - m) * r * g4.y + b4.y);
        w.y = pack2h((v[j].z - m) * r * g4.z + b4.z, (v[j].w - m) * r * g4.w + b4.w);
        *(uint2*)(orow + col) = w;
    }
}

// ---------------------------------------------------------------------------
// Fully-async FP16 mma.sync GEMM (R9, unchanged): C[128x128] = op(A) @ W + epi
// ---------------------------------------------------------------------------
template<int AMODE, int EPI>
__global__ void __launch_bounds__(128, 2)
gemm_mma(const __half* __restrict__ A, const __half* __restrict__ A2, int lda,
         const uint32_t* __restrict__ Bp, int nbCols,
         const float* __restrict__ bias,
         void* __restrict__ Cov, int ldc,
         const int* __restrict__ scat, const float* __restrict__ res, int Kd)
{
    extern __shared__ uint32_t sm[];
    uint32_t* sB = sm + 8192;
    uint32_t sAaddr;
    asm("{ .reg .u64 t; cvta.to.shared.u64 t, %1; cvt.u32.u64 %0, t; }"
        : "=r"(sAaddr) : "l"((const void*)sm));
    const uint32_t sBaddr = sAaddr + 32768;

    const int tid  = threadIdx.x;
    const int lane = tid & 31, wid = tid >> 5;
    const int brow = blockIdx.y * 128, bcol = blockIdx.x * 128;
    const int nblk = blockIdx.x;
    const int mf0 = (wid >> 1) * 4;
    const int nf0 = (wid & 1) * 8;

    float acc[4][8][4];
    #pragma unroll
    for (int a = 0; a < 4; a++)
        #pragma unroll
        for (int b = 0; b < 8; b++)
            #pragma unroll
            for (int r = 0; r < 4; r++) acc[a][b][r] = 0.f;

    const int ar0 = tid >> 3;
    const int ac  = tid & 7;
    auto CPA = [&](int c, int st) {
        const int k0 = c << 6;
        const __half* src;
        int kk;
        if (AMODE == 2) {
            src = (k0 < 512) ? A : A2;
            kk  = (k0 < 512) ? k0 : k0 - 512;
        } else { src = A; kk = k0; }
        #pragma unroll
        for (int i = 0; i < 8; i++) {
            const int row = ar0 + 16 * i;
            uint32_t dst = sAaddr + st * 16384 + row * 128 + ((ac ^ (row & 7)) << 4);
            cp16(dst, src + (size_t)(brow + row) * lda + kk + ac * 8);
        }
    };
    auto CPB = [&](int c, int st) {
        const uint32_t* src = Bp + ((size_t)(c * nbCols + nblk) << 12);
        #pragma unroll
        for (int j = 0; j < 8; j++)
            cp16(sBaddr + (st * 4096 + (j << 9) + (tid << 2)) * 4,
                 src + (j << 9) + (tid << 2));
    };

    auto COMPUTE = [&](int st) {
        #pragma unroll
        for (int ks = 0; ks < 4; ks++) {
            uint32_t af[4][4], bf[8][2];
            #pragma unroll
            for (int mi = 0; mi < 4; mi++) {
                uint32_t addr = sAaddr + st * 16384
                              + ((mf0 + mi) * 16 + (lane & 15)) * 128
                              + ((((ks << 1) + (lane >> 4)) ^ (lane & 7)) << 4);
                asm volatile(
                    "ldmatrix.sync.aligned.m8n8.x4.shared.b16 {%0,%1,%2,%3}, [%4];"
                    : "=r"(af[mi][0]), "=r"(af[mi][1]), "=r"(af[mi][2]), "=r"(af[mi][3])
                    : "r"(addr));
            }
            #pragma unroll
            for (int ni = 0; ni < 8; ni++) {
                uint2 t = *(const uint2*)(sB + st * 4096 + ks * 1024 +
                                          (nf0 + ni) * 64 + lane * 2);
                bf[ni][0] = t.x; bf[ni][1] = t.y;
            }
            #pragma unroll
            for (int mi = 0; mi < 4; mi++)
                #pragma unroll
                for (int ni = 0; ni < 8; ni++)
                    mma_f16(acc[mi][ni], af[mi], bf[ni]);
        }
    };

    const int KC = Kd >> 6;
    CPA(0, 0); CPB(0, 0); CP_COMMIT();
    CPA(1, 1); CPB(1, 1); CP_COMMIT();
    for (int c = 0; c < KC; c++) {
        const int st = c & 1;
        if (c + 1 < KC) CP_WAIT1(); else CP_WAIT0();
        __syncthreads();
        COMPUTE(st);
        __syncthreads();
        if (c + 2 < KC) { CPA(c + 2, st); CPB(c + 2, st); CP_COMMIT(); }
    }

    const int wm = (wid >> 1) * 64, wn = (wid & 1) * 64;
    float*  Cf = (float*)Cov;
    __half* Ch = (__half*)Cov;
    #pragma unroll
    for (int mi = 0; mi < 4; mi++) {
        const int ra = brow + wm + mi * 16 + (lane >> 2);
        const int rb = ra + 8;
        const int ora = (EPI == 1) ? scat[ra] : ra;
        const int orb = (EPI == 1) ? scat[rb] : rb;
        #pragma unroll
        for (int ni = 0; ni < 8; ni++) {
            const int col = bcol + wn + ni * 8 + (lane & 3) * 2;
            const float b0 = bias[col], b1 = bias[col + 1];
            float v0 = acc[mi][ni][0] + b0, v1 = acc[mi][ni][1] + b1;
            float v2 = acc[mi][ni][2] + b0, v3 = acc[mi][ni][3] + b1;
            if (EPI == 2) {
                v0 = 0.5f * v0 * (1.f + erff(v0 * 0.7071067811865475f));
                v1 = 0.5f * v1 * (1.f + erff(v1 * 0.7071067811865475f));
                v2 = 0.5f * v2 * (1.f + erff(v2 * 0.7071067811865475f));
                v3 = 0.5f * v3 * (1.f + erff(v3 * 0.7071067811865475f));
            }
            if (EPI == 3) {
                v0 += res[(size_t)ra * ldc + col];
                v1 += res[(size_t)ra * ldc + col + 1];
                v2 += res[(size_t)rb * ldc + col];
                v3 += res[(size_t)rb * ldc + col + 1];
                *(float2*)(Cf + (size_t)ra * ldc + col) = make_float2(v0, v1);
                *(float2*)(Cf + (size_t)rb * ldc + col) = make_float2(v2, v3);
            } else {
                *(uint32_t*)(Ch + (size_t)ora * ldc + col) = pack2h(v0, v1);
                *(uint32_t*)(Ch + (size_t)orb * ldc + col) = pack2h(v2, v3);
            }
        }
    }
}

// ---------------------------------------------------------------------------
// Tensor-core per-(patch, head, stream) attention.
// grid = (PP*HH, 2), 128 threads (4 warps).
// Scores: mma m16n8k16, A = Q (x4 non-trans), B = K rows (x2 non-trans).
// AV:     A = probs fp16 (x4 non-trans), B = V rows (x2 TRANS).
// Softmax warp-per-row in fp32. fp16 in/out.
// ---------------------------------------------------------------------------
#define AST 72    // q/k/v smem stride in halves (144 B rows, conflict-free)
#define SCST 52   // score fp32 stride
#define PST 56    // prob fp16 stride (112 B rows)
__global__ void __launch_bounds__(128)
patch_attn_kernel(const __half* __restrict__ qf,
                  const __half* __restrict__ qkv_s,
                  const __half* __restrict__ qkv_b,
                  const int* __restrict__ order,
                  __half* __restrict__ attn_s,
                  __half* __restrict__ attn_b)
{
    const int p = blockIdx.x >> 3;
    const int h = blockIdx.x & 7;
    const __half* qkv = blockIdx.y ? qkv_b : qkv_s;
    __half* out = blockIdx.y ? attn_b : attn_s;

    __shared__ __half Qh[48 * AST];
    __shared__ __half Kh[48 * AST];
    __shared__ __half Vh[48 * AST];
    __shared__ float  scs[48 * SCST];
    __shared__ __half Ph[48 * PST];

    const int tid = threadIdx.x, lane = tid & 31, wid = tid >> 5;
    const size_t rowbase = (size_t)p * KK;
    const uint32_t qa = smem_u32(Qh), ka = smem_u32(Kh), va = smem_u32(Vh);
    const uint32_t pa = smem_u32(Ph);

    // ---- load q/k/v rows (fp16, 128B each) via cp.async: 144 rows x 8 chunks
    #pragma unroll
    for (int i = 0; i < 9; i++) {
        const int idx = i * 128 + tid;
        const int row = idx >> 3, c = idx & 7;
        const int seg = row / 48;            // 0=q, 1=k, 2=v
        const int r = row - seg * 48;
        const __half* src = (seg == 0)
            ? qf + (rowbase + r) * CC + h * DD
            : qkv + (rowbase + r) * C3 + (seg == 1 ? 512 : 1024) + h * DD;
        const uint32_t base = (seg == 0) ? qa : (seg == 1) ? ka : va;
        cp16(base + r * (AST * 2) + c * 16, src + c * 8);
    }
    CP_COMMIT();
    CP_WAIT0();
    __syncthreads();

    // ---- phase 1: S = Q @ K^T * scale  (18 tiles: 3 mfrag x 6 nfrag)
    for (int t = wid; t < 18; t += 4) {
        const int mf = t / 6, nf = t % 6;
        float d4[4] = { 0.f, 0.f, 0.f, 0.f };
        #pragma unroll
        for (int ks = 0; ks < 4; ks++) {
            uint32_t a[4], b[2];
            uint32_t aaddr = qa + ((mf * 16 + (lane & 15)) * AST
                                   + ks * 16 + ((lane >> 4) << 3)) * 2;
            asm volatile("ldmatrix.sync.aligned.m8n8.x4.shared.b16 {%0,%1,%2,%3}, [%4];"
                         : "=r"(a[0]), "=r"(a[1]), "=r"(a[2]), "=r"(a[3]) : "r"(aaddr));
            uint32_t baddr = ka + ((nf * 8 + (lane & 7)) * AST
                                   + ks * 16 + (((lane >> 3) & 1) << 3)) * 2;
            asm volatile("ldmatrix.sync.aligned.m8n8.x2.shared.b16 {%0,%1}, [%2];"
                         : "=r"(b[0]), "=r"(b[1]) : "r"(baddr));
            mma_f16(d4, a, b);
        }
        const int r0 = mf * 16 + (lane >> 2), c0 = nf * 8 + (lane & 3) * 2;
        scs[r0 * SCST + c0]       = d4[0] * 0.125f;
        scs[r0 * SCST + c0 + 1]   = d4[1] * 0.125f;
        scs[(r0 + 8) * SCST + c0]     = d4[2] * 0.125f;
        scs[(r0 + 8) * SCST + c0 + 1] = d4[3] * 0.125f;
    }
    __syncthreads();

    // ---- phase 2: softmax, warp per row, write probs as fp16
    for (int r = wid; r < 48; r += 4) {
        float x0 = scs[r * SCST + lane];
        float x1 = (lane < 16) ? scs[r * SCST + 32 + lane] : -1e30f;
        float mx = fmaxf(x0, x1);
        #pragma unroll
        for (int o = 16; o > 0; o >>= 1) mx = fmaxf(mx, __shfl_xor_sync(0xffffffffu, mx, o));
        float e0 = expf(x0 - mx);
        float e1 = (lane < 16) ? expf(x1 - mx) : 0.f;
        float s = e0 + e1;
        #pragma unroll
        for (int o = 16; o > 0; o >>= 1) s += __shfl_xor_sync(0xffffffffu, s, o);
        float inv = 1.f / s;
        Ph[r * PST + lane] = __float2half(e0 * inv);
        if (lane < 16) Ph[r * PST + 32 + lane] = __float2half(e1 * inv);
    }
    __syncthreads();

    // ---- phase 3: O = P @ V  (24 tiles: 3 mfrag x 8 nfrag), scatter by order
    for (int t = wid; t < 24; t += 4) {
        const int mf = t >> 3, nf = t & 7;
        float d4[4] = { 0.f, 0.f, 0.f, 0.f };
        #pragma unroll
        for (int ks = 0; ks < 3; ks++) {
            uint32_t a[4], b[2];
            uint32_t aaddr = pa + ((mf * 16 + (lane & 15)) * PST
                                   + ks * 16 + ((lane >> 4) << 3)) * 2;
            asm volatile("ldmatrix.sync.aligned.m8n8.x4.shared.b16 {%0,%1,%2,%3}, [%4];"
                         : "=r"(a[0]), "=r"(a[1]), "=r"(a[2]), "=r"(a[3]) : "r"(aaddr));
            uint32_t baddr = va + ((ks * 16 + (((lane >> 3) & 1) << 3) + (lane & 7)) * AST
                                   + nf * 8) * 2;
            asm volatile("ldmatrix.sync.aligned.m8n8.x2.trans.shared.b16 {%0,%1}, [%2];"
                         : "=r"(b[0]), "=r"(b[1]) : "r"(baddr));
            mma_f16(d4, a, b);
        }
        const int r0 = mf * 16 + (lane >> 2), c0 = nf * 8 + (lane & 3) * 2;
        const int g0 = order[rowbase + r0];
        const int g1 = order[rowbase + r0 + 8];
        *(uint32_t*)(out + (size_t)g0 * CC + h * DD + c0) = pack2h(d4[0], d4[1]);
        *(uint32_t*)(out + (size_t)g1 * CC + h * DD + c0) = pack2h(d4[2], d4[3]);
    }
}

// ---------------------------------------------------------------------------
// Host launch
// ---------------------------------------------------------------------------
extern "C" void kernel_launch(void* const* d_in, const int* in_sizes, int n_in,
                              void* d_out, int out_size)
{
    const float* sem_feat = (const float*)d_in[0];
    const float* bnd_feat = (const float*)d_in[1];
    const int*   order    = (const int*)d_in[2];
    const int*   inverse  = (const int*)d_in[3];
    const float* g_sem    = (const float*)d_in[4];
    const float* b_sem    = (const float*)d_in[5];
    const float* g_bnd    = (const float*)d_in[6];
    const float* b_bnd    = (const float*)d_in[7];
    const float* w_qkv_s  = (const float*)d_in[8];
    const float* b_qkv_s  = (const float*)d_in[9];
    const float* w_qkv_b  = (const float*)d_in[10];
    const float* b_qkv_b  = (const float*)d_in[11];
    const float* w_f1     = (const float*)d_in[12];
    const float* b_f1     = (const float*)d_in[13];
    const float* w_f2     = (const float*)d_in[14];
    const float* b_f2     = (const float*)d_in[15];
    const float* w_os     = (const float*)d_in[16];
    const float* b_os     = (const float*)d_in[17];
    const float* w_ob     = (const float*)d_in[18];
    const float* b_ob     = (const float*)d_in[19];
    float* out = (float*)d_out;

    __half *xln_s, *xln_b, *qkv_s, *qkv_b, *h1, *qf, *attn_s, *attn_b;
    uint32_t *wp_qs, *wp_qb, *wp_f1, *wp_f2, *wp_os, *wp_ob;
    cudaGetSymbolAddress((void**)&xln_s,  g_xln_s);
    cudaGetSymbolAddress((void**)&xln_b,  g_xln_b);
    cudaGetSymbolAddress((void**)&qkv_s,  g_qkv_s);
    cudaGetSymbolAddress((void**)&qkv_b,  g_qkv_b);
    cudaGetSymbolAddress((void**)&h1,     g_h1);
    cudaGetSymbolAddress((void**)&qf,     g_qf);
    cudaGetSymbolAddress((void**)&attn_s, g_attn_s);
    cudaGetSymbolAddress((void**)&attn_b, g_attn_b);
    cudaGetSymbolAddress((void**)&wp_qs,  g_wp_qs);
    cudaGetSymbolAddress((void**)&wp_qb,  g_wp_qb);
    cudaGetSymbolAddress((void**)&wp_f1,  g_wp_f1);
    cudaGetSymbolAddress((void**)&wp_f2,  g_wp_f2);
    cudaGetSymbolAddress((void**)&wp_os,  g_wp_os);
    cudaGetSymbolAddress((void**)&wp_ob,  g_wp_ob);

    const int SMEM_DYN = 65536;   // A 32KB + B 32KB (2 stages)
    cudaFuncSetAttribute(gemm_mma<0, 1>, cudaFuncAttributeMaxDynamicSharedMemorySize, SMEM_DYN);
    cudaFuncSetAttribute(gemm_mma<2, 2>, cudaFuncAttributeMaxDynamicSharedMemorySize, SMEM_DYN);
    cudaFuncSetAttribute(gemm_mma<0, 0>, cudaFuncAttributeMaxDynamicSharedMemorySize, SMEM_DYN);
    cudaFuncSetAttribute(gemm_mma<0, 3>, cudaFuncAttributeMaxDynamicSharedMemorySize, SMEM_DYN);

    prep_w<<<(CC / 2) * C3 / 256, 256>>>(w_qkv_s, wp_qs, CC, C3);            // 0
    prep_w<<<(CC / 2) * C3 / 256, 256>>>(w_qkv_b, wp_qb, CC, C3);            // 1
    ln_fp16<<<NN / 8, 256>>>(sem_feat, g_sem, b_sem, xln_s);                 // 2
    ln_fp16<<<NN / 8, 256>>>(bnd_feat, g_bnd, b_bnd, xln_b);                 // 3
    prep_w<<<(C2 / 2) * C2 / 256, 256>>>(w_f1, wp_f1, C2, C2);               // 4

    // QKV GEMMs (fp16 LN'd A, scatter by inverse, fp16 out)
    gemm_mma<0, 1><<<dim3(C3 / 128, NN / 128), 128, SMEM_DYN>>>(             // 5
        xln_s, nullptr, CC, wp_qs, C3 / 128, b_qkv_s, qkv_s, C3,
        inverse, nullptr, CC);
    gemm_mma<0, 1><<<dim3(C3 / 128, NN / 128), 128, SMEM_DYN>>>(             // 6
        xln_b, nullptr, CC, wp_qb, C3 / 128, b_qkv_b, qkv_b, C3,
        inverse, nullptr, CC);

    prep_w<<<(C2 / 2) * CC / 256, 256>>>(w_f2, wp_f2, C2, CC);               // 7
    gemm_mma<2, 2><<<dim3(C2 / 128, NN / 128), 128, SMEM_DYN>>>(             // 8
        qkv_s, qkv_b, C3, wp_f1, C2 / 128, b_f1, h1, C2,
        nullptr, nullptr, C2);
    prep_w<<<(CC / 2) * CC / 256, 256>>>(w_os, wp_os, CC, CC);               // 9
    gemm_mma<0, 0><<<dim3(CC / 128, NN / 128), 128, SMEM_DYN>>>(             // 10
        h1, nullptr, C2, wp_f2, CC / 128, b_f2, qf, CC,
        nullptr, nullptr, C2);
    prep_w<<<(CC / 2) * CC / 256, 256>>>(w_ob, wp_ob, CC, CC);               // 11

    patch_attn_kernel<<<dim3(PP * HH, 2), 128>>>(qf, qkv_s, qkv_b, order,    // 12
                                                 attn_s, attn_b);

    gemm_mma<0, 3><<<dim3(CC / 128, NN / 128), 128, SMEM_DYN>>>(             // 13
        attn_s, nullptr, CC, wp_os, CC / 128, b_os, out, CC,
        nullptr, sem_feat, CC);
    gemm_mma<0, 3><<<dim3(CC / 128, NN / 128), 128, SMEM_DYN>>>(             // 14
        attn_b, nullptr, CC, wp_ob, CC / 128, b_ob, out + (size_t)NN * CC, CC,
        nullptr, bnd_feat, CC);
}

// round 14
// speedup vs baseline: 7.9485x; 1.0084x over previous
#include <cuda_runtime.h>
#include <cuda_fp16.h>
#include <math.h>
#include <stdint.h>

// Problem constants
#define NN 49152
#define CC 512
#define HH 8
#define KK 48
#define DD 64
#define PP 1024            // NN / KK
#define C3 1536            // 3*C
#define C2 1024            // 2*C

// ---------------------------------------------------------------------------
// Scratch (device globals; no runtime allocation). Intermediates are fp16.
// ---------------------------------------------------------------------------
__device__ __half g_xln_s[(size_t)NN * CC];   // LN-transformed inputs, fp16
__device__ __half g_xln_b[(size_t)NN * CC];
__device__ __half g_qkv_s[(size_t)NN * C3];
__device__ __half g_qkv_b[(size_t)NN * C3];
__device__ __half g_h1[(size_t)NN * C2];
__device__ __half g_qf[(size_t)NN * CC];
__device__ __half g_attn_s[(size_t)NN * CC];
__device__ __half g_attn_b[(size_t)NN * CC];
// Packed fp16 weights, fragment-major, grouped by 64-k chunk:
// u32 index = ((chunk*(N/128) + nblk)*4 + k16step)*1024 + nfrag*64 + lane*2 + reg
__device__ uint32_t g_wp_qs[(size_t)(CC / 2) * C3];
__device__ uint32_t g_wp_qb[(size_t)(CC / 2) * C3];
__device__ uint32_t g_wp_f1[(size_t)(C2 / 2) * C2];
__device__ uint32_t g_wp_f2[(size_t)(C2 / 2) * CC];
__device__ uint32_t g_wp_os[(size_t)(CC / 2) * CC];
__device__ uint32_t g_wp_ob[(size_t)(CC / 2) * CC];

// ---------------------------------------------------------------------------
// Helpers (base-target PTX, sm_80+ only)
// ---------------------------------------------------------------------------
__device__ __forceinline__ uint32_t pack2h(float a, float b) {
    __half2 h = __floats2half2_rn(a, b);
    return *reinterpret_cast<uint32_t*>(&h);
}

__device__ __forceinline__ uint32_t smem_u32(const void* p) {
    uint32_t a;
    asm("{ .reg .u64 t; cvta.to.shared.u64 t, %1; cvt.u32.u64 %0, t; }"
        : "=r"(a) : "l"(p));
    return a;
}

__device__ __forceinline__ void mma_f16(float* d, const uint32_t* a, const uint32_t* b) {
    asm volatile(
        "mma.sync.aligned.m16n8k16.row.col.f32.f16.f16.f32 "
        "{%0,%1,%2,%3}, {%4,%5,%6,%7}, {%8,%9}, {%0,%1,%2,%3};"
        : "+f"(d[0]), "+f"(d[1]), "+f"(d[2]), "+f"(d[3])
        : "r"(a[0]), "r"(a[1]), "r"(a[2]), "r"(a[3]), "r"(b[0]), "r"(b[1]));
}

__device__ __forceinline__ void cp16(uint32_t saddr, const void* gptr) {
    asm volatile("cp.async.cg.shared.global [%0], [%1], 16;" :: "r"(saddr), "l"(gptr));
}
#define CP_COMMIT() asm volatile("cp.async.commit_group;" ::: "memory")
#define CP_WAIT0()  asm volatile("cp.async.wait_group 0;" ::: "memory")
#define CP_WAIT1()  asm volatile("cp.async.wait_group 1;" ::: "memory")

// ---------------------------------------------------------------------------
// Weight pack body: w [K,N] fp32 -> fp16 pairs, fragment-major, 64-k chunks
// ---------------------------------------------------------------------------
__device__ __forceinline__ void prep_body(const float* __restrict__ w,
                                          uint32_t* __restrict__ out,
                                          int Kd, int Nd, int idx)
{
    int n  = idx % Nd;
    int k  = (idx / Nd) << 1;                      // even k
    float v0 = w[(size_t)k * Nd + n];
    float v1 = w[(size_t)(k + 1) * Nd + n];
    int cc   = k >> 6;                             // 64-k chunk
    int step = (k >> 4) & 3;
    int nblk = n >> 7, nn = n & 127;
    int nfrag = nn >> 3;
    int lane  = (nn & 7) * 4 + ((k & 7) >> 1);
    int reg   = (k & 15) >> 3;
    size_t o = ((size_t)(cc * (Nd >> 7) + nblk) * 4 + step) * 1024
             + nfrag * 64 + lane * 2 + reg;
    out[o] = pack2h(v0, v1);
}

// One launch packs all 6 weight matrices (segment if-chain).
__global__ void __launch_bounds__(256)
prep_all(const float* __restrict__ w0, const float* __restrict__ w1,
         const float* __restrict__ w2, const float* __restrict__ w3,
         const float* __restrict__ w4, const float* __restrict__ w5,
         uint32_t* __restrict__ o0, uint32_t* __restrict__ o1,
         uint32_t* __restrict__ o2, uint32_t* __restrict__ o3,
         uint32_t* __restrict__ o4, uint32_t* __restrict__ o5)
{
    int idx = blockIdx.x * 256 + threadIdx.x;
    if (idx < 393216)        prep_body(w0, o0, 512, 1536, idx);
    else if (idx < 786432)   prep_body(w1, o1, 512, 1536, idx - 393216);
    else if (idx < 1310720)  prep_body(w2, o2, 1024, 1024, idx - 786432);
    else if (idx < 1572864)  prep_body(w3, o3, 1024, 512, idx - 1310720);
    else if (idx < 1703936)  prep_body(w4, o4, 512, 512, idx - 1572864);
    else if (idx < 1835008)  prep_body(w5, o5, 512, 512, idx - 1703936);
}

// ---------------------------------------------------------------------------
// Fused LayerNorm (both streams via grid.y): fp32 in -> fp16 out, warp/row
// ---------------------------------------------------------------------------
__global__ void __launch_bounds__(256)
ln_fp16(const float* __restrict__ x0, const float* __restrict__ x1,
        const float* __restrict__ g0, const float* __restrict__ b0,
        const float* __restrict__ g1, const float* __restrict__ b1,
        __half* __restrict__ o0, __half* __restrict__ o1)
{
    const float* x = blockIdx.y ? x1 : x0;
    const float* g = blockIdx.y ? g1 : g0;
    const float* b = blockIdx.y ? b1 : b0;
    __half* o = blockIdx.y ? o1 : o0;

    const int row  = blockIdx.x * 8 + (threadIdx.x >> 5);
    const int lane = threadIdx.x & 31;
    const float* xr = x + (size_t)row * CC;
    float4 v[4];
    float s = 0.f, sq = 0.f;
    #pragma unroll
    for (int j = 0; j < 4; j++) {
        v[j] = *(const float4*)(xr + lane * 4 + 128 * j);
        s  += v[j].x + v[j].y + v[j].z + v[j].w;
        sq += v[j].x * v[j].x + v[j].y * v[j].y + v[j].z * v[j].z + v[j].w * v[j].w;
    }
    #pragma unroll
    for (int off = 16; off > 0; off >>= 1) {
        s  += __shfl_xor_sync(0xffffffffu, s, off);
        sq += __shfl_xor_sync(0xffffffffu, sq, off);
    }
    const float m = s * (1.f / CC);
    const float r = rsqrtf(sq * (1.f / CC) - m * m + 1e-5f);
    __half* orow = o + (size_t)row * CC;
    #pragma unroll
    for (int j = 0; j < 4; j++) {
        const int col = lane * 4 + 128 * j;
        float4 g4 = *(const float4*)(g + col);
        float4 b4 = *(const float4*)(b + col);
        uint2 w;
        w.x = pack2h((v[j].x - m) * r * g4.x + b4.x, (v[j].y - m) * r * g4.y + b4.y);
        w.y = pack2h((v[j].z - m) * r * g4.z + b4.z, (v[j].w - m) * r * g4.w + b4.w);
        *(uint2*)(orow + col) = w;
    }
}

// ---------------------------------------------------------------------------
// Fully-async FP16 mma.sync GEMM, 3-stage cp.async pipeline, ONE barrier/chunk.
// C[128x128] = op(A)[128xK] @ W + epilogue. 128 threads (4 warps, 2x2).
// A fp16 row-major -> cp.async, swizzled -> ldmatrix. B prepacked frag-major.
// AMODE: 0 plain fp16, 2 concat(A|A2)
// EPI:   0 bias->fp16, 1 bias+scatter->fp16, 2 bias+GELU->fp16, 3 bias+residual->fp32
// ---------------------------------------------------------------------------
template<int AMODE, int EPI>
__global__ void __launch_bounds__(128, 2)
gemm_mma(const __half* __restrict__ A, const __half* __restrict__ A2, int lda,
         const uint32_t* __restrict__ Bp, int nbCols,
         const float* __restrict__ bias,
         void* __restrict__ Cov, int ldc,
         const int* __restrict__ scat, const float* __restrict__ res, int Kd)
{
    extern __shared__ uint32_t sm[];
    // A: 3 stages x 16384 B (swizzled). B: 3 stages x 4096 u32 (frag-major).
    uint32_t* sB = sm + 12288;
    uint32_t sAaddr;
    asm("{ .reg .u64 t; cvta.to.shared.u64 t, %1; cvt.u32.u64 %0, t; }"
        : "=r"(sAaddr) : "l"((const void*)sm));

    const int tid  = threadIdx.x;
    const int lane = tid & 31, wid = tid >> 5;
    const int brow = blockIdx.y * 128, bcol = blockIdx.x * 128;
    const int nblk = blockIdx.x;
    const int mf0 = (wid >> 1) * 4;
    const int nf0 = (wid & 1) * 8;

    float acc[4][8][4];
    #pragma unroll
    for (int a = 0; a < 4; a++)
        #pragma unroll
        for (int b = 0; b < 8; b++)
            #pragma unroll
            for (int r = 0; r < 4; r++) acc[a][b][r] = 0.f;

    const int ar0 = tid >> 3;
    const int ac  = tid & 7;
    auto CPA = [&](int c, int st) {
        const int k0 = c << 6;
        const __half* src;
        int kk;
        if (AMODE == 2) {
            src = (k0 < 512) ? A : A2;
            kk  = (k0 < 512) ? k0 : k0 - 512;
        } else { src = A; kk = k0; }
        #pragma unroll
        for (int i = 0; i < 8; i++) {
            const int row = ar0 + 16 * i;
            uint32_t dst = sAaddr + st * 16384 + row * 128 + ((ac ^ (row & 7)) << 4);
            cp16(dst, src + (size_t)(brow + row) * lda + kk + ac * 8);
        }
    };
    auto CPB = [&](int c, int st) {
        const uint32_t* src = Bp + ((size_t)(c * nbCols + nblk) << 12);
        uint32_t sBaddr = sAaddr + 49152;
        #pragma unroll
        for (int j = 0; j < 8; j++)
            cp16(sBaddr + (st * 4096 + (j << 9) + (tid << 2)) * 4,
                 src + (j << 9) + (tid << 2));
    };

    auto COMPUTE = [&](int st) {
        #pragma unroll
        for (int ks = 0; ks < 4; ks++) {
            uint32_t af[4][4], bf[8][2];
            #pragma unroll
            for (int mi = 0; mi < 4; mi++) {
                uint32_t addr = sAaddr + st * 16384
                              + ((mf0 + mi) * 16 + (lane & 15)) * 128
                              + ((((ks << 1) + (lane >> 4)) ^ (lane & 7)) << 4);
                asm volatile(
                    "ldmatrix.sync.aligned.m8n8.x4.shared.b16 {%0,%1,%2,%3}, [%4];"
                    : "=r"(af[mi][0]), "=r"(af[mi][1]), "=r"(af[mi][2]), "=r"(af[mi][3])
                    : "r"(addr));
            }
            #pragma unroll
            for (int ni = 0; ni < 8; ni++) {
                uint2 t = *(const uint2*)(sB + st * 4096 + ks * 1024 +
                                          (nf0 + ni) * 64 + lane * 2);
                bf[ni][0] = t.x; bf[ni][1] = t.y;
            }
            #pragma unroll
            for (int mi = 0; mi < 4; mi++)
                #pragma unroll
                for (int ni = 0; ni < 8; ni++)
                    mma_f16(acc[mi][ni], af[mi], bf[ni]);
        }
    };

    const int KC = Kd >> 6;
    CPA(0, 0); CPB(0, 0); CP_COMMIT();
    CPA(1, 1); CPB(1, 1); CP_COMMIT();
    int st = 0;
    for (int c = 0; c < KC; c++) {
        if (c + 1 < KC) CP_WAIT1(); else CP_WAIT0();
        __syncthreads();
        if (c + 2 < KC) {
            const int si = (st + 2 >= 3) ? st - 1 : st + 2;
            CPA(c + 2, si); CPB(c + 2, si); CP_COMMIT();
        }
        COMPUTE(st);
        st = (st + 1 == 3) ? 0 : st + 1;
    }

    // ---- epilogue: fused bias / gelu / scatter / residual
    const int wm = (wid >> 1) * 64, wn = (wid & 1) * 64;
    float*  Cf = (float*)Cov;
    __half* Ch = (__half*)Cov;
    #pragma unroll
    for (int mi = 0; mi < 4; mi++) {
        const int ra = brow + wm + mi * 16 + (lane >> 2);
        const int rb = ra + 8;
        const int ora = (EPI == 1) ? scat[ra] : ra;
        const int orb = (EPI == 1) ? scat[rb] : rb;
        #pragma unroll
        for (int ni = 0; ni < 8; ni++) {
            const int col = bcol + wn + ni * 8 + (lane & 3) * 2;
            const float b0 = bias[col], b1 = bias[col + 1];
            float v0 = acc[mi][ni][0] + b0, v1 = acc[mi][ni][1] + b1;
            float v2 = acc[mi][ni][2] + b0, v3 = acc[mi][ni][3] + b1;
            if (EPI == 2) {
                v0 = 0.5f * v0 * (1.f + erff(v0 * 0.7071067811865475f));
                v1 = 0.5f * v1 * (1.f + erff(v1 * 0.7071067811865475f));
                v2 = 0.5f * v2 * (1.f + erff(v2 * 0.7071067811865475f));
                v3 = 0.5f * v3 * (1.f + erff(v3 * 0.7071067811865475f));
            }
            if (EPI == 3) {
                v0 += res[(size_t)ra * ldc + col];
                v1 += res[(size_t)ra * ldc + col + 1];
                v2 += res[(size_t)rb * ldc + col];
                v3 += res[(size_t)rb * ldc + col + 1];
                *(float2*)(Cf + (size_t)ra * ldc + col) = make_float2(v0, v1);
                *(float2*)(Cf + (size_t)rb * ldc + col) = make_float2(v2, v3);
            } else {
                *(uint32_t*)(Ch + (size_t)ora * ldc + col) = pack2h(v0, v1);
                *(uint32_t*)(Ch + (size_t)orb * ldc + col) = pack2h(v2, v3);
            }
        }
    }
}

// ---------------------------------------------------------------------------
// Tensor-core per-(patch, head, stream) attention (R12, unchanged).
// ---------------------------------------------------------------------------
#define AST 72    // q/k/v smem stride in halves (144 B rows, conflict-free)
#define SCST 52   // score fp32 stride
#define PST 56    // prob fp16 stride (112 B rows)
__global__ void __launch_bounds__(128)
patch_attn_kernel(const __half* __restrict__ qf,
                  const __half* __restrict__ qkv_s,
                  const __half* __restrict__ qkv_b,
                  const int* __restrict__ order,
                  __half* __restrict__ attn_s,
                  __half* __restrict__ attn_b)
{
    const int p = blockIdx.x >> 3;
    const int h = blockIdx.x & 7;
    const __half* qkv = blockIdx.y ? qkv_b : qkv_s;
    __half* out = blockIdx.y ? attn_b : attn_s;

    __shared__ __half Qh[48 * AST];
    __shared__ __half Kh[48 * AST];
    __shared__ __half Vh[48 * AST];
    __shared__ float  scs[48 * SCST];
    __shared__ __half Ph[48 * PST];

    const int tid = threadIdx.x, lane = tid & 31, wid = tid >> 5;
    const size_t rowbase = (size_t)p * KK;
    const uint32_t qa = smem_u32(Qh), ka = smem_u32(Kh), va = smem_u32(Vh);
    const uint32_t pa = smem_u32(Ph);

    #pragma unroll
    for (int i = 0; i < 9; i++) {
        const int idx = i * 128 + tid;
        const int row = idx >> 3, c = idx & 7;
        const int seg = row / 48;            // 0=q, 1=k, 2=v
        const int r = row - seg * 48;
        const __half* src = (seg == 0)
            ? qf + (rowbase + r) * CC + h * DD
            : qkv + (rowbase + r) * C3 + (seg == 1 ? 512 : 1024) + h * DD;
        const uint32_t base = (seg == 0) ? qa : (seg == 1) ? ka : va;
        cp16(base + r * (AST * 2) + c * 16, src + c * 8);
    }
    CP_COMMIT();
    CP_WAIT0();
    __syncthreads();

    for (int t = wid; t < 18; t += 4) {
        const int mf = t / 6, nf = t % 6;
        float d4[4] = { 0.f, 0.f, 0.f, 0.f };
        #pragma unroll
        for (int ks = 0; ks < 4; ks++) {
            uint32_t a[4], b[2];
            uint32_t aaddr = qa + ((mf * 16 + (lane & 15)) * AST
                                   + ks * 16 + ((lane >> 4) << 3)) * 2;
            asm volatile("ldmatrix.sync.aligned.m8n8.x4.shared.b16 {%0,%1,%2,%3}, [%4];"
                         : "=r"(a[0]), "=r"(a[1]), "=r"(a[2]), "=r"(a[3]) : "r"(aaddr));
            uint32_t baddr = ka + ((nf * 8 + (lane & 7)) * AST
                                   + ks * 16 + (((lane >> 3) & 1) << 3)) * 2;
            asm volatile("ldmatrix.sync.aligned.m8n8.x2.shared.b16 {%0,%1}, [%2];"
                         : "=r"(b[0]), "=r"(b[1]) : "r"(baddr));
            mma_f16(d4, a, b);
        }
        const int r0 = mf * 16 + (lane >> 2), c0 = nf * 8 + (lane & 3) * 2;
        scs[r0 * SCST + c0]       = d4[0] * 0.125f;
        scs[r0 * SCST + c0 + 1]   = d4[1] * 0.125f;
        scs[(r0 + 8) * SCST + c0]     = d4[2] * 0.125f;
        scs[(r0 + 8) * SCST + c0 + 1] = d4[3] * 0.125f;
    }
    __syncthreads();

    for (int r = wid; r < 48; r += 4) {
        float x0 = scs[r * SCST + lane];
        float x1 = (lane < 16) ? scs[r * SCST + 32 + lane] : -1e30f;
        float mx = fmaxf(x0, x1);
        #pragma unroll
        for (int o = 16; o > 0; o >>= 1) mx = fmaxf(mx, __shfl_xor_sync(0xffffffffu, mx, o));
        float e0 = expf(x0 - mx);
        float e1 = (lane < 16) ? expf(x1 - mx) : 0.f;
        float s = e0 + e1;
        #pragma unroll
        for (int o = 16; o > 0; o >>= 1) s += __shfl_xor_sync(0xffffffffu, s, o);
        float inv = 1.f / s;
        Ph[r * PST + lane] = __float2half(e0 * inv);
        if (lane < 16) Ph[r * PST + 32 + lane] = __float2half(e1 * inv);
    }
    __syncthreads();

    for (int t = wid; t < 24; t += 4) {
        const int mf = t >> 3, nf = t & 7;
        float d4[4] = { 0.f, 0.f, 0.f, 0.f };
        #pragma unroll
        for (int ks = 0; ks < 3; ks++) {
            uint32_t a[4], b[2];
            uint32_t aaddr = pa + ((mf * 16 + (lane & 15)) * PST
                                   + ks * 16 + ((lane >> 4) << 3)) * 2;
            asm volatile("ldmatrix.sync.aligned.m8n8.x4.shared.b16 {%0,%1,%2,%3}, [%4];"
                         : "=r"(a[0]), "=r"(a[1]), "=r"(a[2]), "=r"(a[3]) : "r"(aaddr));
            uint32_t baddr = va + ((ks * 16 + (((lane >> 3) & 1) << 3) + (lane & 7)) * AST
                                   + nf * 8) * 2;
            asm volatile("ldmatrix.sync.aligned.m8n8.x2.trans.shared.b16 {%0,%1}, [%2];"
                         : "=r"(b[0]), "=r"(b[1]) : "r"(baddr));
            mma_f16(d4, a, b);
        }
        const int r0 = mf * 16 + (lane >> 2), c0 = nf * 8 + (lane & 3) * 2;
        const int g0 = order[rowbase + r0];
        const int g1 = order[rowbase + r0 + 8];
        *(uint32_t*)(out + (size_t)g0 * CC + h * DD + c0) = pack2h(d4[0], d4[1]);
        *(uint32_t*)(out + (size_t)g1 * CC + h * DD + c0) = pack2h(d4[2], d4[3]);
    }
}

// ---------------------------------------------------------------------------
// Host launch (f2 GEMM at launch index 5 so ncu -s 5 profiles a GEMM)
// ---------------------------------------------------------------------------
extern "C" void kernel_launch(void* const* d_in, const int* in_sizes, int n_in,
                              void* d_out, int out_size)
{
    const float* sem_feat = (const float*)d_in[0];
    const float* bnd_feat = (const float*)d_in[1];
    const int*   order    = (const int*)d_in[2];
    const int*   inverse  = (const int*)d_in[3];
    const float* g_sem    = (const float*)d_in[4];
    const float* b_sem    = (const float*)d_in[5];
    const float* g_bnd    = (const float*)d_in[6];
    const float* b_bnd    = (const float*)d_in[7];
    const float* w_qkv_s  = (const float*)d_in[8];
    const float* b_qkv_s  = (const float*)d_in[9];
    const float* w_qkv_b  = (const float*)d_in[10];
    const float* b_qkv_b  = (const float*)d_in[11];
    const float* w_f1     = (const float*)d_in[12];
    const float* b_f1     = (const float*)d_in[13];
    const float* w_f2     = (const float*)d_in[14];
    const float* b_f2     = (const float*)d_in[15];
    const float* w_os     = (const float*)d_in[16];
    const float* b_os     = (const float*)d_in[17];
    const float* w_ob     = (const float*)d_in[18];
    const float* b_ob     = (const float*)d_in[19];
    float* out = (float*)d_out;

    __half *xln_s, *xln_b, *qkv_s, *qkv_b, *h1, *qf, *attn_s, *attn_b;
    uint32_t *wp_qs, *wp_qb, *wp_f1, *wp_f2, *wp_os, *wp_ob;
    cudaGetSymbolAddress((void**)&xln_s,  g_xln_s);
    cudaGetSymbolAddress((void**)&xln_b,  g_xln_b);
    cudaGetSymbolAddress((void**)&qkv_s,  g_qkv_s);
    cudaGetSymbolAddress((void**)&qkv_b,  g_qkv_b);
    cudaGetSymbolAddress((void**)&h1,     g_h1);
    cudaGetSymbolAddress((void**)&qf,     g_qf);
    cudaGetSymbolAddress((void**)&attn_s, g_attn_s);
    cudaGetSymbolAddress((void**)&attn_b, g_attn_b);
    cudaGetSymbolAddress((void**)&wp_qs,  g_wp_qs);
    cudaGetSymbolAddress((void**)&wp_qb,  g_wp_qb);
    cudaGetSymbolAddress((void**)&wp_f1,  g_wp_f1);
    cudaGetSymbolAddress((void**)&wp_f2,  g_wp_f2);
    cudaGetSymbolAddress((void**)&wp_os,  g_wp_os);
    cudaGetSymbolAddress((void**)&wp_ob,  g_wp_ob);

    const int SMEM_DYN = 98304;   // 3 stages x (A 16KB + B 16KB)
    cudaFuncSetAttribute(gemm_mma<0, 1>, cudaFuncAttributeMaxDynamicSharedMemorySize, SMEM_DYN);
    cudaFuncSetAttribute(gemm_mma<2, 2>, cudaFuncAttributeMaxDynamicSharedMemorySize, SMEM_DYN);
    cudaFuncSetAttribute(gemm_mma<0, 0>, cudaFuncAttributeMaxDynamicSharedMemorySize, SMEM_DYN);
    cudaFuncSetAttribute(gemm_mma<0, 3>, cudaFuncAttributeMaxDynamicSharedMemorySize, SMEM_DYN);

    // 0: pack all weights, 1: LN both streams
    prep_all<<<7168, 256>>>(w_qkv_s, w_qkv_b, w_f1, w_f2, w_os, w_ob,
                            wp_qs, wp_qb, wp_f1, wp_f2, wp_os, wp_ob);
    ln_fp16<<<dim3(NN / 8, 2), 256>>>(sem_feat, bnd_feat, g_sem, b_sem,
                                      g_bnd, b_bnd, xln_s, xln_b);

    // 2-3: QKV GEMMs (scatter by inverse, fp16 out)
    gemm_mma<0, 1><<<dim3(C3 / 128, NN / 128), 128, SMEM_DYN>>>(
        xln_s, nullptr, CC, wp_qs, C3 / 128, b_qkv_s, qkv_s, C3,
        inverse, nullptr, CC);
    gemm_mma<0, 1><<<dim3(C3 / 128, NN / 128), 128, SMEM_DYN>>>(
        xln_b, nullptr, CC, wp_qb, C3 / 128, b_qkv_b, qkv_b, C3,
        inverse, nullptr, CC);

    // 4: fusion MLP layer 1 (concat + GELU)
    gemm_mma<2, 2><<<dim3(C2 / 128, NN / 128), 128, SMEM_DYN>>>(
        qkv_s, qkv_b, C3, wp_f1, C2 / 128, b_f1, h1, C2,
        nullptr, nullptr, C2);
    // 5: fusion MLP layer 2 (ncu target)
    gemm_mma<0, 0><<<dim3(CC / 128, NN / 128), 128, SMEM_DYN>>>(
        h1, nullptr, C2, wp_f2, CC / 128, b_f2, qf, CC,
        nullptr, nullptr, C2);

    // 6: attention, both streams
    patch_attn_kernel<<<dim3(PP * HH, 2), 128>>>(qf, qkv_s, qkv_b, order,
                                                 attn_s, attn_b);

    // 7-8: output projections + residual
    gemm_mma<0, 3><<<dim3(CC / 128, NN / 128), 128, SMEM_DYN>>>(
        attn_s, nullptr, CC, wp_os, CC / 128, b_os, out, CC,
        nullptr, sem_feat, CC);
    gemm_mma<0, 3><<<dim3(CC / 128, NN / 128), 128, SMEM_DYN>>>(
        attn_b, nullptr, CC, wp_ob, CC / 128, b_ob, out + (size_t)NN * CC, CC,
        nullptr, bnd_feat, CC);
}

// round 15
// speedup vs baseline: 8.0625x; 1.0144x over previous
#include <cuda_runtime.h>
#include <cuda_fp16.h>
#include <math.h>
#include <stdint.h>

// Problem constants
#define NN 49152
#define CC 512
#define HH 8
#define KK 48
#define DD 64
#define PP 1024            // NN / KK
#define C3 1536            // 3*C
#define C2 1024            // 2*C

// ---------------------------------------------------------------------------
// Scratch (device globals; no runtime allocation). Intermediates are fp16.
// ---------------------------------------------------------------------------
__device__ __half g_xln_s[(size_t)NN * CC];   // LN-transformed inputs, fp16
__device__ __half g_xln_b[(size_t)NN * CC];
__device__ __half g_qkv_s[(size_t)NN * C3];
__device__ __half g_qkv_b[(size_t)NN * C3];
__device__ __half g_h1[(size_t)NN * C2];
__device__ __half g_qf[(size_t)NN * CC];
__device__ __half g_attn_s[(size_t)NN * CC];
__device__ __half g_attn_b[(size_t)NN * CC];
// Packed fp16 weights, fragment-major, grouped by 64-k chunk:
// u32 index = ((chunk*(N/128) + nblk)*4 + k16step)*1024 + nfrag*64 + lane*2 + reg
__device__ uint32_t g_wp_qs[(size_t)(CC / 2) * C3];
__device__ uint32_t g_wp_qb[(size_t)(CC / 2) * C3];
__device__ uint32_t g_wp_f1[(size_t)(C2 / 2) * C2];
__device__ uint32_t g_wp_f2[(size_t)(C2 / 2) * CC];
__device__ uint32_t g_wp_os[(size_t)(CC / 2) * CC];
__device__ uint32_t g_wp_ob[(size_t)(CC / 2) * CC];

// ---------------------------------------------------------------------------
// Helpers (base-target PTX, sm_80+ only)
// ---------------------------------------------------------------------------
__device__ __forceinline__ uint32_t pack2h(float a, float b) {
    __half2 h = __floats2half2_rn(a, b);
    return *reinterpret_cast<uint32_t*>(&h);
}

__device__ __forceinline__ uint32_t smem_u32(const void* p) {
    uint32_t a;
    asm("{ .reg .u64 t; cvta.to.shared.u64 t, %1; cvt.u32.u64 %0, t; }"
        : "=r"(a) : "l"(p));
    return a;
}

__device__ __forceinline__ void mma_f16(float* d, const uint32_t* a, const uint32_t* b) {
    asm volatile(
        "mma.sync.aligned.m16n8k16.row.col.f32.f16.f16.f32 "
        "{%0,%1,%2,%3}, {%4,%5,%6,%7}, {%8,%9}, {%0,%1,%2,%3};"
        : "+f"(d[0]), "+f"(d[1]), "+f"(d[2]), "+f"(d[3])
        : "r"(a[0]), "r"(a[1]), "r"(a[2]), "r"(a[3]), "r"(b[0]), "r"(b[1]));
}

__device__ __forceinline__ void cp16(uint32_t saddr, const void* gptr) {
    asm volatile("cp.async.cg.shared.global [%0], [%1], 16;" :: "r"(saddr), "l"(gptr));
}
#define CP_COMMIT() asm volatile("cp.async.commit_group;" ::: "memory")
#define CP_WAIT0()  asm volatile("cp.async.wait_group 0;" ::: "memory")
#define CP_WAIT1()  asm volatile("cp.async.wait_group 1;" ::: "memory")

// ---------------------------------------------------------------------------
// Weight pack body: w [K,N] fp32 -> fp16 pairs, fragment-major, 64-k chunks
// ---------------------------------------------------------------------------
__device__ __forceinline__ void prep_body(const float* __restrict__ w,
                                          uint32_t* __restrict__ out,
                                          int Kd, int Nd, int idx)
{
    int n  = idx % Nd;
    int k  = (idx / Nd) << 1;                      // even k
    float v0 = w[(size_t)k * Nd + n];
    float v1 = w[(size_t)(k + 1) * Nd + n];
    int cc   = k >> 6;                             // 64-k chunk
    int step = (k >> 4) & 3;
    int nblk = n >> 7, nn = n & 127;
    int nfrag = nn >> 3;
    int lane  = (nn & 7) * 4 + ((k & 7) >> 1);
    int reg   = (k & 15) >> 3;
    size_t o = ((size_t)(cc * (Nd >> 7) + nblk) * 4 + step) * 1024
             + nfrag * 64 + lane * 2 + reg;
    out[o] = pack2h(v0, v1);
}

// One launch packs all 6 weight matrices (segment if-chain).
__global__ void __launch_bounds__(256)
prep_all(const float* __restrict__ w0, const float* __restrict__ w1,
         const float* __restrict__ w2, const float* __restrict__ w3,
         const float* __restrict__ w4, const float* __restrict__ w5,
         uint32_t* __restrict__ o0, uint32_t* __restrict__ o1,
         uint32_t* __restrict__ o2, uint32_t* __restrict__ o3,
         uint32_t* __restrict__ o4, uint32_t* __restrict__ o5)
{
    int idx = blockIdx.x * 256 + threadIdx.x;
    if (idx < 393216)        prep_body(w0, o0, 512, 1536, idx);
    else if (idx < 786432)   prep_body(w1, o1, 512, 1536, idx - 393216);
    else if (idx < 1310720)  prep_body(w2, o2, 1024, 1024, idx - 786432);
    else if (idx < 1572864)  prep_body(w3, o3, 1024, 512, idx - 1310720);
    else if (idx < 1703936)  prep_body(w4, o4, 512, 512, idx - 1572864);
    else if (idx < 1835008)  prep_body(w5, o5, 512, 512, idx - 1703936);
}

// ---------------------------------------------------------------------------
// Fused LayerNorm (both streams via grid.y): fp32 in -> fp16 out, warp/row
// ---------------------------------------------------------------------------
__global__ void __launch_bounds__(256)
ln_fp16(const float* __restrict__ x0, const float* __restrict__ x1,
        const float* __restrict__ g0, const float* __restrict__ b0,
        const float* __restrict__ g1, const float* __restrict__ b1,
        __half* __restrict__ o0, __half* __restrict__ o1)
{
    const float* x = blockIdx.y ? x1 : x0;
    const float* g = blockIdx.y ? g1 : g0;
    const float* b = blockIdx.y ? b1 : b0;
    __half* o = blockIdx.y ? o1 : o0;

    const int row  = blockIdx.x * 8 + (threadIdx.x >> 5);
    const int lane = threadIdx.x & 31;
    const float* xr = x + (size_t)row * CC;
    float4 v[4];
    float s = 0.f, sq = 0.f;
    #pragma unroll
    for (int j = 0; j < 4; j++) {
        v[j] = *(const float4*)(xr + lane * 4 + 128 * j);
        s  += v[j].x + v[j].y + v[j].z + v[j].w;
        sq += v[j].x * v[j].x + v[j].y * v[j].y + v[j].z * v[j].z + v[j].w * v[j].w;
    }
    #pragma unroll
    for (int off = 16; off > 0; off >>= 1) {
        s  += __shfl_xor_sync(0xffffffffu, s, off);
        sq += __shfl_xor_sync(0xffffffffu, sq, off);
    }
    const float m = s * (1.f / CC);
    const float r = rsqrtf(sq * (1.f / CC) - m * m + 1e-5f);
    __half* orow = o + (size_t)row * CC;
    #pragma unroll
    for (int j = 0; j < 4; j++) {
        const int col = lane * 4 + 128 * j;
        float4 g4 = *(const float4*)(g + col);
        float4 b4 = *(const float4*)(b + col);
        uint2 w;
        w.x = pack2h((v[j].x - m) * r * g4.x + b4.x, (v[j].y - m) * r * g4.y + b4.y);
        w.y = pack2h((v[j].z - m) * r * g4.z + b4.z, (v[j].w - m) * r * g4.w + b4.w);
        *(uint2*)(orow + col) = w;
    }
}

// ---------------------------------------------------------------------------
// Fully-async FP16 mma.sync GEMM, 3-stage cp.async, cp-issue interleaved into
// the middle of compute. Optional dual-problem mode via blockIdx.z (grid.z=2).
// C[128x128] = op(A)[128xK] @ W + epilogue. 128 threads (4 warps, 2x2).
// AMODE: 0 plain fp16, 2 concat(A|A2)
// EPI:   0 bias->fp16, 1 bias+scatter->fp16, 2 bias+GELU->fp16, 3 bias+residual->fp32
// ---------------------------------------------------------------------------
template<int AMODE, int EPI>
__global__ void __launch_bounds__(128, 2)
gemm_mma(const __half* __restrict__ A0, const __half* __restrict__ A1,
         const __half* __restrict__ A2, int lda,
         const uint32_t* __restrict__ Bp0, const uint32_t* __restrict__ Bp1,
         int nbCols,
         const float* __restrict__ bias0, const float* __restrict__ bias1,
         void* __restrict__ Cov0, void* __restrict__ Cov1, int ldc,
         const int* __restrict__ scat,
         const float* __restrict__ res0, const float* __restrict__ res1,
         int Kd)
{
    extern __shared__ uint32_t sm[];
    // A: 3 stages x 16384 B (swizzled). B: 3 stages x 4096 u32 (frag-major).
    uint32_t* sB = sm + 12288;
    uint32_t sAaddr;
    asm("{ .reg .u64 t; cvta.to.shared.u64 t, %1; cvt.u32.u64 %0, t; }"
        : "=r"(sAaddr) : "l"((const void*)sm));

    const int z = blockIdx.z;
    const __half*    A    = z ? A1 : A0;
    const uint32_t*  Bp   = z ? Bp1 : Bp0;
    const float*     bias = z ? bias1 : bias0;
    void*            Cov  = z ? Cov1 : Cov0;
    const float*     res  = z ? res1 : res0;

    const int tid  = threadIdx.x;
    const int lane = tid & 31, wid = tid >> 5;
    const int brow = blockIdx.y * 128, bcol = blockIdx.x * 128;
    const int nblk = blockIdx.x;
    const int mf0 = (wid >> 1) * 4;
    const int nf0 = (wid & 1) * 8;

    float acc[4][8][4];
    #pragma unroll
    for (int a = 0; a < 4; a++)
        #pragma unroll
        for (int b = 0; b < 8; b++)
            #pragma unroll
            for (int r = 0; r < 4; r++) acc[a][b][r] = 0.f;

    const int ar0 = tid >> 3;
    const int ac  = tid & 7;
    auto CPA = [&](int c, int st) {
        const int k0 = c << 6;
        const __half* src;
        int kk;
        if (AMODE == 2) {
            src = (k0 < 512) ? A : A2;
            kk  = (k0 < 512) ? k0 : k0 - 512;
        } else { src = A; kk = k0; }
        #pragma unroll
        for (int i = 0; i < 8; i++) {
            const int row = ar0 + 16 * i;
            uint32_t dst = sAaddr + st * 16384 + row * 128 + ((ac ^ (row & 7)) << 4);
            cp16(dst, src + (size_t)(brow + row) * lda + kk + ac * 8);
        }
    };
    auto CPB = [&](int c, int st) {
        const uint32_t* src = Bp + ((size_t)(c * nbCols + nblk) << 12);
        uint32_t sBaddr = sAaddr + 49152;
        #pragma unroll
        for (int j = 0; j < 8; j++)
            cp16(sBaddr + (st * 4096 + (j << 9) + (tid << 2)) * 4,
                 src + (j << 9) + (tid << 2));
    };

    // two ks-steps of compute (half a chunk)
    auto COMPUTE2 = [&](int st, int ksb) {
        #pragma unroll
        for (int ks = ksb; ks < ksb + 2; ks++) {
            uint32_t af[4][4], bf[8][2];
            #pragma unroll
            for (int mi = 0; mi < 4; mi++) {
                uint32_t addr = sAaddr + st * 16384
                              + ((mf0 + mi) * 16 + (lane & 15)) * 128
                              + ((((ks << 1) + (lane >> 4)) ^ (lane & 7)) << 4);
                asm volatile(
                    "ldmatrix.sync.aligned.m8n8.x4.shared.b16 {%0,%1,%2,%3}, [%4];"
                    : "=r"(af[mi][0]), "=r"(af[mi][1]), "=r"(af[mi][2]), "=r"(af[mi][3])
                    : "r"(addr));
            }
            #pragma unroll
            for (int ni = 0; ni < 8; ni++) {
                uint2 t = *(const uint2*)(sB + st * 4096 + ks * 1024 +
                                          (nf0 + ni) * 64 + lane * 2);
                bf[ni][0] = t.x; bf[ni][1] = t.y;
            }
            #pragma unroll
            for (int mi = 0; mi < 4; mi++)
                #pragma unroll
                for (int ni = 0; ni < 8; ni++)
                    mma_f16(acc[mi][ni], af[mi], bf[ni]);
        }
    };

    const int KC = Kd >> 6;
    CPA(0, 0); CPB(0, 0); CP_COMMIT();
    CPA(1, 1); CPB(1, 1); CP_COMMIT();
    int st = 0;
    for (int c = 0; c < KC; c++) {
        if (c + 1 < KC) CP_WAIT1(); else CP_WAIT0();
        __syncthreads();
        COMPUTE2(st, 0);
        if (c + 2 < KC) {
            // stage (st+2)%3 == stage of chunk c-1; safe after this barrier
            const int si = (st + 2 >= 3) ? st - 1 : st + 2;
            CPA(c + 2, si); CPB(c + 2, si); CP_COMMIT();
        }
        COMPUTE2(st, 2);
        st = (st + 1 == 3) ? 0 : st + 1;
    }

    // ---- epilogue: fused bias / gelu / scatter / residual
    const int wm = (wid >> 1) * 64, wn = (wid & 1) * 64;
    float*  Cf = (float*)Cov;
    __half* Ch = (__half*)Cov;
    #pragma unroll
    for (int mi = 0; mi < 4; mi++) {
        const int ra = brow + wm + mi * 16 + (lane >> 2);
        const int rb = ra + 8;
        const int ora = (EPI == 1) ? scat[ra] : ra;
        const int orb = (EPI == 1) ? scat[rb] : rb;
        #pragma unroll
        for (int ni = 0; ni < 8; ni++) {
            const int col = bcol + wn + ni * 8 + (lane & 3) * 2;
            const float b0 = bias[col], b1 = bias[col + 1];
            float v0 = acc[mi][ni][0] + b0, v1 = acc[mi][ni][1] + b1;
            float v2 = acc[mi][ni][2] + b0, v3 = acc[mi][ni][3] + b1;
            if (EPI == 2) {
                v0 = 0.5f * v0 * (1.f + erff(v0 * 0.7071067811865475f));
                v1 = 0.5f * v1 * (1.f + erff(v1 * 0.7071067811865475f));
                v2 = 0.5f * v2 * (1.f + erff(v2 * 0.7071067811865475f));
                v3 = 0.5f * v3 * (1.f + erff(v3 * 0.7071067811865475f));
            }
            if (EPI == 3) {
                v0 += res[(size_t)ra * ldc + col];
                v1 += res[(size_t)ra * ldc + col + 1];
                v2 += res[(size_t)rb * ldc + col];
                v3 += res[(size_t)rb * ldc + col + 1];
                *(float2*)(Cf + (size_t)ra * ldc + col) = make_float2(v0, v1);
                *(float2*)(Cf + (size_t)rb * ldc + col) = make_float2(v2, v3);
            } else {
                *(uint32_t*)(Ch + (size_t)ora * ldc + col) = pack2h(v0, v1);
                *(uint32_t*)(Ch + (size_t)orb * ldc + col) = pack2h(v2, v3);
            }
        }
    }
}

// ---------------------------------------------------------------------------
// Tensor-core per-(patch, head, stream) attention (R12, unchanged).
// ---------------------------------------------------------------------------
#define AST 72    // q/k/v smem stride in halves (144 B rows, conflict-free)
#define SCST 52   // score fp32 stride
#define PST 56    // prob fp16 stride (112 B rows)
__global__ void __launch_bounds__(128)
patch_attn_kernel(const __half* __restrict__ qf,
                  const __half* __restrict__ qkv_s,
                  const __half* __restrict__ qkv_b,
                  const int* __restrict__ order,
                  __half* __restrict__ attn_s,
                  __half* __restrict__ attn_b)
{
    const int p = blockIdx.x >> 3;
    const int h = blockIdx.x & 7;
    const __half* qkv = blockIdx.y ? qkv_b : qkv_s;
    __half* out = blockIdx.y ? attn_b : attn_s;

    __shared__ __half Qh[48 * AST];
    __shared__ __half Kh[48 * AST];
    __shared__ __half Vh[48 * AST];
    __shared__ float  scs[48 * SCST];
    __shared__ __half Ph[48 * PST];

    const int tid = threadIdx.x, lane = tid & 31, wid = tid >> 5;
    const size_t rowbase = (size_t)p * KK;
    const uint32_t qa = smem_u32(Qh), ka = smem_u32(Kh), va = smem_u32(Vh);
    const uint32_t pa = smem_u32(Ph);

    #pragma unroll
    for (int i = 0; i < 9; i++) {
        const int idx = i * 128 + tid;
        const int row = idx >> 3, c = idx & 7;
        const int seg = row / 48;            // 0=q, 1=k, 2=v
        const int r = row - seg * 48;
        const __half* src = (seg == 0)
            ? qf + (rowbase + r) * CC + h * DD
            : qkv + (rowbase + r) * C3 + (seg == 1 ? 512 : 1024) + h * DD;
        const uint32_t base = (seg == 0) ? qa : (seg == 1) ? ka : va;
        cp16(base + r * (AST * 2) + c * 16, src + c * 8);
    }
    CP_COMMIT();
    CP_WAIT0();
    __syncthreads();

    for (int t = wid; t < 18; t += 4) {
        const int mf = t / 6, nf = t % 6;
        float d4[4] = { 0.f, 0.f, 0.f, 0.f };
        #pragma unroll
        for (int ks = 0; ks < 4; ks++) {
            uint32_t a[4], b[2];
            uint32_t aaddr = qa + ((mf * 16 + (lane & 15)) * AST
                                   + ks * 16 + ((lane >> 4) << 3)) * 2;
            asm volatile("ldmatrix.sync.aligned.m8n8.x4.shared.b16 {%0,%1,%2,%3}, [%4];"
                         : "=r"(a[0]), "=r"(a[1]), "=r"(a[2]), "=r"(a[3]) : "r"(aaddr));
            uint32_t baddr = ka + ((nf * 8 + (lane & 7)) * AST
                                   + ks * 16 + (((lane >> 3) & 1) << 3)) * 2;
            asm volatile("ldmatrix.sync.aligned.m8n8.x2.shared.b16 {%0,%1}, [%2];"
                         : "=r"(b[0]), "=r"(b[1]) : "r"(baddr));
            mma_f16(d4, a, b);
        }
        const int r0 = mf * 16 + (lane >> 2), c0 = nf * 8 + (lane & 3) * 2;
        scs[r0 * SCST + c0]       = d4[0] * 0.125f;
        scs[r0 * SCST + c0 + 1]   = d4[1] * 0.125f;
        scs[(r0 + 8) * SCST + c0]     = d4[2] * 0.125f;
        scs[(r0 + 8) * SCST + c0 + 1] = d4[3] * 0.125f;
    }
    __syncthreads();

    for (int r = wid; r < 48; r += 4) {
        float x0 = scs[r * SCST + lane];
        float x1 = (lane < 16) ? scs[r * SCST + 32 + lane] : -1e30f;
        float mx = fmaxf(x0, x1);
        #pragma unroll
        for (int o = 16; o > 0; o >>= 1) mx = fmaxf(mx, __shfl_xor_sync(0xffffffffu, mx, o));
        float e0 = expf(x0 - mx);
        float e1 = (lane < 16) ? expf(x1 - mx) : 0.f;
        float s = e0 + e1;
        #pragma unroll
        for (int o = 16; o > 0; o >>= 1) s += __shfl_xor_sync(0xffffffffu, s, o);
        float inv = 1.f / s;
        Ph[r * PST + lane] = __float2half(e0 * inv);
        if (lane < 16) Ph[r * PST + 32 + lane] = __float2half(e1 * inv);
    }
    __syncthreads();

    for (int t = wid; t < 24; t += 4) {
        const int mf = t >> 3, nf = t & 7;
        float d4[4] = { 0.f, 0.f, 0.f, 0.f };
        #pragma unroll
        for (int ks = 0; ks < 3; ks++) {
            uint32_t a[4], b[2];
            uint32_t aaddr = pa + ((mf * 16 + (lane & 15)) * PST
                                   + ks * 16 + ((lane >> 4) << 3)) * 2;
            asm volatile("ldmatrix.sync.aligned.m8n8.x4.shared.b16 {%0,%1,%2,%3}, [%4];"
                         : "=r"(a[0]), "=r"(a[1]), "=r"(a[2]), "=r"(a[3]) : "r"(aaddr));
            uint32_t baddr = va + ((ks * 16 + (((lane >> 3) & 1) << 3) + (lane & 7)) * AST
                                   + nf * 8) * 2;
            asm volatile("ldmatrix.sync.aligned.m8n8.x2.trans.shared.b16 {%0,%1}, [%2];"
                         : "=r"(b[0]), "=r"(b[1]) : "r"(baddr));
            mma_f16(d4, a, b);
        }
        const int r0 = mf * 16 + (lane >> 2), c0 = nf * 8 + (lane & 3) * 2;
        const int g0 = order[rowbase + r0];
        const int g1 = order[rowbase + r0 + 8];
        *(uint32_t*)(out + (size_t)g0 * CC + h * DD + c0) = pack2h(d4[0], d4[1]);
        *(uint32_t*)(out + (size_t)g1 * CC + h * DD + c0) = pack2h(d4[2], d4[3]);
    }
}

// ---------------------------------------------------------------------------
// Host launch
// ---------------------------------------------------------------------------
extern "C" void kernel_launch(void* const* d_in, const int* in_sizes, int n_in,
                              void* d_out, int out_size)
{
    const float* sem_feat = (const float*)d_in[0];
    const float* bnd_feat = (const float*)d_in[1];
    const int*   order    = (const int*)d_in[2];
    const int*   inverse  = (const int*)d_in[3];
    const float* g_sem    = (const float*)d_in[4];
    const float* b_sem    = (const float*)d_in[5];
    const float* g_bnd    = (const float*)d_in[6];
    const float* b_bnd    = (const float*)d_in[7];
    const float* w_qkv_s  = (const float*)d_in[8];
    const float* b_qkv_s  = (const float*)d_in[9];
    const float* w_qkv_b  = (const float*)d_in[10];
    const float* b_qkv_b  = (const float*)d_in[11];
    const float* w_f1     = (const float*)d_in[12];
    const float* b_f1     = (const float*)d_in[13];
    const float* w_f2     = (const float*)d_in[14];
    const float* b_f2     = (const float*)d_in[15];
    const float* w_os     = (const float*)d_in[16];
    const float* b_os     = (const float*)d_in[17];
    const float* w_ob     = (const float*)d_in[18];
    const float* b_ob     = (const float*)d_in[19];
    float* out = (float*)d_out;

    __half *xln_s, *xln_b, *qkv_s, *qkv_b, *h1, *qf, *attn_s, *attn_b;
    uint32_t *wp_qs, *wp_qb, *wp_f1, *wp_f2, *wp_os, *wp_ob;
    cudaGetSymbolAddress((void**)&xln_s,  g_xln_s);
    cudaGetSymbolAddress((void**)&xln_b,  g_xln_b);
    cudaGetSymbolAddress((void**)&qkv_s,  g_qkv_s);
    cudaGetSymbolAddress((void**)&qkv_b,  g_qkv_b);
    cudaGetSymbolAddress((void**)&h1,     g_h1);
    cudaGetSymbolAddress((void**)&qf,     g_qf);
    cudaGetSymbolAddress((void**)&attn_s, g_attn_s);
    cudaGetSymbolAddress((void**)&attn_b, g_attn_b);
    cudaGetSymbolAddress((void**)&wp_qs,  g_wp_qs);
    cudaGetSymbolAddress((void**)&wp_qb,  g_wp_qb);
    cudaGetSymbolAddress((void**)&wp_f1,  g_wp_f1);
    cudaGetSymbolAddress((void**)&wp_f2,  g_wp_f2);
    cudaGetSymbolAddress((void**)&wp_os,  g_wp_os);
    cudaGetSymbolAddress((void**)&wp_ob,  g_wp_ob);

    const int SMEM_DYN = 98304;   // 3 stages x (A 16KB + B 16KB)
    cudaFuncSetAttribute(gemm_mma<0, 1>, cudaFuncAttributeMaxDynamicSharedMemorySize, SMEM_DYN);
    cudaFuncSetAttribute(gemm_mma<2, 2>, cudaFuncAttributeMaxDynamicSharedMemorySize, SMEM_DYN);
    cudaFuncSetAttribute(gemm_mma<0, 0>, cudaFuncAttributeMaxDynamicSharedMemorySize, SMEM_DYN);
    cudaFuncSetAttribute(gemm_mma<0, 3>, cudaFuncAttributeMaxDynamicSharedMemorySize, SMEM_DYN);

    // 0: pack all weights, 1: LN both streams
    prep_all<<<7168, 256>>>(w_qkv_s, w_qkv_b, w_f1, w_f2, w_os, w_ob,
                            wp_qs, wp_qb, wp_f1, wp_f2, wp_os, wp_ob);
    ln_fp16<<<dim3(NN / 8, 2), 256>>>(sem_feat, bnd_feat, g_sem, b_sem,
                                      g_bnd, b_bnd, xln_s, xln_b);

    // 2: both QKV GEMMs in one launch (grid.z picks stream)
    gemm_mma<0, 1><<<dim3(C3 / 128, NN / 128, 2), 128, SMEM_DYN>>>(
        xln_s, xln_b, nullptr, CC, wp_qs, wp_qb, C3 / 128,
        b_qkv_s, b_qkv_b, qkv_s, qkv_b, C3,
        inverse, nullptr, nullptr, CC);

    // 3: fusion MLP layer 1 (concat + GELU)
    gemm_mma<2, 2><<<dim3(C2 / 128, NN / 128), 128, SMEM_DYN>>>(
        qkv_s, qkv_s, qkv_b, C3, wp_f1, wp_f1, C2 / 128,
        b_f1, b_f1, h1, h1, C2,
        nullptr, nullptr, nullptr, C2);
    // 4: fusion MLP layer 2
    gemm_mma<0, 0><<<dim3(CC / 128, NN / 128), 128, SMEM_DYN>>>(
        h1, h1, nullptr, C2, wp_f2, wp_f2, CC / 128,
        b_f2, b_f2, qf, qf, CC,
        nullptr, nullptr, nullptr, C2);

    // 5: attention, both streams
    patch_attn_kernel<<<dim3(PP * HH, 2), 128>>>(qf, qkv_s, qkv_b, order,
                                                 attn_s, attn_b);

    // 6: both output projections + residual in one launch
    gemm_mma<0, 3><<<dim3(CC / 128, NN / 128, 2), 128, SMEM_DYN>>>(
        attn_s, attn_b, nullptr, CC, wp_os, wp_ob, CC / 128,
        b_os, b_ob, out, out + (size_t)NN * CC, CC,
        nullptr, sem_feat, bnd_feat, CC);
}